// round 3
// baseline (speedup 1.0000x reference)
#include <cuda_runtime.h>
#include <math.h>

#define N_NODES 50000
#define N_EDGES 800000
#define DIM     128
#define HEADS   8
#define GRAPHS  64
#define NCLASS  10
#define SLOPE   0.2f
#define BN_EPS  1e-5f

// ---------------- scratch (device globals) ----------------------------------
__device__ float g_h[N_NODES * DIM];        // h = X@W (per layer)
__device__ float g_mid[N_NODES * DIM];      // layer1 output after BN+ELU
__device__ float g_asrc[N_NODES * HEADS];
__device__ float g_adst[N_NODES * HEADS];
__device__ int   g_deg[N_NODES];
__device__ int   g_off[N_NODES + 1];
__device__ int   g_cur[N_NODES];
__device__ int   g_srcs[N_EDGES];           // CSR-sorted source node ids
__device__ float g_gsum[GRAPHS * DIM];
__device__ float g_gcnt[GRAPHS];

__device__ __forceinline__ float leaky(float x) { return x > 0.f ? x : SLOPE * x; }

// ---------------- packed f32x2 helpers ---------------------------------------
__device__ __forceinline__ void fma2(unsigned long long& d, unsigned long long a,
                                     unsigned long long b)
{
    asm("fma.rn.f32x2 %0, %1, %2, %0;" : "+l"(d) : "l"(a), "l"(b));
}
__device__ __forceinline__ unsigned long long pack2(float x, float y)
{
    unsigned long long r;
    asm("mov.b64 %0, {%1, %2};" : "=l"(r) : "f"(x), "f"(y));
    return r;
}
__device__ __forceinline__ float2 unpack2(unsigned long long v)
{
    float2 f;
    asm("mov.b64 {%0, %1}, %2;" : "=f"(f.x), "=f"(f.y) : "l"(v));
    return f;
}

// ---------------- CSR build --------------------------------------------------
__global__ void zero_all(int* __restrict__ deg, float* __restrict__ gsum,
                         float* __restrict__ gcnt)
{
    int i = blockIdx.x * blockDim.x + threadIdx.x;
    if (i < N_NODES) deg[i] = 0;
    if (i < GRAPHS * DIM) gsum[i] = 0.f;
    if (i < GRAPHS) gcnt[i] = 0.f;
}

__global__ void hist_dst(const int* __restrict__ dst, int* __restrict__ deg)
{
    int e = blockIdx.x * blockDim.x + threadIdx.x;
    if (e < N_EDGES) atomicAdd(&deg[dst[e]], 1);
}

__global__ void scan_deg(const int* __restrict__ deg, int* __restrict__ off,
                         int* __restrict__ cur)
{
    __shared__ int s[1024];
    int t = threadIdx.x;
    const int R = (N_NODES + 1023) / 1024;
    int base = t * R;
    int sum = 0;
    for (int i = 0; i < R; i++) {
        int idx = base + i;
        if (idx < N_NODES) sum += deg[idx];
    }
    s[t] = sum;
    __syncthreads();
    for (int d = 1; d < 1024; d <<= 1) {
        int u = (t >= d) ? s[t - d] : 0;
        __syncthreads();
        s[t] += u;
        __syncthreads();
    }
    int run = s[t] - sum;
    for (int i = 0; i < R; i++) {
        int idx = base + i;
        if (idx < N_NODES) {
            off[idx] = run;
            cur[idx] = run;
            run += deg[idx];
        }
    }
    if (t == 0) off[N_NODES] = N_EDGES;
}

__global__ void scatter_edges(const int* __restrict__ src, const int* __restrict__ dst,
                              int* __restrict__ cur, int* __restrict__ srcs)
{
    int e = blockIdx.x * blockDim.x + threadIdx.x;
    if (e < N_EDGES) {
        int pos = atomicAdd(&cur[dst[e]], 1);
        srcs[pos] = src[e];
    }
}

// ---------------- GEMM (h = X @ W) fused with alpha reductions --------------
// 16 rows per 256-thread block; each thread computes 8 consecutive output cols
// of one row with packed fma.rn.f32x2. W read as ulonglong2 (already packed).
__global__ void __launch_bounds__(256) gemm_alpha_kernel(
        const float* __restrict__ X,
        const float* __restrict__ W,
        const float* __restrict__ attS,
        const float* __restrict__ attD,
        float* __restrict__ Hout,
        float* __restrict__ aS,
        float* __restrict__ aD,
        int heads)
{
    __shared__ unsigned long long xs2[16][DIM];   // x value duplicated into both halves
    int tid   = threadIdx.x;
    int row   = tid >> 4;          // 0..15
    int cpart = tid & 15;          // 8 cols each: cpart*8 .. cpart*8+7
    int row0  = blockIdx.x * 16;

    // load & pack X tile (16x128): 8 elements per thread, coalesced
#pragma unroll
    for (int j = 0; j < 8; j++) {
        int idx = tid + j * 256;
        int r = idx >> 7, c = idx & 127;
        float xv = X[(long)(row0 + r) * DIM + c];
        xs2[r][c] = pack2(xv, xv);
    }
    __syncthreads();

    const ulonglong2* Wp = (const ulonglong2*)W;   // 32 ulonglong2 per row of W
    unsigned long long a0 = 0, a1 = 0, a2 = 0, a3 = 0;
#pragma unroll 8
    for (int k = 0; k < DIM; k++) {
        unsigned long long xk = xs2[row][k];
        ulonglong2 wa = Wp[k * 32 + cpart * 2];
        ulonglong2 wb = Wp[k * 32 + cpart * 2 + 1];
        fma2(a0, xk, wa.x);
        fma2(a1, xk, wa.y);
        fma2(a2, xk, wb.x);
        fma2(a3, xk, wb.y);
    }

    int grow = row0 + row;
    ulonglong2* Hp = (ulonglong2*)Hout;
    Hp[(long)grow * 32 + cpart * 2]     = make_ulonglong2(a0, a1);
    Hp[(long)grow * 32 + cpart * 2 + 1] = make_ulonglong2(a2, a3);

    // alpha dot products over this thread's 8 columns
    float2 f0 = unpack2(a0), f1 = unpack2(a1), f2 = unpack2(a2), f3 = unpack2(a3);
    int cbase = cpart * 8;
    float ps = 0.f, pd = 0.f;
    {
        const float* As = attS + cbase;
        const float* Ad = attD + cbase;
        ps = f0.x*As[0] + f0.y*As[1] + f1.x*As[2] + f1.y*As[3]
           + f2.x*As[4] + f2.y*As[5] + f3.x*As[6] + f3.y*As[7];
        pd = f0.x*Ad[0] + f0.y*Ad[1] + f1.x*Ad[2] + f1.y*Ad[3]
           + f2.x*Ad[4] + f2.y*Ad[5] + f3.x*Ad[6] + f3.y*Ad[7];
    }
    if (heads == HEADS) {
        // head = cpart>>1 (16 channels per head = 2 threads)
        ps += __shfl_xor_sync(0xffffffff, ps, 1);
        pd += __shfl_xor_sync(0xffffffff, pd, 1);
        if ((cpart & 1) == 0) {
            aS[(long)grow * HEADS + (cpart >> 1)] = ps;
            aD[(long)grow * HEADS + (cpart >> 1)] = pd;
        }
    } else {
        ps += __shfl_xor_sync(0xffffffff, ps, 1);
        ps += __shfl_xor_sync(0xffffffff, ps, 2);
        ps += __shfl_xor_sync(0xffffffff, ps, 4);
        ps += __shfl_xor_sync(0xffffffff, ps, 8);
        pd += __shfl_xor_sync(0xffffffff, pd, 1);
        pd += __shfl_xor_sync(0xffffffff, pd, 2);
        pd += __shfl_xor_sync(0xffffffff, pd, 4);
        pd += __shfl_xor_sync(0xffffffff, pd, 8);
        if (cpart == 0) { aS[grow] = ps; aD[grow] = pd; }
    }
}

// ---------------- layer 1 fused aggregation (+bias+BN+ELU) ------------------
// one warp per destination node; single pass, no max subtraction (scores are
// O(10), exp cannot overflow fp32). Each lane tracks its own head's softmax
// denominator redundantly -> zero shuffles in the hot loop.
__global__ void __launch_bounds__(256) agg_layer1(
        const int* __restrict__ srcs, const int* __restrict__ off,
        const float* __restrict__ aS, const float* __restrict__ aD,
        const float* __restrict__ H,
        const float* __restrict__ b1,
        const float* __restrict__ bn_g, const float* __restrict__ bn_b,
        const float* __restrict__ bn_m, const float* __restrict__ bn_v,
        float* __restrict__ out)
{
    int node = blockIdx.x * 8 + (threadIdx.x >> 5);
    if (node >= N_NODES) return;
    int lane = threadIdx.x & 31;
    int h    = lane >> 2;          // head of this lane's 4 output channels

    float aD_h = aD[(long)node * HEADS + h];
    float den  = __expf(leaky(aS[(long)node * HEADS + h] + aD_h));   // self loop
    float4 hv  = ((const float4*)H)[(long)node * 32 + lane];
    float4 acc = make_float4(hv.x * den, hv.y * den, hv.z * den, hv.w * den);

    int beg = off[node], end = off[node + 1];
    int s = (beg < end) ? srcs[beg] : 0;
    for (int i = beg; i < end; i++) {
        int s_next = (i + 1 < end) ? srcs[i + 1] : 0;
        float as = aS[(long)s * HEADS + h];
        float4 hs = ((const float4*)H)[(long)s * 32 + lane];
        float ex = __expf(leaky(as + aD_h));
        den += ex;
        acc.x = fmaf(hs.x, ex, acc.x);
        acc.y = fmaf(hs.y, ex, acc.y);
        acc.z = fmaf(hs.z, ex, acc.z);
        acc.w = fmaf(hs.w, ex, acc.w);
        s = s_next;
    }
    float inv = 1.f / den;

    // epilogue: + b1, BN(eval), ELU
    float4 bb = ((const float4*)b1)[lane];
    float4 gg = ((const float4*)bn_g)[lane];
    float4 be = ((const float4*)bn_b)[lane];
    float4 mu = ((const float4*)bn_m)[lane];
    float4 va = ((const float4*)bn_v)[lane];
    float4 o;
    o.x = (acc.x * inv + bb.x - mu.x) * gg.x * rsqrtf(va.x + BN_EPS) + be.x;
    o.y = (acc.y * inv + bb.y - mu.y) * gg.y * rsqrtf(va.y + BN_EPS) + be.y;
    o.z = (acc.z * inv + bb.z - mu.z) * gg.z * rsqrtf(va.z + BN_EPS) + be.z;
    o.w = (acc.w * inv + bb.w - mu.w) * gg.w * rsqrtf(va.w + BN_EPS) + be.w;
    o.x = o.x > 0.f ? o.x : expm1f(o.x);
    o.y = o.y > 0.f ? o.y : expm1f(o.y);
    o.z = o.z > 0.f ? o.z : expm1f(o.z);
    o.w = o.w > 0.f ? o.w : expm1f(o.w);
    ((float4*)out)[(long)node * 32 + lane] = o;
}

// ---------------- layer 2 fused aggregation (+pool) -------------------------
__global__ void __launch_bounds__(256) agg_layer2(
        const int* __restrict__ srcs, const int* __restrict__ off,
        const float* __restrict__ aS, const float* __restrict__ aD,
        const float* __restrict__ H,
        const int* __restrict__ batch,
        float* __restrict__ gsum)
{
    __shared__ float sacc[8][DIM];
    __shared__ int   sbatch[8];
    int wid  = threadIdx.x >> 5;
    int lane = threadIdx.x & 31;
    int node = blockIdx.x * 8 + wid;
    bool valid = node < N_NODES;

    float4 acc = make_float4(0.f, 0.f, 0.f, 0.f);
    int g = -1;
    if (valid) {
        float aDn = aD[node];
        float den = __expf(leaky(aS[node] + aDn));   // self loop
        float4 hv = ((const float4*)H)[(long)node * 32 + lane];
        acc = make_float4(hv.x * den, hv.y * den, hv.z * den, hv.w * den);

        int beg = off[node], end = off[node + 1];
        int s = (beg < end) ? srcs[beg] : 0;
        for (int i = beg; i < end; i++) {
            int s_next = (i + 1 < end) ? srcs[i + 1] : 0;
            float as = aS[s];
            float4 hs = ((const float4*)H)[(long)s * 32 + lane];
            float ex = __expf(leaky(as + aDn));
            den += ex;
            acc.x = fmaf(hs.x, ex, acc.x);
            acc.y = fmaf(hs.y, ex, acc.y);
            acc.z = fmaf(hs.z, ex, acc.z);
            acc.w = fmaf(hs.w, ex, acc.w);
            s = s_next;
        }
        float inv = 1.f / den;
        acc.x *= inv; acc.y *= inv; acc.z *= inv; acc.w *= inv;
        g = batch[node];
    }
    if (lane == 0) sbatch[wid] = g;
    ((float4*)sacc[wid])[lane] = acc;
    __syncthreads();

    int g0 = sbatch[0];
    bool uniform = (g0 >= 0);
#pragma unroll
    for (int w = 1; w < 8; w++) uniform &= (sbatch[w] == g0);

    if (uniform) {
        if (threadIdx.x < DIM) {
            float v = 0.f;
#pragma unroll
            for (int w = 0; w < 8; w++) v += sacc[w][threadIdx.x];
            atomicAdd(&gsum[(long)g0 * DIM + threadIdx.x], v);
        }
    } else if (valid) {
        float* dp = &gsum[(long)g * DIM + lane * 4];
        atomicAdd(dp + 0, acc.x);
        atomicAdd(dp + 1, acc.y);
        atomicAdd(dp + 2, acc.z);
        atomicAdd(dp + 3, acc.w);
    }
}

// ---------------- pool counts (smem histogram) -------------------------------
__global__ void pool_cnt_hist(const int* __restrict__ batch, float* __restrict__ gcnt)
{
    __shared__ int hist[GRAPHS];
    int t = threadIdx.x;
    if (t < GRAPHS) hist[t] = 0;
    __syncthreads();
    int i = blockIdx.x * blockDim.x + t;
    if (i < N_NODES) atomicAdd(&hist[batch[i]], 1);
    __syncthreads();
    if (t < GRAPHS && hist[t] > 0) atomicAdd(&gcnt[t], (float)hist[t]);
}

// ---------------- classifier MLP ---------------------------------------------
__global__ void classifier(const float* __restrict__ gsum, const float* __restrict__ gcnt,
                           const float* __restrict__ b2,
                           const float* __restrict__ Wc1, const float* __restrict__ bc1,
                           const float* __restrict__ Wc2, const float* __restrict__ bc2,
                           float* __restrict__ out)
{
    __shared__ float emb[DIM];
    __shared__ float z[64];
    int g = blockIdx.x, t = threadIdx.x;
    float cnt = fmaxf(gcnt[g], 1.f);
    emb[t] = gsum[(long)g * DIM + t] / cnt + b2[t];
    __syncthreads();
    if (t < 64) {
        float a = bc1[t];
#pragma unroll 8
        for (int k = 0; k < DIM; k++) a = fmaf(emb[k], Wc1[k * 64 + t], a);
        z[t] = a > 0.f ? a : expm1f(a);
    }
    __syncthreads();
    if (t < NCLASS) {
        float a = bc2[t];
#pragma unroll
        for (int k = 0; k < 64; k++) a = fmaf(z[k], Wc2[k * NCLASS + t], a);
        out[(long)g * NCLASS + t] = a;
    }
}

// ---------------- launch ------------------------------------------------------
extern "C" void kernel_launch(void* const* d_in, const int* in_sizes, int n_in,
                              void* d_out, int out_size)
{
    const float* x        = (const float*)d_in[0];
    const int*   esrc     = (const int*)  d_in[1];
    const int*   edst     = (const int*)  d_in[2];
    const int*   batch    = (const int*)  d_in[3];
    const float* W1       = (const float*)d_in[4];
    const float* b1       = (const float*)d_in[5];
    const float* att_src1 = (const float*)d_in[6];
    const float* att_dst1 = (const float*)d_in[7];
    const float* W2       = (const float*)d_in[8];
    const float* b2       = (const float*)d_in[9];
    const float* att_src2 = (const float*)d_in[10];
    const float* att_dst2 = (const float*)d_in[11];
    const float* bn_g     = (const float*)d_in[12];
    const float* bn_b     = (const float*)d_in[13];
    const float* bn_m     = (const float*)d_in[14];
    const float* bn_v     = (const float*)d_in[15];
    const float* Wc1      = (const float*)d_in[16];
    const float* bc1      = (const float*)d_in[17];
    const float* Wc2      = (const float*)d_in[18];
    const float* bc2      = (const float*)d_in[19];
    float* out = (float*)d_out;

    float *p_h, *p_mid, *p_as, *p_ad, *p_gsum, *p_gcnt;
    int *p_deg, *p_off, *p_cur, *p_srcs;
    cudaGetSymbolAddress((void**)&p_h,    g_h);
    cudaGetSymbolAddress((void**)&p_mid,  g_mid);
    cudaGetSymbolAddress((void**)&p_as,   g_asrc);
    cudaGetSymbolAddress((void**)&p_ad,   g_adst);
    cudaGetSymbolAddress((void**)&p_deg,  g_deg);
    cudaGetSymbolAddress((void**)&p_off,  g_off);
    cudaGetSymbolAddress((void**)&p_cur,  g_cur);
    cudaGetSymbolAddress((void**)&p_srcs, g_srcs);
    cudaGetSymbolAddress((void**)&p_gsum, g_gsum);
    cudaGetSymbolAddress((void**)&p_gcnt, g_gcnt);

    const int TB = 256;
    int node_blocks = (N_NODES + TB - 1) / TB;
    int edge_blocks = (N_EDGES + TB - 1) / TB;
    int gemm_blocks = (N_NODES + 15) / 16;
    int agg_blocks  = (N_NODES + 7) / 8;

    // CSR build (per-launch; depends only on edge_dst/src)
    zero_all<<<node_blocks, TB>>>(p_deg, p_gsum, p_gcnt);
    hist_dst<<<edge_blocks, TB>>>(edst, p_deg);
    scan_deg<<<1, 1024>>>(p_deg, p_off, p_cur);
    scatter_edges<<<edge_blocks, TB>>>(esrc, edst, p_cur, p_srcs);

    // layer 1
    gemm_alpha_kernel<<<gemm_blocks, TB>>>(x, W1, att_src1, att_dst1, p_h, p_as, p_ad, HEADS);
    agg_layer1<<<agg_blocks, TB>>>(p_srcs, p_off, p_as, p_ad, p_h,
                                   b1, bn_g, bn_b, bn_m, bn_v, p_mid);

    // layer 2
    gemm_alpha_kernel<<<gemm_blocks, TB>>>(p_mid, W2, att_src2, att_dst2, p_h, p_as, p_ad, 1);
    agg_layer2<<<agg_blocks, TB>>>(p_srcs, p_off, p_as, p_ad, p_h, batch, p_gsum);

    // pool counts + classifier
    pool_cnt_hist<<<node_blocks, TB>>>(batch, p_gcnt);
    classifier<<<GRAPHS, DIM>>>(p_gsum, p_gcnt, b2, Wc1, bc1, Wc2, bc2, out);
}

// round 4
// speedup vs baseline: 1.8456x; 1.8456x over previous
#include <cuda_runtime.h>
#include <math.h>

#define N_NODES 50000
#define N_EDGES 800000
#define DIM     128
#define HEADS   8
#define GRAPHS  64
#define NCLASS  10
#define SLOPE   0.2f
#define BN_EPS  1e-5f

// ---------------- scratch (device globals) ----------------------------------
__device__ float g_h[N_NODES * DIM];        // h = X@W (per layer)
__device__ float g_mid[N_NODES * DIM];      // layer1 output after BN+ELU
__device__ float g_asrc[N_NODES * HEADS];
__device__ float g_adst[N_NODES * HEADS];
__device__ int   g_deg[N_NODES];
__device__ int   g_off[N_NODES + 1];
__device__ int   g_cur[N_NODES];
__device__ int   g_srcs[N_EDGES];           // CSR-sorted source node ids
__device__ float g_gsum[GRAPHS * DIM];
__device__ float g_gcnt[GRAPHS];

__device__ __forceinline__ float leaky(float x) { return x > 0.f ? x : SLOPE * x; }

// ---------------- CSR build --------------------------------------------------
__global__ void zero_all(int* __restrict__ deg, float* __restrict__ gsum,
                         float* __restrict__ gcnt)
{
    int i = blockIdx.x * blockDim.x + threadIdx.x;
    if (i < N_NODES) deg[i] = 0;
    if (i < GRAPHS * DIM) gsum[i] = 0.f;
    if (i < GRAPHS) gcnt[i] = 0.f;
}

__global__ void hist_dst(const int* __restrict__ dst, int* __restrict__ deg)
{
    int e = blockIdx.x * blockDim.x + threadIdx.x;
    if (e < N_EDGES) atomicAdd(&deg[dst[e]], 1);
}

__global__ void scan_deg(const int* __restrict__ deg, int* __restrict__ off,
                         int* __restrict__ cur)
{
    __shared__ int s[1024];
    int t = threadIdx.x;
    const int R = (N_NODES + 1023) / 1024;
    int base = t * R;
    int sum = 0;
    for (int i = 0; i < R; i++) {
        int idx = base + i;
        if (idx < N_NODES) sum += deg[idx];
    }
    s[t] = sum;
    __syncthreads();
    for (int d = 1; d < 1024; d <<= 1) {
        int u = (t >= d) ? s[t - d] : 0;
        __syncthreads();
        s[t] += u;
        __syncthreads();
    }
    int run = s[t] - sum;
    for (int i = 0; i < R; i++) {
        int idx = base + i;
        if (idx < N_NODES) {
            off[idx] = run;
            cur[idx] = run;
            run += deg[idx];
        }
    }
    if (t == 0) off[N_NODES] = N_EDGES;
}

__global__ void scatter_edges(const int* __restrict__ src, const int* __restrict__ dst,
                              int* __restrict__ cur, int* __restrict__ srcs)
{
    int e = blockIdx.x * blockDim.x + threadIdx.x;
    if (e < N_EDGES) {
        int pos = atomicAdd(&cur[dst[e]], 1);
        srcs[pos] = src[e];
    }
}

// ---------------- GEMM (h = X @ W) fused with alpha reductions --------------
// 256 threads = 8 warps; each warp computes 4 rows (32 rows/block).
// X tile transposed in smem so one broadcast LDS.128 feeds 4 rows per k.
// W float4 load amortized over 4 rows. FFMA-pipe bound (~80us).
__global__ void __launch_bounds__(256) gemm_alpha_kernel(
        const float* __restrict__ X,
        const float* __restrict__ W,
        const float* __restrict__ attS,
        const float* __restrict__ attD,
        float* __restrict__ Hout,
        float* __restrict__ aS,
        float* __restrict__ aD,
        int heads)
{
    __shared__ float xsT[DIM][36];   // [k][row], pad 36: 4-way max bank conflict,
                                     // 16B-aligned float4 at [k][4w]
    int tid  = threadIdx.x;
    int lane = tid & 31;
    int w    = tid >> 5;
    int row0 = blockIdx.x * 32;

    // load X tile (32 rows x 128 cols), store transposed
#pragma unroll
    for (int j = 0; j < 16; j++) {
        int idx = tid + j * 256;          // 0..4095
        int r = idx >> 7, c = idx & 127;
        float v = (row0 + r < N_NODES) ? X[(long)(row0 + r) * DIM + c] : 0.f;
        xsT[c][r] = v;
    }
    __syncthreads();

    const float4* W4 = (const float4*)W;
    float4 a0 = make_float4(0.f,0.f,0.f,0.f), a1 = a0, a2 = a0, a3 = a0;
#pragma unroll 4
    for (int k = 0; k < DIM; k++) {
        float4 wv = W4[k * 32 + lane];
        float4 xq = *(const float4*)&xsT[k][w * 4];
        a0.x = fmaf(xq.x, wv.x, a0.x); a0.y = fmaf(xq.x, wv.y, a0.y);
        a0.z = fmaf(xq.x, wv.z, a0.z); a0.w = fmaf(xq.x, wv.w, a0.w);
        a1.x = fmaf(xq.y, wv.x, a1.x); a1.y = fmaf(xq.y, wv.y, a1.y);
        a1.z = fmaf(xq.y, wv.z, a1.z); a1.w = fmaf(xq.y, wv.w, a1.w);
        a2.x = fmaf(xq.z, wv.x, a2.x); a2.y = fmaf(xq.z, wv.y, a2.y);
        a2.z = fmaf(xq.z, wv.z, a2.z); a2.w = fmaf(xq.z, wv.w, a2.w);
        a3.x = fmaf(xq.w, wv.x, a3.x); a3.y = fmaf(xq.w, wv.y, a3.y);
        a3.z = fmaf(xq.w, wv.z, a3.z); a3.w = fmaf(xq.w, wv.w, a3.w);
    }

    float4 sv = ((const float4*)attS)[lane];
    float4 dv = ((const float4*)attD)[lane];
    int rbase = row0 + w * 4;

#pragma unroll
    for (int r = 0; r < 4; r++) {
        int grow = rbase + r;
        if (grow >= N_NODES) break;
        float4 acc = (r == 0) ? a0 : (r == 1) ? a1 : (r == 2) ? a2 : a3;
        ((float4*)(Hout + (long)grow * DIM))[lane] = acc;

        float ps = acc.x*sv.x + acc.y*sv.y + acc.z*sv.z + acc.w*sv.w;
        float pd = acc.x*dv.x + acc.y*dv.y + acc.z*dv.z + acc.w*dv.w;
        ps += __shfl_xor_sync(0xffffffff, ps, 1);
        ps += __shfl_xor_sync(0xffffffff, ps, 2);
        pd += __shfl_xor_sync(0xffffffff, pd, 1);
        pd += __shfl_xor_sync(0xffffffff, pd, 2);
        if (heads == 1) {
            ps += __shfl_xor_sync(0xffffffff, ps, 4);
            ps += __shfl_xor_sync(0xffffffff, ps, 8);
            ps += __shfl_xor_sync(0xffffffff, ps, 16);
            pd += __shfl_xor_sync(0xffffffff, pd, 4);
            pd += __shfl_xor_sync(0xffffffff, pd, 8);
            pd += __shfl_xor_sync(0xffffffff, pd, 16);
            if (lane == 0) { aS[grow] = ps; aD[grow] = pd; }
        } else {
            if ((lane & 3) == 0) {
                aS[(long)grow * HEADS + (lane >> 2)] = ps;
                aD[(long)grow * HEADS + (lane >> 2)] = pd;
            }
        }
    }
}

// ---------------- layer 1 fused aggregation (+bias+BN+ELU) ------------------
// one warp per destination node; single pass, no max subtraction (scores are
// O(10), exp cannot overflow fp32). Each lane tracks its own head's softmax
// denominator redundantly -> zero shuffles in the hot loop.
__global__ void __launch_bounds__(256) agg_layer1(
        const int* __restrict__ srcs, const int* __restrict__ off,
        const float* __restrict__ aS, const float* __restrict__ aD,
        const float* __restrict__ H,
        const float* __restrict__ b1,
        const float* __restrict__ bn_g, const float* __restrict__ bn_b,
        const float* __restrict__ bn_m, const float* __restrict__ bn_v,
        float* __restrict__ out)
{
    int node = blockIdx.x * 8 + (threadIdx.x >> 5);
    if (node >= N_NODES) return;
    int lane = threadIdx.x & 31;
    int h    = lane >> 2;          // head of this lane's 4 output channels

    float aD_h = aD[(long)node * HEADS + h];
    float den  = __expf(leaky(aS[(long)node * HEADS + h] + aD_h));   // self loop
    float4 hv  = ((const float4*)H)[(long)node * 32 + lane];
    float4 acc = make_float4(hv.x * den, hv.y * den, hv.z * den, hv.w * den);

    int beg = off[node], end = off[node + 1];
    int s = (beg < end) ? srcs[beg] : 0;
    for (int i = beg; i < end; i++) {
        int s_next = (i + 1 < end) ? srcs[i + 1] : 0;
        float as = aS[(long)s * HEADS + h];
        float4 hs = ((const float4*)H)[(long)s * 32 + lane];
        float ex = __expf(leaky(as + aD_h));
        den += ex;
        acc.x = fmaf(hs.x, ex, acc.x);
        acc.y = fmaf(hs.y, ex, acc.y);
        acc.z = fmaf(hs.z, ex, acc.z);
        acc.w = fmaf(hs.w, ex, acc.w);
        s = s_next;
    }
    float inv = 1.f / den;

    // epilogue: + b1, BN(eval), ELU
    float4 bb = ((const float4*)b1)[lane];
    float4 gg = ((const float4*)bn_g)[lane];
    float4 be = ((const float4*)bn_b)[lane];
    float4 mu = ((const float4*)bn_m)[lane];
    float4 va = ((const float4*)bn_v)[lane];
    float4 o;
    o.x = (acc.x * inv + bb.x - mu.x) * gg.x * rsqrtf(va.x + BN_EPS) + be.x;
    o.y = (acc.y * inv + bb.y - mu.y) * gg.y * rsqrtf(va.y + BN_EPS) + be.y;
    o.z = (acc.z * inv + bb.z - mu.z) * gg.z * rsqrtf(va.z + BN_EPS) + be.z;
    o.w = (acc.w * inv + bb.w - mu.w) * gg.w * rsqrtf(va.w + BN_EPS) + be.w;
    o.x = o.x > 0.f ? o.x : expm1f(o.x);
    o.y = o.y > 0.f ? o.y : expm1f(o.y);
    o.z = o.z > 0.f ? o.z : expm1f(o.z);
    o.w = o.w > 0.f ? o.w : expm1f(o.w);
    ((float4*)out)[(long)node * 32 + lane] = o;
}

// ---------------- layer 2 fused aggregation (+pool) -------------------------
__global__ void __launch_bounds__(256) agg_layer2(
        const int* __restrict__ srcs, const int* __restrict__ off,
        const float* __restrict__ aS, const float* __restrict__ aD,
        const float* __restrict__ H,
        const int* __restrict__ batch,
        float* __restrict__ gsum)
{
    __shared__ float sacc[8][DIM];
    __shared__ int   sbatch[8];
    int wid  = threadIdx.x >> 5;
    int lane = threadIdx.x & 31;
    int node = blockIdx.x * 8 + wid;
    bool valid = node < N_NODES;

    float4 acc = make_float4(0.f, 0.f, 0.f, 0.f);
    int g = -1;
    if (valid) {
        float aDn = aD[node];
        float den = __expf(leaky(aS[node] + aDn));   // self loop
        float4 hv = ((const float4*)H)[(long)node * 32 + lane];
        acc = make_float4(hv.x * den, hv.y * den, hv.z * den, hv.w * den);

        int beg = off[node], end = off[node + 1];
        int s = (beg < end) ? srcs[beg] : 0;
        for (int i = beg; i < end; i++) {
            int s_next = (i + 1 < end) ? srcs[i + 1] : 0;
            float as = aS[s];
            float4 hs = ((const float4*)H)[(long)s * 32 + lane];
            float ex = __expf(leaky(as + aDn));
            den += ex;
            acc.x = fmaf(hs.x, ex, acc.x);
            acc.y = fmaf(hs.y, ex, acc.y);
            acc.z = fmaf(hs.z, ex, acc.z);
            acc.w = fmaf(hs.w, ex, acc.w);
            s = s_next;
        }
        float inv = 1.f / den;
        acc.x *= inv; acc.y *= inv; acc.z *= inv; acc.w *= inv;
        g = batch[node];
    }
    if (lane == 0) sbatch[wid] = g;
    ((float4*)sacc[wid])[lane] = acc;
    __syncthreads();

    int g0 = sbatch[0];
    bool uniform = (g0 >= 0);
#pragma unroll
    for (int w = 1; w < 8; w++) uniform &= (sbatch[w] == g0);

    if (uniform) {
        if (threadIdx.x < DIM) {
            float v = 0.f;
#pragma unroll
            for (int w = 0; w < 8; w++) v += sacc[w][threadIdx.x];
            atomicAdd(&gsum[(long)g0 * DIM + threadIdx.x], v);
        }
    } else if (valid) {
        float* dp = &gsum[(long)g * DIM + lane * 4];
        atomicAdd(dp + 0, acc.x);
        atomicAdd(dp + 1, acc.y);
        atomicAdd(dp + 2, acc.z);
        atomicAdd(dp + 3, acc.w);
    }
}

// ---------------- pool counts (smem histogram) -------------------------------
__global__ void pool_cnt_hist(const int* __restrict__ batch, float* __restrict__ gcnt)
{
    __shared__ int hist[GRAPHS];
    int t = threadIdx.x;
    if (t < GRAPHS) hist[t] = 0;
    __syncthreads();
    int i = blockIdx.x * blockDim.x + t;
    if (i < N_NODES) atomicAdd(&hist[batch[i]], 1);
    __syncthreads();
    if (t < GRAPHS && hist[t] > 0) atomicAdd(&gcnt[t], (float)hist[t]);
}

// ---------------- classifier MLP ---------------------------------------------
__global__ void classifier(const float* __restrict__ gsum, const float* __restrict__ gcnt,
                           const float* __restrict__ b2,
                           const float* __restrict__ Wc1, const float* __restrict__ bc1,
                           const float* __restrict__ Wc2, const float* __restrict__ bc2,
                           float* __restrict__ out)
{
    __shared__ float emb[DIM];
    __shared__ float z[64];
    int g = blockIdx.x, t = threadIdx.x;
    float cnt = fmaxf(gcnt[g], 1.f);
    emb[t] = gsum[(long)g * DIM + t] / cnt + b2[t];
    __syncthreads();
    if (t < 64) {
        float a = bc1[t];
#pragma unroll 8
        for (int k = 0; k < DIM; k++) a = fmaf(emb[k], Wc1[k * 64 + t], a);
        z[t] = a > 0.f ? a : expm1f(a);
    }
    __syncthreads();
    if (t < NCLASS) {
        float a = bc2[t];
#pragma unroll
        for (int k = 0; k < 64; k++) a = fmaf(z[k], Wc2[k * NCLASS + t], a);
        out[(long)g * NCLASS + t] = a;
    }
}

// ---------------- launch ------------------------------------------------------
extern "C" void kernel_launch(void* const* d_in, const int* in_sizes, int n_in,
                              void* d_out, int out_size)
{
    const float* x        = (const float*)d_in[0];
    const int*   esrc     = (const int*)  d_in[1];
    const int*   edst     = (const int*)  d_in[2];
    const int*   batch    = (const int*)  d_in[3];
    const float* W1       = (const float*)d_in[4];
    const float* b1       = (const float*)d_in[5];
    const float* att_src1 = (const float*)d_in[6];
    const float* att_dst1 = (const float*)d_in[7];
    const float* W2       = (const float*)d_in[8];
    const float* b2       = (const float*)d_in[9];
    const float* att_src2 = (const float*)d_in[10];
    const float* att_dst2 = (const float*)d_in[11];
    const float* bn_g     = (const float*)d_in[12];
    const float* bn_b     = (const float*)d_in[13];
    const float* bn_m     = (const float*)d_in[14];
    const float* bn_v     = (const float*)d_in[15];
    const float* Wc1      = (const float*)d_in[16];
    const float* bc1      = (const float*)d_in[17];
    const float* Wc2      = (const float*)d_in[18];
    const float* bc2      = (const float*)d_in[19];
    float* out = (float*)d_out;

    float *p_h, *p_mid, *p_as, *p_ad, *p_gsum, *p_gcnt;
    int *p_deg, *p_off, *p_cur, *p_srcs;
    cudaGetSymbolAddress((void**)&p_h,    g_h);
    cudaGetSymbolAddress((void**)&p_mid,  g_mid);
    cudaGetSymbolAddress((void**)&p_as,   g_asrc);
    cudaGetSymbolAddress((void**)&p_ad,   g_adst);
    cudaGetSymbolAddress((void**)&p_deg,  g_deg);
    cudaGetSymbolAddress((void**)&p_off,  g_off);
    cudaGetSymbolAddress((void**)&p_cur,  g_cur);
    cudaGetSymbolAddress((void**)&p_srcs, g_srcs);
    cudaGetSymbolAddress((void**)&p_gsum, g_gsum);
    cudaGetSymbolAddress((void**)&p_gcnt, g_gcnt);

    const int TB = 256;
    int node_blocks = (N_NODES + TB - 1) / TB;
    int edge_blocks = (N_EDGES + TB - 1) / TB;
    int gemm_blocks = (N_NODES + 31) / 32;
    int agg_blocks  = (N_NODES + 7) / 8;

    // CSR build (per-launch; depends only on edge_dst/src)
    zero_all<<<node_blocks, TB>>>(p_deg, p_gsum, p_gcnt);
    hist_dst<<<edge_blocks, TB>>>(edst, p_deg);
    scan_deg<<<1, 1024>>>(p_deg, p_off, p_cur);
    scatter_edges<<<edge_blocks, TB>>>(esrc, edst, p_cur, p_srcs);

    // layer 1
    gemm_alpha_kernel<<<gemm_blocks, TB>>>(x, W1, att_src1, att_dst1, p_h, p_as, p_ad, HEADS);
    agg_layer1<<<agg_blocks, TB>>>(p_srcs, p_off, p_as, p_ad, p_h,
                                   b1, bn_g, bn_b, bn_m, bn_v, p_mid);

    // layer 2
    gemm_alpha_kernel<<<gemm_blocks, TB>>>(p_mid, W2, att_src2, att_dst2, p_h, p_as, p_ad, 1);
    agg_layer2<<<agg_blocks, TB>>>(p_srcs, p_off, p_as, p_ad, p_h, batch, p_gsum);

    // pool counts + classifier
    pool_cnt_hist<<<node_blocks, TB>>>(batch, p_gcnt);
    classifier<<<GRAPHS, DIM>>>(p_gsum, p_gcnt, b2, Wc1, bc1, Wc2, bc2, out);
}

// round 5
// speedup vs baseline: 1.9228x; 1.0418x over previous
#include <cuda_runtime.h>
#include <math.h>

#define N_NODES 50000
#define N_EDGES 800000
#define DIM     128
#define HEADS   8
#define GRAPHS  64
#define NCLASS  10
#define SLOPE   0.2f
#define BN_EPS  1e-5f

// ---------------- scratch (device globals) ----------------------------------
__device__ float g_h[N_NODES * DIM];        // h = X@W (per layer)
__device__ float g_mid[N_NODES * DIM];      // layer1 output after BN+ELU
__device__ float g_asrc[N_NODES * HEADS];
__device__ float g_adst[N_NODES * HEADS];
__device__ int   g_deg[N_NODES];
__device__ int   g_off[N_NODES + 1];
__device__ int   g_cur[N_NODES];
__device__ int   g_srcs[N_EDGES];           // CSR-sorted source node ids
__device__ float g_gsum[GRAPHS * DIM];
__device__ float g_gcnt[GRAPHS];

__device__ __forceinline__ float leaky(float x) { return x > 0.f ? x : SLOPE * x; }

// ---------------- CSR build --------------------------------------------------
__global__ void zero_all(int* __restrict__ deg, float* __restrict__ gsum,
                         float* __restrict__ gcnt)
{
    int i = blockIdx.x * blockDim.x + threadIdx.x;
    if (i < N_NODES) deg[i] = 0;
    if (i < GRAPHS * DIM) gsum[i] = 0.f;
    if (i < GRAPHS) gcnt[i] = 0.f;
}

__global__ void hist_dst(const int* __restrict__ dst, int* __restrict__ deg)
{
    int e = blockIdx.x * blockDim.x + threadIdx.x;
    if (e < N_EDGES) atomicAdd(&deg[dst[e]], 1);
}

__global__ void scan_deg(const int* __restrict__ deg, int* __restrict__ off,
                         int* __restrict__ cur)
{
    __shared__ int s[1024];
    int t = threadIdx.x;
    const int R = (N_NODES + 1023) / 1024;
    int base = t * R;
    int sum = 0;
    for (int i = 0; i < R; i++) {
        int idx = base + i;
        if (idx < N_NODES) sum += deg[idx];
    }
    s[t] = sum;
    __syncthreads();
    for (int d = 1; d < 1024; d <<= 1) {
        int u = (t >= d) ? s[t - d] : 0;
        __syncthreads();
        s[t] += u;
        __syncthreads();
    }
    int run = s[t] - sum;
    for (int i = 0; i < R; i++) {
        int idx = base + i;
        if (idx < N_NODES) {
            off[idx] = run;
            cur[idx] = run;
            run += deg[idx];
        }
    }
    if (t == 0) off[N_NODES] = N_EDGES;
}

__global__ void scatter_edges(const int* __restrict__ src, const int* __restrict__ dst,
                              int* __restrict__ cur, int* __restrict__ srcs)
{
    int e = blockIdx.x * blockDim.x + threadIdx.x;
    if (e < N_EDGES) {
        int pos = atomicAdd(&cur[dst[e]], 1);
        srcs[pos] = src[e];
    }
}

// ---------------- GEMM (h = X @ W) fused with alpha reductions --------------
// 256 threads = 8 warps; each warp computes 4 rows (32 rows/block).
__global__ void __launch_bounds__(256) gemm_alpha_kernel(
        const float* __restrict__ X,
        const float* __restrict__ W,
        const float* __restrict__ attS,
        const float* __restrict__ attD,
        float* __restrict__ Hout,
        float* __restrict__ aS,
        float* __restrict__ aD,
        int heads)
{
    __shared__ float xsT[DIM][36];
    int tid  = threadIdx.x;
    int lane = tid & 31;
    int w    = tid >> 5;
    int row0 = blockIdx.x * 32;

#pragma unroll
    for (int j = 0; j < 16; j++) {
        int idx = tid + j * 256;
        int r = idx >> 7, c = idx & 127;
        float v = (row0 + r < N_NODES) ? X[(long)(row0 + r) * DIM + c] : 0.f;
        xsT[c][r] = v;
    }
    __syncthreads();

    const float4* W4 = (const float4*)W;
    float4 a0 = make_float4(0.f,0.f,0.f,0.f), a1 = a0, a2 = a0, a3 = a0;
#pragma unroll 4
    for (int k = 0; k < DIM; k++) {
        float4 wv = W4[k * 32 + lane];
        float4 xq = *(const float4*)&xsT[k][w * 4];
        a0.x = fmaf(xq.x, wv.x, a0.x); a0.y = fmaf(xq.x, wv.y, a0.y);
        a0.z = fmaf(xq.x, wv.z, a0.z); a0.w = fmaf(xq.x, wv.w, a0.w);
        a1.x = fmaf(xq.y, wv.x, a1.x); a1.y = fmaf(xq.y, wv.y, a1.y);
        a1.z = fmaf(xq.y, wv.z, a1.z); a1.w = fmaf(xq.y, wv.w, a1.w);
        a2.x = fmaf(xq.z, wv.x, a2.x); a2.y = fmaf(xq.z, wv.y, a2.y);
        a2.z = fmaf(xq.z, wv.z, a2.z); a2.w = fmaf(xq.z, wv.w, a2.w);
        a3.x = fmaf(xq.w, wv.x, a3.x); a3.y = fmaf(xq.w, wv.y, a3.y);
        a3.z = fmaf(xq.w, wv.z, a3.z); a3.w = fmaf(xq.w, wv.w, a3.w);
    }

    float4 sv = ((const float4*)attS)[lane];
    float4 dv = ((const float4*)attD)[lane];
    int rbase = row0 + w * 4;

#pragma unroll
    for (int r = 0; r < 4; r++) {
        int grow = rbase + r;
        if (grow >= N_NODES) break;
        float4 acc = (r == 0) ? a0 : (r == 1) ? a1 : (r == 2) ? a2 : a3;
        ((float4*)(Hout + (long)grow * DIM))[lane] = acc;

        float ps = acc.x*sv.x + acc.y*sv.y + acc.z*sv.z + acc.w*sv.w;
        float pd = acc.x*dv.x + acc.y*dv.y + acc.z*dv.z + acc.w*dv.w;
        ps += __shfl_xor_sync(0xffffffff, ps, 1);
        ps += __shfl_xor_sync(0xffffffff, ps, 2);
        pd += __shfl_xor_sync(0xffffffff, pd, 1);
        pd += __shfl_xor_sync(0xffffffff, pd, 2);
        if (heads == 1) {
            ps += __shfl_xor_sync(0xffffffff, ps, 4);
            ps += __shfl_xor_sync(0xffffffff, ps, 8);
            ps += __shfl_xor_sync(0xffffffff, ps, 16);
            pd += __shfl_xor_sync(0xffffffff, pd, 4);
            pd += __shfl_xor_sync(0xffffffff, pd, 8);
            pd += __shfl_xor_sync(0xffffffff, pd, 16);
            if (lane == 0) { aS[grow] = ps; aD[grow] = pd; }
        } else {
            if ((lane & 3) == 0) {
                aS[(long)grow * HEADS + (lane >> 2)] = ps;
                aD[(long)grow * HEADS + (lane >> 2)] = pd;
            }
        }
    }
}

// ---------------- layer 1 fused aggregation (+bias+BN+ELU) ------------------
// one warp per dst node; single-pass softmax; software-pipelined gathers.
__global__ void __launch_bounds__(256) agg_layer1(
        const int* __restrict__ srcs, const int* __restrict__ off,
        const float* __restrict__ aS, const float* __restrict__ aD,
        const float* __restrict__ H,
        const float* __restrict__ b1,
        const float* __restrict__ bn_g, const float* __restrict__ bn_b,
        const float* __restrict__ bn_m, const float* __restrict__ bn_v,
        float* __restrict__ out)
{
    int node = blockIdx.x * 8 + (threadIdx.x >> 5);
    if (node >= N_NODES) return;
    int lane = threadIdx.x & 31;
    int h    = lane >> 2;

    float aD_h = aD[(long)node * HEADS + h];
    float den  = __expf(leaky(aS[(long)node * HEADS + h] + aD_h));   // self loop
    float4 hv  = ((const float4*)H)[(long)node * 32 + lane];
    float4 acc = make_float4(hv.x * den, hv.y * den, hv.z * den, hv.w * den);

    int beg = off[node], end = off[node + 1];
    if (beg < end) {
        int    s_cur  = srcs[beg];
        float  as_cur = aS[(long)s_cur * HEADS + h];
        float4 h_cur  = ((const float4*)H)[(long)s_cur * 32 + lane];
        int last = end - 1;
        for (int i = beg; i < end; i++) {
            // issue next iteration's loads before current math
            int    j      = (i < last) ? i + 1 : last;
            int    s_nxt  = srcs[j];
            float  as_nxt = aS[(long)s_nxt * HEADS + h];
            float4 h_nxt  = ((const float4*)H)[(long)s_nxt * 32 + lane];

            float ex = __expf(leaky(as_cur + aD_h));
            den += ex;
            acc.x = fmaf(h_cur.x, ex, acc.x);
            acc.y = fmaf(h_cur.y, ex, acc.y);
            acc.z = fmaf(h_cur.z, ex, acc.z);
            acc.w = fmaf(h_cur.w, ex, acc.w);

            as_cur = as_nxt; h_cur = h_nxt;
        }
    }
    float inv = 1.f / den;

    float4 bb = ((const float4*)b1)[lane];
    float4 gg = ((const float4*)bn_g)[lane];
    float4 be = ((const float4*)bn_b)[lane];
    float4 mu = ((const float4*)bn_m)[lane];
    float4 va = ((const float4*)bn_v)[lane];
    float4 o;
    o.x = (acc.x * inv + bb.x - mu.x) * gg.x * rsqrtf(va.x + BN_EPS) + be.x;
    o.y = (acc.y * inv + bb.y - mu.y) * gg.y * rsqrtf(va.y + BN_EPS) + be.y;
    o.z = (acc.z * inv + bb.z - mu.z) * gg.z * rsqrtf(va.z + BN_EPS) + be.z;
    o.w = (acc.w * inv + bb.w - mu.w) * gg.w * rsqrtf(va.w + BN_EPS) + be.w;
    o.x = o.x > 0.f ? o.x : expm1f(o.x);
    o.y = o.y > 0.f ? o.y : expm1f(o.y);
    o.z = o.z > 0.f ? o.z : expm1f(o.z);
    o.w = o.w > 0.f ? o.w : expm1f(o.w);
    ((float4*)out)[(long)node * 32 + lane] = o;
}

// ---------------- layer 2 fused aggregation (+pool) -------------------------
__global__ void __launch_bounds__(256) agg_layer2(
        const int* __restrict__ srcs, const int* __restrict__ off,
        const float* __restrict__ aS, const float* __restrict__ aD,
        const float* __restrict__ H,
        const int* __restrict__ batch,
        float* __restrict__ gsum)
{
    __shared__ float sacc[8][DIM];
    __shared__ int   sbatch[8];
    int wid  = threadIdx.x >> 5;
    int lane = threadIdx.x & 31;
    int node = blockIdx.x * 8 + wid;
    bool valid = node < N_NODES;

    float4 acc = make_float4(0.f, 0.f, 0.f, 0.f);
    int g = -1;
    if (valid) {
        float aDn = aD[node];
        float den = __expf(leaky(aS[node] + aDn));   // self loop
        float4 hv = ((const float4*)H)[(long)node * 32 + lane];
        acc = make_float4(hv.x * den, hv.y * den, hv.z * den, hv.w * den);

        int beg = off[node], end = off[node + 1];
        if (beg < end) {
            int    s_cur  = srcs[beg];
            float  as_cur = aS[s_cur];
            float4 h_cur  = ((const float4*)H)[(long)s_cur * 32 + lane];
            int last = end - 1;
            for (int i = beg; i < end; i++) {
                int    j      = (i < last) ? i + 1 : last;
                int    s_nxt  = srcs[j];
                float  as_nxt = aS[s_nxt];
                float4 h_nxt  = ((const float4*)H)[(long)s_nxt * 32 + lane];

                float ex = __expf(leaky(as_cur + aDn));
                den += ex;
                acc.x = fmaf(h_cur.x, ex, acc.x);
                acc.y = fmaf(h_cur.y, ex, acc.y);
                acc.z = fmaf(h_cur.z, ex, acc.z);
                acc.w = fmaf(h_cur.w, ex, acc.w);

                as_cur = as_nxt; h_cur = h_nxt;
            }
        }
        float inv = 1.f / den;
        acc.x *= inv; acc.y *= inv; acc.z *= inv; acc.w *= inv;
        g = batch[node];
    }
    if (lane == 0) sbatch[wid] = g;
    ((float4*)sacc[wid])[lane] = acc;
    __syncthreads();

    int g0 = sbatch[0];
    bool uniform = (g0 >= 0);
#pragma unroll
    for (int w = 1; w < 8; w++) uniform &= (sbatch[w] == g0);

    if (uniform) {
        if (threadIdx.x < DIM) {
            float v = 0.f;
#pragma unroll
            for (int w = 0; w < 8; w++) v += sacc[w][threadIdx.x];
            atomicAdd(&gsum[(long)g0 * DIM + threadIdx.x], v);
        }
    } else if (valid) {
        float* dp = &gsum[(long)g * DIM + lane * 4];
        atomicAdd(dp + 0, acc.x);
        atomicAdd(dp + 1, acc.y);
        atomicAdd(dp + 2, acc.z);
        atomicAdd(dp + 3, acc.w);
    }
}

// ---------------- pool counts (smem histogram) -------------------------------
__global__ void pool_cnt_hist(const int* __restrict__ batch, float* __restrict__ gcnt)
{
    __shared__ int hist[GRAPHS];
    int t = threadIdx.x;
    if (t < GRAPHS) hist[t] = 0;
    __syncthreads();
    int i = blockIdx.x * blockDim.x + t;
    if (i < N_NODES) atomicAdd(&hist[batch[i]], 1);
    __syncthreads();
    if (t < GRAPHS && hist[t] > 0) atomicAdd(&gcnt[t], (float)hist[t]);
}

// ---------------- classifier MLP ---------------------------------------------
__global__ void classifier(const float* __restrict__ gsum, const float* __restrict__ gcnt,
                           const float* __restrict__ b2,
                           const float* __restrict__ Wc1, const float* __restrict__ bc1,
                           const float* __restrict__ Wc2, const float* __restrict__ bc2,
                           float* __restrict__ out)
{
    __shared__ float emb[DIM];
    __shared__ float z[64];
    int g = blockIdx.x, t = threadIdx.x;
    float cnt = fmaxf(gcnt[g], 1.f);
    emb[t] = gsum[(long)g * DIM + t] / cnt + b2[t];
    __syncthreads();
    if (t < 64) {
        float a = bc1[t];
#pragma unroll 8
        for (int k = 0; k < DIM; k++) a = fmaf(emb[k], Wc1[k * 64 + t], a);
        z[t] = a > 0.f ? a : expm1f(a);
    }
    __syncthreads();
    if (t < NCLASS) {
        float a = bc2[t];
#pragma unroll
        for (int k = 0; k < 64; k++) a = fmaf(z[k], Wc2[k * NCLASS + t], a);
        out[(long)g * NCLASS + t] = a;
    }
}

// ---------------- launch ------------------------------------------------------
extern "C" void kernel_launch(void* const* d_in, const int* in_sizes, int n_in,
                              void* d_out, int out_size)
{
    const float* x        = (const float*)d_in[0];
    const int*   esrc     = (const int*)  d_in[1];
    const int*   edst     = (const int*)  d_in[2];
    const int*   batch    = (const int*)  d_in[3];
    const float* W1       = (const float*)d_in[4];
    const float* b1       = (const float*)d_in[5];
    const float* att_src1 = (const float*)d_in[6];
    const float* att_dst1 = (const float*)d_in[7];
    const float* W2       = (const float*)d_in[8];
    const float* b2       = (const float*)d_in[9];
    const float* att_src2 = (const float*)d_in[10];
    const float* att_dst2 = (const float*)d_in[11];
    const float* bn_g     = (const float*)d_in[12];
    const float* bn_b     = (const float*)d_in[13];
    const float* bn_m     = (const float*)d_in[14];
    const float* bn_v     = (const float*)d_in[15];
    const float* Wc1      = (const float*)d_in[16];
    const float* bc1      = (const float*)d_in[17];
    const float* Wc2      = (const float*)d_in[18];
    const float* bc2      = (const float*)d_in[19];
    float* out = (float*)d_out;

    float *p_h, *p_mid, *p_as, *p_ad, *p_gsum, *p_gcnt;
    int *p_deg, *p_off, *p_cur, *p_srcs;
    cudaGetSymbolAddress((void**)&p_h,    g_h);
    cudaGetSymbolAddress((void**)&p_mid,  g_mid);
    cudaGetSymbolAddress((void**)&p_as,   g_asrc);
    cudaGetSymbolAddress((void**)&p_ad,   g_adst);
    cudaGetSymbolAddress((void**)&p_deg,  g_deg);
    cudaGetSymbolAddress((void**)&p_off,  g_off);
    cudaGetSymbolAddress((void**)&p_cur,  g_cur);
    cudaGetSymbolAddress((void**)&p_srcs, g_srcs);
    cudaGetSymbolAddress((void**)&p_gsum, g_gsum);
    cudaGetSymbolAddress((void**)&p_gcnt, g_gcnt);

    // side stream + events, created once on the first (uncaptured) call.
    static cudaStream_t s2 = 0;
    static cudaEvent_t evFork = 0, evJoin = 0;
    if (s2 == 0) {
        cudaStreamCreateWithFlags(&s2, cudaStreamNonBlocking);
        cudaEventCreateWithFlags(&evFork, cudaEventDisableTiming);
        cudaEventCreateWithFlags(&evJoin, cudaEventDisableTiming);
    }

    const int TB = 256;
    int node_blocks = (N_NODES + TB - 1) / TB;
    int edge_blocks = (N_EDGES + TB - 1) / TB;
    int gemm_blocks = (N_NODES + 31) / 32;
    int agg_blocks  = (N_NODES + 7) / 8;

    // fork: CSR build + pool counts run concurrently with gemm1
    cudaEventRecord(evFork, 0);
    cudaStreamWaitEvent(s2, evFork, 0);

    zero_all<<<node_blocks, TB, 0, s2>>>(p_deg, p_gsum, p_gcnt);
    hist_dst<<<edge_blocks, TB, 0, s2>>>(edst, p_deg);
    scan_deg<<<1, 1024, 0, s2>>>(p_deg, p_off, p_cur);
    scatter_edges<<<edge_blocks, TB, 0, s2>>>(esrc, edst, p_cur, p_srcs);
    pool_cnt_hist<<<node_blocks, TB, 0, s2>>>(batch, p_gcnt);
    cudaEventRecord(evJoin, s2);

    gemm_alpha_kernel<<<gemm_blocks, TB>>>(x, W1, att_src1, att_dst1, p_h, p_as, p_ad, HEADS);

    // join: agg1 needs both gemm1 (stream 0) and CSR (s2)
    cudaStreamWaitEvent(0, evJoin, 0);

    agg_layer1<<<agg_blocks, TB>>>(p_srcs, p_off, p_as, p_ad, p_h,
                                   b1, bn_g, bn_b, bn_m, bn_v, p_mid);

    gemm_alpha_kernel<<<gemm_blocks, TB>>>(p_mid, W2, att_src2, att_dst2, p_h, p_as, p_ad, 1);
    agg_layer2<<<agg_blocks, TB>>>(p_srcs, p_off, p_as, p_ad, p_h, batch, p_gsum);

    classifier<<<GRAPHS, DIM>>>(p_gsum, p_gcnt, b2, Wc1, bc1, Wc2, bc2, out);
}

// round 6
// speedup vs baseline: 1.9278x; 1.0026x over previous
#include <cuda_runtime.h>
#include <cuda_bf16.h>
#include <math.h>

#define N_NODES 50000
#define N_EDGES 800000
#define DIM     128
#define HEADS   8
#define GRAPHS  64
#define NCLASS  10
#define SLOPE   0.2f
#define BN_EPS  1e-5f

// ---------------- scratch (device globals) ----------------------------------
__device__ __nv_bfloat16 g_h[N_NODES * DIM];  // h = X@W in bf16 (message payload)
__device__ float g_mid[N_NODES * DIM];        // layer1 output after BN+ELU (fp32)
__device__ float g_asrc[N_NODES * HEADS];
__device__ float g_adst[N_NODES * HEADS];
__device__ int   g_deg[N_NODES];
__device__ int   g_off[N_NODES + 1];
__device__ int   g_cur[N_NODES];
__device__ int   g_srcs[N_EDGES];             // CSR-sorted source node ids
__device__ float g_gsum[GRAPHS * DIM];
__device__ float g_gcnt[GRAPHS];

__device__ __forceinline__ float leaky(float x) { return x > 0.f ? x : SLOPE * x; }

// unpack uint2 (4 bf16) -> 2 float2
__device__ __forceinline__ void bf16x4_unpack(uint2 v, float2& lo, float2& hi)
{
    lo = __bfloat1622float2(*(const __nv_bfloat162*)&v.x);
    hi = __bfloat1622float2(*(const __nv_bfloat162*)&v.y);
}

// ---------------- CSR build --------------------------------------------------
__global__ void zero_all(int* __restrict__ deg, float* __restrict__ gsum,
                         float* __restrict__ gcnt)
{
    int i = blockIdx.x * blockDim.x + threadIdx.x;
    if (i < N_NODES) deg[i] = 0;
    if (i < GRAPHS * DIM) gsum[i] = 0.f;
    if (i < GRAPHS) gcnt[i] = 0.f;
}

__global__ void hist_dst(const int* __restrict__ dst, int* __restrict__ deg)
{
    int e = blockIdx.x * blockDim.x + threadIdx.x;
    if (e < N_EDGES) atomicAdd(&deg[dst[e]], 1);
}

__global__ void scan_deg(const int* __restrict__ deg, int* __restrict__ off,
                         int* __restrict__ cur)
{
    __shared__ int s[1024];
    int t = threadIdx.x;
    const int R = (N_NODES + 1023) / 1024;
    int base = t * R;
    int sum = 0;
    for (int i = 0; i < R; i++) {
        int idx = base + i;
        if (idx < N_NODES) sum += deg[idx];
    }
    s[t] = sum;
    __syncthreads();
    for (int d = 1; d < 1024; d <<= 1) {
        int u = (t >= d) ? s[t - d] : 0;
        __syncthreads();
        s[t] += u;
        __syncthreads();
    }
    int run = s[t] - sum;
    for (int i = 0; i < R; i++) {
        int idx = base + i;
        if (idx < N_NODES) {
            off[idx] = run;
            cur[idx] = run;
            run += deg[idx];
        }
    }
    if (t == 0) off[N_NODES] = N_EDGES;
}

__global__ void scatter_edges(const int* __restrict__ src, const int* __restrict__ dst,
                              int* __restrict__ cur, int* __restrict__ srcs)
{
    int e = blockIdx.x * blockDim.x + threadIdx.x;
    if (e < N_EDGES) {
        int pos = atomicAdd(&cur[dst[e]], 1);
        srcs[pos] = src[e];
    }
}

// ---------------- GEMM (h = X @ W) fused with alpha reductions --------------
// 256 threads = 8 warps; each warp computes 4 rows (32 rows/block).
// fp32 accumulation; H written as bf16; alphas from fp32 accumulators.
__global__ void __launch_bounds__(256) gemm_alpha_kernel(
        const float* __restrict__ X,
        const float* __restrict__ W,
        const float* __restrict__ attS,
        const float* __restrict__ attD,
        __nv_bfloat16* __restrict__ Hout,
        float* __restrict__ aS,
        float* __restrict__ aD,
        int heads)
{
    __shared__ float xsT[DIM][36];
    int tid  = threadIdx.x;
    int lane = tid & 31;
    int w    = tid >> 5;
    int row0 = blockIdx.x * 32;

#pragma unroll
    for (int j = 0; j < 16; j++) {
        int idx = tid + j * 256;
        int r = idx >> 7, c = idx & 127;
        float v = (row0 + r < N_NODES) ? X[(long)(row0 + r) * DIM + c] : 0.f;
        xsT[c][r] = v;
    }
    __syncthreads();

    const float4* W4 = (const float4*)W;
    float4 a0 = make_float4(0.f,0.f,0.f,0.f), a1 = a0, a2 = a0, a3 = a0;
#pragma unroll 4
    for (int k = 0; k < DIM; k++) {
        float4 wv = W4[k * 32 + lane];
        float4 xq = *(const float4*)&xsT[k][w * 4];
        a0.x = fmaf(xq.x, wv.x, a0.x); a0.y = fmaf(xq.x, wv.y, a0.y);
        a0.z = fmaf(xq.x, wv.z, a0.z); a0.w = fmaf(xq.x, wv.w, a0.w);
        a1.x = fmaf(xq.y, wv.x, a1.x); a1.y = fmaf(xq.y, wv.y, a1.y);
        a1.z = fmaf(xq.y, wv.z, a1.z); a1.w = fmaf(xq.y, wv.w, a1.w);
        a2.x = fmaf(xq.z, wv.x, a2.x); a2.y = fmaf(xq.z, wv.y, a2.y);
        a2.z = fmaf(xq.z, wv.z, a2.z); a2.w = fmaf(xq.z, wv.w, a2.w);
        a3.x = fmaf(xq.w, wv.x, a3.x); a3.y = fmaf(xq.w, wv.y, a3.y);
        a3.z = fmaf(xq.w, wv.z, a3.z); a3.w = fmaf(xq.w, wv.w, a3.w);
    }

    float4 sv = ((const float4*)attS)[lane];
    float4 dv = ((const float4*)attD)[lane];
    int rbase = row0 + w * 4;

#pragma unroll
    for (int r = 0; r < 4; r++) {
        int grow = rbase + r;
        if (grow >= N_NODES) break;
        float4 acc = (r == 0) ? a0 : (r == 1) ? a1 : (r == 2) ? a2 : a3;

        // store bf16 (4 values = 8 bytes per lane, coalesced)
        uint2 hb;
        *(__nv_bfloat162*)&hb.x = __floats2bfloat162_rn(acc.x, acc.y);
        *(__nv_bfloat162*)&hb.y = __floats2bfloat162_rn(acc.z, acc.w);
        ((uint2*)Hout)[(long)grow * 32 + lane] = hb;

        float ps = acc.x*sv.x + acc.y*sv.y + acc.z*sv.z + acc.w*sv.w;
        float pd = acc.x*dv.x + acc.y*dv.y + acc.z*dv.z + acc.w*dv.w;
        ps += __shfl_xor_sync(0xffffffff, ps, 1);
        ps += __shfl_xor_sync(0xffffffff, ps, 2);
        pd += __shfl_xor_sync(0xffffffff, pd, 1);
        pd += __shfl_xor_sync(0xffffffff, pd, 2);
        if (heads == 1) {
            ps += __shfl_xor_sync(0xffffffff, ps, 4);
            ps += __shfl_xor_sync(0xffffffff, ps, 8);
            ps += __shfl_xor_sync(0xffffffff, ps, 16);
            pd += __shfl_xor_sync(0xffffffff, pd, 4);
            pd += __shfl_xor_sync(0xffffffff, pd, 8);
            pd += __shfl_xor_sync(0xffffffff, pd, 16);
            if (lane == 0) { aS[grow] = ps; aD[grow] = pd; }
        } else {
            if ((lane & 3) == 0) {
                aS[(long)grow * HEADS + (lane >> 2)] = ps;
                aD[(long)grow * HEADS + (lane >> 2)] = pd;
            }
        }
    }
}

// ---------------- layer 1 fused aggregation (+bias+BN+ELU) ------------------
// one warp per dst node; single-pass softmax; bf16 h gather (256B/edge).
__global__ void __launch_bounds__(256) agg_layer1(
        const int* __restrict__ srcs, const int* __restrict__ off,
        const float* __restrict__ aS, const float* __restrict__ aD,
        const __nv_bfloat16* __restrict__ H,
        const float* __restrict__ b1,
        const float* __restrict__ bn_g, const float* __restrict__ bn_b,
        const float* __restrict__ bn_m, const float* __restrict__ bn_v,
        float* __restrict__ out)
{
    int node = blockIdx.x * 8 + (threadIdx.x >> 5);
    if (node >= N_NODES) return;
    int lane = threadIdx.x & 31;
    int h    = lane >> 2;

    float aD_h = aD[(long)node * HEADS + h];
    float den  = __expf(leaky(aS[(long)node * HEADS + h] + aD_h));   // self loop
    float2 slo, shi;
    bf16x4_unpack(((const uint2*)H)[(long)node * 32 + lane], slo, shi);
    float4 acc = make_float4(slo.x * den, slo.y * den, shi.x * den, shi.y * den);

    int beg = off[node], end = off[node + 1];
    if (beg < end) {
        int   s_cur  = srcs[beg];
        float as_cur = aS[(long)s_cur * HEADS + h];
        uint2 h_cur  = ((const uint2*)H)[(long)s_cur * 32 + lane];
        int last = end - 1;
        for (int i = beg; i < end; i++) {
            int   j      = (i < last) ? i + 1 : last;
            int   s_nxt  = srcs[j];
            float as_nxt = aS[(long)s_nxt * HEADS + h];
            uint2 h_nxt  = ((const uint2*)H)[(long)s_nxt * 32 + lane];

            float ex = __expf(leaky(as_cur + aD_h));
            den += ex;
            float2 lo, hi;
            bf16x4_unpack(h_cur, lo, hi);
            acc.x = fmaf(lo.x, ex, acc.x);
            acc.y = fmaf(lo.y, ex, acc.y);
            acc.z = fmaf(hi.x, ex, acc.z);
            acc.w = fmaf(hi.y, ex, acc.w);

            as_cur = as_nxt; h_cur = h_nxt;
        }
    }
    float inv = 1.f / den;

    float4 bb = ((const float4*)b1)[lane];
    float4 gg = ((const float4*)bn_g)[lane];
    float4 be = ((const float4*)bn_b)[lane];
    float4 mu = ((const float4*)bn_m)[lane];
    float4 va = ((const float4*)bn_v)[lane];
    float4 o;
    o.x = (acc.x * inv + bb.x - mu.x) * gg.x * rsqrtf(va.x + BN_EPS) + be.x;
    o.y = (acc.y * inv + bb.y - mu.y) * gg.y * rsqrtf(va.y + BN_EPS) + be.y;
    o.z = (acc.z * inv + bb.z - mu.z) * gg.z * rsqrtf(va.z + BN_EPS) + be.z;
    o.w = (acc.w * inv + bb.w - mu.w) * gg.w * rsqrtf(va.w + BN_EPS) + be.w;
    o.x = o.x > 0.f ? o.x : expm1f(o.x);
    o.y = o.y > 0.f ? o.y : expm1f(o.y);
    o.z = o.z > 0.f ? o.z : expm1f(o.z);
    o.w = o.w > 0.f ? o.w : expm1f(o.w);
    ((float4*)out)[(long)node * 32 + lane] = o;
}

// ---------------- layer 2 fused aggregation (+pool) -------------------------
__global__ void __launch_bounds__(256) agg_layer2(
        const int* __restrict__ srcs, const int* __restrict__ off,
        const float* __restrict__ aS, const float* __restrict__ aD,
        const __nv_bfloat16* __restrict__ H,
        const int* __restrict__ batch,
        float* __restrict__ gsum)
{
    __shared__ float sacc[8][DIM];
    __shared__ int   sbatch[8];
    int wid  = threadIdx.x >> 5;
    int lane = threadIdx.x & 31;
    int node = blockIdx.x * 8 + wid;
    bool valid = node < N_NODES;

    float4 acc = make_float4(0.f, 0.f, 0.f, 0.f);
    int g = -1;
    if (valid) {
        float aDn = aD[node];
        float den = __expf(leaky(aS[node] + aDn));   // self loop
        float2 slo, shi;
        bf16x4_unpack(((const uint2*)H)[(long)node * 32 + lane], slo, shi);
        acc = make_float4(slo.x * den, slo.y * den, shi.x * den, shi.y * den);

        int beg = off[node], end = off[node + 1];
        if (beg < end) {
            int   s_cur  = srcs[beg];
            float as_cur = aS[s_cur];
            uint2 h_cur  = ((const uint2*)H)[(long)s_cur * 32 + lane];
            int last = end - 1;
            for (int i = beg; i < end; i++) {
                int   j      = (i < last) ? i + 1 : last;
                int   s_nxt  = srcs[j];
                float as_nxt = aS[s_nxt];
                uint2 h_nxt  = ((const uint2*)H)[(long)s_nxt * 32 + lane];

                float ex = __expf(leaky(as_cur + aDn));
                den += ex;
                float2 lo, hi;
                bf16x4_unpack(h_cur, lo, hi);
                acc.x = fmaf(lo.x, ex, acc.x);
                acc.y = fmaf(lo.y, ex, acc.y);
                acc.z = fmaf(hi.x, ex, acc.z);
                acc.w = fmaf(hi.y, ex, acc.w);

                as_cur = as_nxt; h_cur = h_nxt;
            }
        }
        float inv = 1.f / den;
        acc.x *= inv; acc.y *= inv; acc.z *= inv; acc.w *= inv;
        g = batch[node];
    }
    if (lane == 0) sbatch[wid] = g;
    ((float4*)sacc[wid])[lane] = acc;
    __syncthreads();

    int g0 = sbatch[0];
    bool uniform = (g0 >= 0);
#pragma unroll
    for (int w = 1; w < 8; w++) uniform &= (sbatch[w] == g0);

    if (uniform) {
        if (threadIdx.x < DIM) {
            float v = 0.f;
#pragma unroll
            for (int w = 0; w < 8; w++) v += sacc[w][threadIdx.x];
            atomicAdd(&gsum[(long)g0 * DIM + threadIdx.x], v);
        }
    } else if (valid) {
        float* dp = &gsum[(long)g * DIM + lane * 4];
        atomicAdd(dp + 0, acc.x);
        atomicAdd(dp + 1, acc.y);
        atomicAdd(dp + 2, acc.z);
        atomicAdd(dp + 3, acc.w);
    }
}

// ---------------- pool counts (smem histogram) -------------------------------
__global__ void pool_cnt_hist(const int* __restrict__ batch, float* __restrict__ gcnt)
{
    __shared__ int hist[GRAPHS];
    int t = threadIdx.x;
    if (t < GRAPHS) hist[t] = 0;
    __syncthreads();
    int i = blockIdx.x * blockDim.x + t;
    if (i < N_NODES) atomicAdd(&hist[batch[i]], 1);
    __syncthreads();
    if (t < GRAPHS && hist[t] > 0) atomicAdd(&gcnt[t], (float)hist[t]);
}

// ---------------- classifier MLP ---------------------------------------------
__global__ void classifier(const float* __restrict__ gsum, const float* __restrict__ gcnt,
                           const float* __restrict__ b2,
                           const float* __restrict__ Wc1, const float* __restrict__ bc1,
                           const float* __restrict__ Wc2, const float* __restrict__ bc2,
                           float* __restrict__ out)
{
    __shared__ float emb[DIM];
    __shared__ float z[64];
    int g = blockIdx.x, t = threadIdx.x;
    float cnt = fmaxf(gcnt[g], 1.f);
    emb[t] = gsum[(long)g * DIM + t] / cnt + b2[t];
    __syncthreads();
    if (t < 64) {
        float a = bc1[t];
#pragma unroll 8
        for (int k = 0; k < DIM; k++) a = fmaf(emb[k], Wc1[k * 64 + t], a);
        z[t] = a > 0.f ? a : expm1f(a);
    }
    __syncthreads();
    if (t < NCLASS) {
        float a = bc2[t];
#pragma unroll
        for (int k = 0; k < 64; k++) a = fmaf(z[k], Wc2[k * NCLASS + t], a);
        out[(long)g * NCLASS + t] = a;
    }
}

// ---------------- launch ------------------------------------------------------
extern "C" void kernel_launch(void* const* d_in, const int* in_sizes, int n_in,
                              void* d_out, int out_size)
{
    const float* x        = (const float*)d_in[0];
    const int*   esrc     = (const int*)  d_in[1];
    const int*   edst     = (const int*)  d_in[2];
    const int*   batch    = (const int*)  d_in[3];
    const float* W1       = (const float*)d_in[4];
    const float* b1       = (const float*)d_in[5];
    const float* att_src1 = (const float*)d_in[6];
    const float* att_dst1 = (const float*)d_in[7];
    const float* W2       = (const float*)d_in[8];
    const float* b2       = (const float*)d_in[9];
    const float* att_src2 = (const float*)d_in[10];
    const float* att_dst2 = (const float*)d_in[11];
    const float* bn_g     = (const float*)d_in[12];
    const float* bn_b     = (const float*)d_in[13];
    const float* bn_m     = (const float*)d_in[14];
    const float* bn_v     = (const float*)d_in[15];
    const float* Wc1      = (const float*)d_in[16];
    const float* bc1      = (const float*)d_in[17];
    const float* Wc2      = (const float*)d_in[18];
    const float* bc2      = (const float*)d_in[19];
    float* out = (float*)d_out;

    __nv_bfloat16 *p_h;
    float *p_mid, *p_as, *p_ad, *p_gsum, *p_gcnt;
    int *p_deg, *p_off, *p_cur, *p_srcs;
    cudaGetSymbolAddress((void**)&p_h,    g_h);
    cudaGetSymbolAddress((void**)&p_mid,  g_mid);
    cudaGetSymbolAddress((void**)&p_as,   g_asrc);
    cudaGetSymbolAddress((void**)&p_ad,   g_adst);
    cudaGetSymbolAddress((void**)&p_deg,  g_deg);
    cudaGetSymbolAddress((void**)&p_off,  g_off);
    cudaGetSymbolAddress((void**)&p_cur,  g_cur);
    cudaGetSymbolAddress((void**)&p_srcs, g_srcs);
    cudaGetSymbolAddress((void**)&p_gsum, g_gsum);
    cudaGetSymbolAddress((void**)&p_gcnt, g_gcnt);

    // side stream + events, created once on the first (uncaptured) call.
    static cudaStream_t s2 = 0;
    static cudaEvent_t evFork = 0, evJoin = 0;
    if (s2 == 0) {
        cudaStreamCreateWithFlags(&s2, cudaStreamNonBlocking);
        cudaEventCreateWithFlags(&evFork, cudaEventDisableTiming);
        cudaEventCreateWithFlags(&evJoin, cudaEventDisableTiming);
    }

    const int TB = 256;
    int node_blocks = (N_NODES + TB - 1) / TB;
    int edge_blocks = (N_EDGES + TB - 1) / TB;
    int gemm_blocks = (N_NODES + 31) / 32;
    int agg_blocks  = (N_NODES + 7) / 8;

    // fork: CSR build + pool counts run concurrently with gemm1
    cudaEventRecord(evFork, 0);
    cudaStreamWaitEvent(s2, evFork, 0);

    zero_all<<<node_blocks, TB, 0, s2>>>(p_deg, p_gsum, p_gcnt);
    hist_dst<<<edge_blocks, TB, 0, s2>>>(edst, p_deg);
    scan_deg<<<1, 1024, 0, s2>>>(p_deg, p_off, p_cur);
    scatter_edges<<<edge_blocks, TB, 0, s2>>>(esrc, edst, p_cur, p_srcs);
    pool_cnt_hist<<<node_blocks, TB, 0, s2>>>(batch, p_gcnt);
    cudaEventRecord(evJoin, s2);

    gemm_alpha_kernel<<<gemm_blocks, TB>>>(x, W1, att_src1, att_dst1, p_h, p_as, p_ad, HEADS);

    // join: agg1 needs both gemm1 (stream 0) and CSR (s2)
    cudaStreamWaitEvent(0, evJoin, 0);

    agg_layer1<<<agg_blocks, TB>>>(p_srcs, p_off, p_as, p_ad, p_h,
                                   b1, bn_g, bn_b, bn_m, bn_v, p_mid);

    gemm_alpha_kernel<<<gemm_blocks, TB>>>(p_mid, W2, att_src2, att_dst2, p_h, p_as, p_ad, 1);
    agg_layer2<<<agg_blocks, TB>>>(p_srcs, p_off, p_as, p_ad, p_h, batch, p_gsum);

    classifier<<<GRAPHS, DIM>>>(p_gsum, p_gcnt, b2, Wc1, bc1, Wc2, bc2, out);
}

// round 7
// speedup vs baseline: 1.9492x; 1.0111x over previous
#include <cuda_runtime.h>
#include <cuda_bf16.h>
#include <math.h>

#define N_NODES 50000
#define N_EDGES 800000
#define DIM     128
#define HEADS   8
#define GRAPHS  64
#define NCLASS  10
#define SLOPE   0.2f
#define BN_EPS  1e-5f

// ---------------- scratch (device globals) ----------------------------------
__device__ __nv_bfloat16 g_h[N_NODES * DIM];  // h = X@W in bf16 (message payload)
__device__ float g_mid[N_NODES * DIM];        // layer1 output after BN+ELU (fp32)
__device__ float g_asrc[N_NODES * HEADS];
__device__ float g_adst[N_NODES * HEADS];
__device__ int   g_deg[N_NODES];
__device__ int   g_off[N_NODES + 1];
__device__ int   g_cur[N_NODES];
__device__ int   g_srcs[N_EDGES];             // CSR-sorted source node ids
__device__ float g_gsum[GRAPHS * DIM];
__device__ float g_gcnt[GRAPHS];

__device__ __forceinline__ float leaky(float x) { return x > 0.f ? x : SLOPE * x; }

__device__ __forceinline__ void bf16x4_unpack(uint2 v, float2& lo, float2& hi)
{
    lo = __bfloat1622float2(*(const __nv_bfloat162*)&v.x);
    hi = __bfloat1622float2(*(const __nv_bfloat162*)&v.y);
}

// ---------------- CSR build --------------------------------------------------
__global__ void zero_all(int* __restrict__ deg, float* __restrict__ gsum,
                         float* __restrict__ gcnt)
{
    int i = blockIdx.x * blockDim.x + threadIdx.x;
    if (i < N_NODES) deg[i] = 0;
    if (i < GRAPHS * DIM) gsum[i] = 0.f;
    if (i < GRAPHS) gcnt[i] = 0.f;
}

__global__ void hist_dst(const int* __restrict__ dst, int* __restrict__ deg)
{
    int e = blockIdx.x * blockDim.x + threadIdx.x;
    if (e < N_EDGES) atomicAdd(&deg[dst[e]], 1);
}

__global__ void scan_deg(const int* __restrict__ deg, int* __restrict__ off,
                         int* __restrict__ cur)
{
    __shared__ int s[1024];
    int t = threadIdx.x;
    const int R = (N_NODES + 1023) / 1024;
    int base = t * R;
    int sum = 0;
    for (int i = 0; i < R; i++) {
        int idx = base + i;
        if (idx < N_NODES) sum += deg[idx];
    }
    s[t] = sum;
    __syncthreads();
    for (int d = 1; d < 1024; d <<= 1) {
        int u = (t >= d) ? s[t - d] : 0;
        __syncthreads();
        s[t] += u;
        __syncthreads();
    }
    int run = s[t] - sum;
    for (int i = 0; i < R; i++) {
        int idx = base + i;
        if (idx < N_NODES) {
            off[idx] = run;
            cur[idx] = run;
            run += deg[idx];
        }
    }
    if (t == 0) off[N_NODES] = N_EDGES;
}

__global__ void scatter_edges(const int* __restrict__ src, const int* __restrict__ dst,
                              int* __restrict__ cur, int* __restrict__ srcs)
{
    int e = blockIdx.x * blockDim.x + threadIdx.x;
    if (e < N_EDGES) {
        int pos = atomicAdd(&cur[dst[e]], 1);
        srcs[pos] = src[e];
    }
}

// ---------------- GEMM (h = X @ W) fused with alpha reductions --------------
__global__ void __launch_bounds__(256) gemm_alpha_kernel(
        const float* __restrict__ X,
        const float* __restrict__ W,
        const float* __restrict__ attS,
        const float* __restrict__ attD,
        __nv_bfloat16* __restrict__ Hout,
        float* __restrict__ aS,
        float* __restrict__ aD,
        int heads)
{
    __shared__ float xsT[DIM][36];
    int tid  = threadIdx.x;
    int lane = tid & 31;
    int w    = tid >> 5;
    int row0 = blockIdx.x * 32;

#pragma unroll
    for (int j = 0; j < 16; j++) {
        int idx = tid + j * 256;
        int r = idx >> 7, c = idx & 127;
        float v = (row0 + r < N_NODES) ? X[(long)(row0 + r) * DIM + c] : 0.f;
        xsT[c][r] = v;
    }
    __syncthreads();

    const float4* W4 = (const float4*)W;
    float4 a0 = make_float4(0.f,0.f,0.f,0.f), a1 = a0, a2 = a0, a3 = a0;
#pragma unroll 4
    for (int k = 0; k < DIM; k++) {
        float4 wv = W4[k * 32 + lane];
        float4 xq = *(const float4*)&xsT[k][w * 4];
        a0.x = fmaf(xq.x, wv.x, a0.x); a0.y = fmaf(xq.x, wv.y, a0.y);
        a0.z = fmaf(xq.x, wv.z, a0.z); a0.w = fmaf(xq.x, wv.w, a0.w);
        a1.x = fmaf(xq.y, wv.x, a1.x); a1.y = fmaf(xq.y, wv.y, a1.y);
        a1.z = fmaf(xq.y, wv.z, a1.z); a1.w = fmaf(xq.y, wv.w, a1.w);
        a2.x = fmaf(xq.z, wv.x, a2.x); a2.y = fmaf(xq.z, wv.y, a2.y);
        a2.z = fmaf(xq.z, wv.z, a2.z); a2.w = fmaf(xq.z, wv.w, a2.w);
        a3.x = fmaf(xq.w, wv.x, a3.x); a3.y = fmaf(xq.w, wv.y, a3.y);
        a3.z = fmaf(xq.w, wv.z, a3.z); a3.w = fmaf(xq.w, wv.w, a3.w);
    }

    float4 sv = ((const float4*)attS)[lane];
    float4 dv = ((const float4*)attD)[lane];
    int rbase = row0 + w * 4;

#pragma unroll
    for (int r = 0; r < 4; r++) {
        int grow = rbase + r;
        if (grow >= N_NODES) break;
        float4 acc = (r == 0) ? a0 : (r == 1) ? a1 : (r == 2) ? a2 : a3;

        uint2 hb;
        *(__nv_bfloat162*)&hb.x = __floats2bfloat162_rn(acc.x, acc.y);
        *(__nv_bfloat162*)&hb.y = __floats2bfloat162_rn(acc.z, acc.w);
        ((uint2*)Hout)[(long)grow * 32 + lane] = hb;

        float ps = acc.x*sv.x + acc.y*sv.y + acc.z*sv.z + acc.w*sv.w;
        float pd = acc.x*dv.x + acc.y*dv.y + acc.z*dv.z + acc.w*dv.w;
        ps += __shfl_xor_sync(0xffffffff, ps, 1);
        ps += __shfl_xor_sync(0xffffffff, ps, 2);
        pd += __shfl_xor_sync(0xffffffff, pd, 1);
        pd += __shfl_xor_sync(0xffffffff, pd, 2);
        if (heads == 1) {
            ps += __shfl_xor_sync(0xffffffff, ps, 4);
            ps += __shfl_xor_sync(0xffffffff, ps, 8);
            ps += __shfl_xor_sync(0xffffffff, ps, 16);
            pd += __shfl_xor_sync(0xffffffff, pd, 4);
            pd += __shfl_xor_sync(0xffffffff, pd, 8);
            pd += __shfl_xor_sync(0xffffffff, pd, 16);
            if (lane == 0) { aS[grow] = ps; aD[grow] = pd; }
        } else {
            if ((lane & 3) == 0) {
                aS[(long)grow * HEADS + (lane >> 2)] = ps;
                aD[(long)grow * HEADS + (lane >> 2)] = pd;
            }
        }
    }
}

// ---------------- layer 1 fused aggregation (+bias+BN+ELU) ------------------
// one warp per dst node; dual interleaved edge chains, each prefetched 1 deep
// -> >=4 independent L2 loads in flight. All hot indices in int32.
__global__ void __launch_bounds__(256) agg_layer1(
        const int* __restrict__ srcs, const int* __restrict__ off,
        const float* __restrict__ aS, const float* __restrict__ aD,
        const __nv_bfloat16* __restrict__ H,
        const float* __restrict__ b1,
        const float* __restrict__ bn_g, const float* __restrict__ bn_b,
        const float* __restrict__ bn_m, const float* __restrict__ bn_v,
        float* __restrict__ out)
{
    int node = blockIdx.x * 8 + (threadIdx.x >> 5);
    if (node >= N_NODES) return;
    int lane = threadIdx.x & 31;
    int h    = lane >> 2;
    const uint2* H4 = (const uint2*)H;

    float aD_h = aD[node * HEADS + h];
    float denA = __expf(leaky(aS[node * HEADS + h] + aD_h));   // self loop
    float2 slo, shi;
    bf16x4_unpack(H4[node * 32 + lane], slo, shi);
    float4 accA = make_float4(slo.x * denA, slo.y * denA, shi.x * denA, shi.y * denA);
    float denB = 0.f;
    float4 accB = make_float4(0.f, 0.f, 0.f, 0.f);

    int beg = off[node], end = off[node + 1];
    int n = end - beg;
    if (n > 0) {
        int last = end - 1;
        int cntB = n >> 1;
        int cntA = n - cntB;
        int iA = beg;
        int iB = min(beg + 1, last);
        int   sA  = srcs[iA],              sB  = srcs[iB];
        float asA = aS[sA * HEADS + h],    asB = aS[sB * HEADS + h];
        uint2 hA  = H4[sA * 32 + lane],    hB  = H4[sB * 32 + lane];
        for (int t = 0; t < cntA; t++) {
            int iA2 = min(iA + 2, last), iB2 = min(iB + 2, last);
            int   sA2  = srcs[iA2],             sB2  = srcs[iB2];
            float asA2 = aS[sA2 * HEADS + h],   asB2 = aS[sB2 * HEADS + h];
            uint2 hA2  = H4[sA2 * 32 + lane],   hB2  = H4[sB2 * 32 + lane];

            float exA = __expf(leaky(asA + aD_h));
            denA += exA;
            float2 lo, hi;
            bf16x4_unpack(hA, lo, hi);
            accA.x = fmaf(lo.x, exA, accA.x);
            accA.y = fmaf(lo.y, exA, accA.y);
            accA.z = fmaf(hi.x, exA, accA.z);
            accA.w = fmaf(hi.y, exA, accA.w);

            if (t < cntB) {
                float exB = __expf(leaky(asB + aD_h));
                denB += exB;
                bf16x4_unpack(hB, lo, hi);
                accB.x = fmaf(lo.x, exB, accB.x);
                accB.y = fmaf(lo.y, exB, accB.y);
                accB.z = fmaf(hi.x, exB, accB.z);
                accB.w = fmaf(hi.y, exB, accB.w);
            }
            iA = iA2; iB = iB2;
            asA = asA2; asB = asB2; hA = hA2; hB = hB2;
        }
    }
    float den = denA + denB;
    float4 acc = make_float4(accA.x + accB.x, accA.y + accB.y,
                             accA.z + accB.z, accA.w + accB.w);
    float inv = 1.f / den;

    float4 bb = ((const float4*)b1)[lane];
    float4 gg = ((const float4*)bn_g)[lane];
    float4 be = ((const float4*)bn_b)[lane];
    float4 mu = ((const float4*)bn_m)[lane];
    float4 va = ((const float4*)bn_v)[lane];
    float4 o;
    o.x = (acc.x * inv + bb.x - mu.x) * gg.x * rsqrtf(va.x + BN_EPS) + be.x;
    o.y = (acc.y * inv + bb.y - mu.y) * gg.y * rsqrtf(va.y + BN_EPS) + be.y;
    o.z = (acc.z * inv + bb.z - mu.z) * gg.z * rsqrtf(va.z + BN_EPS) + be.z;
    o.w = (acc.w * inv + bb.w - mu.w) * gg.w * rsqrtf(va.w + BN_EPS) + be.w;
    o.x = o.x > 0.f ? o.x : expm1f(o.x);
    o.y = o.y > 0.f ? o.y : expm1f(o.y);
    o.z = o.z > 0.f ? o.z : expm1f(o.z);
    o.w = o.w > 0.f ? o.w : expm1f(o.w);
    ((float4*)out)[node * 32 + lane] = o;
}

// ---------------- layer 2 fused aggregation (+pool) -------------------------
__global__ void __launch_bounds__(256) agg_layer2(
        const int* __restrict__ srcs, const int* __restrict__ off,
        const float* __restrict__ aS, const float* __restrict__ aD,
        const __nv_bfloat16* __restrict__ H,
        const int* __restrict__ batch,
        float* __restrict__ gsum)
{
    __shared__ float sacc[8][DIM];
    __shared__ int   sbatch[8];
    int wid  = threadIdx.x >> 5;
    int lane = threadIdx.x & 31;
    int node = blockIdx.x * 8 + wid;
    bool valid = node < N_NODES;
    const uint2* H4 = (const uint2*)H;

    float4 acc = make_float4(0.f, 0.f, 0.f, 0.f);
    int g = -1;
    if (valid) {
        float aDn  = aD[node];
        float denA = __expf(leaky(aS[node] + aDn));   // self loop
        float2 slo, shi;
        bf16x4_unpack(H4[node * 32 + lane], slo, shi);
        float4 accA = make_float4(slo.x * denA, slo.y * denA, shi.x * denA, shi.y * denA);
        float denB = 0.f;
        float4 accB = make_float4(0.f, 0.f, 0.f, 0.f);

        int beg = off[node], end = off[node + 1];
        int n = end - beg;
        if (n > 0) {
            int last = end - 1;
            int cntB = n >> 1;
            int cntA = n - cntB;
            int iA = beg;
            int iB = min(beg + 1, last);
            int   sA  = srcs[iA],           sB  = srcs[iB];
            float asA = aS[sA],             asB = aS[sB];
            uint2 hA  = H4[sA * 32 + lane], hB  = H4[sB * 32 + lane];
            for (int t = 0; t < cntA; t++) {
                int iA2 = min(iA + 2, last), iB2 = min(iB + 2, last);
                int   sA2  = srcs[iA2],            sB2  = srcs[iB2];
                float asA2 = aS[sA2],              asB2 = aS[sB2];
                uint2 hA2  = H4[sA2 * 32 + lane],  hB2  = H4[sB2 * 32 + lane];

                float exA = __expf(leaky(asA + aDn));
                denA += exA;
                float2 lo, hi;
                bf16x4_unpack(hA, lo, hi);
                accA.x = fmaf(lo.x, exA, accA.x);
                accA.y = fmaf(lo.y, exA, accA.y);
                accA.z = fmaf(hi.x, exA, accA.z);
                accA.w = fmaf(hi.y, exA, accA.w);

                if (t < cntB) {
                    float exB = __expf(leaky(asB + aDn));
                    denB += exB;
                    bf16x4_unpack(hB, lo, hi);
                    accB.x = fmaf(lo.x, exB, accB.x);
                    accB.y = fmaf(lo.y, exB, accB.y);
                    accB.z = fmaf(hi.x, exB, accB.z);
                    accB.w = fmaf(hi.y, exB, accB.w);
                }
                iA = iA2; iB = iB2;
                asA = asA2; asB = asB2; hA = hA2; hB = hB2;
            }
        }
        float den = denA + denB;
        float inv = 1.f / den;
        acc.x = (accA.x + accB.x) * inv;
        acc.y = (accA.y + accB.y) * inv;
        acc.z = (accA.z + accB.z) * inv;
        acc.w = (accA.w + accB.w) * inv;
        g = batch[node];
    }
    if (lane == 0) sbatch[wid] = g;
    ((float4*)sacc[wid])[lane] = acc;
    __syncthreads();

    int g0 = sbatch[0];
    bool uniform = (g0 >= 0);
#pragma unroll
    for (int w = 1; w < 8; w++) uniform &= (sbatch[w] == g0);

    if (uniform) {
        if (threadIdx.x < DIM) {
            float v = 0.f;
#pragma unroll
            for (int w = 0; w < 8; w++) v += sacc[w][threadIdx.x];
            atomicAdd(&gsum[g0 * DIM + threadIdx.x], v);
        }
    } else if (valid) {
        float* dp = &gsum[g * DIM + lane * 4];
        atomicAdd(dp + 0, acc.x);
        atomicAdd(dp + 1, acc.y);
        atomicAdd(dp + 2, acc.z);
        atomicAdd(dp + 3, acc.w);
    }
}

// ---------------- pool counts (smem histogram) -------------------------------
__global__ void pool_cnt_hist(const int* __restrict__ batch, float* __restrict__ gcnt)
{
    __shared__ int hist[GRAPHS];
    int t = threadIdx.x;
    if (t < GRAPHS) hist[t] = 0;
    __syncthreads();
    int i = blockIdx.x * blockDim.x + t;
    if (i < N_NODES) atomicAdd(&hist[batch[i]], 1);
    __syncthreads();
    if (t < GRAPHS && hist[t] > 0) atomicAdd(&gcnt[t], (float)hist[t]);
}

// ---------------- classifier MLP ---------------------------------------------
__global__ void classifier(const float* __restrict__ gsum, const float* __restrict__ gcnt,
                           const float* __restrict__ b2,
                           const float* __restrict__ Wc1, const float* __restrict__ bc1,
                           const float* __restrict__ Wc2, const float* __restrict__ bc2,
                           float* __restrict__ out)
{
    __shared__ float emb[DIM];
    __shared__ float z[64];
    int g = blockIdx.x, t = threadIdx.x;
    float cnt = fmaxf(gcnt[g], 1.f);
    emb[t] = gsum[g * DIM + t] / cnt + b2[t];
    __syncthreads();
    if (t < 64) {
        float a = bc1[t];
#pragma unroll 8
        for (int k = 0; k < DIM; k++) a = fmaf(emb[k], Wc1[k * 64 + t], a);
        z[t] = a > 0.f ? a : expm1f(a);
    }
    __syncthreads();
    if (t < NCLASS) {
        float a = bc2[t];
#pragma unroll
        for (int k = 0; k < 64; k++) a = fmaf(z[k], Wc2[k * NCLASS + t], a);
        out[g * NCLASS + t] = a;
    }
}

// ---------------- launch ------------------------------------------------------
extern "C" void kernel_launch(void* const* d_in, const int* in_sizes, int n_in,
                              void* d_out, int out_size)
{
    const float* x        = (const float*)d_in[0];
    const int*   esrc     = (const int*)  d_in[1];
    const int*   edst     = (const int*)  d_in[2];
    const int*   batch    = (const int*)  d_in[3];
    const float* W1       = (const float*)d_in[4];
    const float* b1       = (const float*)d_in[5];
    const float* att_src1 = (const float*)d_in[6];
    const float* att_dst1 = (const float*)d_in[7];
    const float* W2       = (const float*)d_in[8];
    const float* b2       = (const float*)d_in[9];
    const float* att_src2 = (const float*)d_in[10];
    const float* att_dst2 = (const float*)d_in[11];
    const float* bn_g     = (const float*)d_in[12];
    const float* bn_b     = (const float*)d_in[13];
    const float* bn_m     = (const float*)d_in[14];
    const float* bn_v     = (const float*)d_in[15];
    const float* Wc1      = (const float*)d_in[16];
    const float* bc1      = (const float*)d_in[17];
    const float* Wc2      = (const float*)d_in[18];
    const float* bc2      = (const float*)d_in[19];
    float* out = (float*)d_out;

    __nv_bfloat16 *p_h;
    float *p_mid, *p_as, *p_ad, *p_gsum, *p_gcnt;
    int *p_deg, *p_off, *p_cur, *p_srcs;
    cudaGetSymbolAddress((void**)&p_h,    g_h);
    cudaGetSymbolAddress((void**)&p_mid,  g_mid);
    cudaGetSymbolAddress((void**)&p_as,   g_asrc);
    cudaGetSymbolAddress((void**)&p_ad,   g_adst);
    cudaGetSymbolAddress((void**)&p_deg,  g_deg);
    cudaGetSymbolAddress((void**)&p_off,  g_off);
    cudaGetSymbolAddress((void**)&p_cur,  g_cur);
    cudaGetSymbolAddress((void**)&p_srcs, g_srcs);
    cudaGetSymbolAddress((void**)&p_gsum, g_gsum);
    cudaGetSymbolAddress((void**)&p_gcnt, g_gcnt);

    static cudaStream_t s2 = 0;
    static cudaEvent_t evFork = 0, evJoin = 0;
    if (s2 == 0) {
        cudaStreamCreateWithFlags(&s2, cudaStreamNonBlocking);
        cudaEventCreateWithFlags(&evFork, cudaEventDisableTiming);
        cudaEventCreateWithFlags(&evJoin, cudaEventDisableTiming);
    }

    const int TB = 256;
    int node_blocks = (N_NODES + TB - 1) / TB;
    int edge_blocks = (N_EDGES + TB - 1) / TB;
    int gemm_blocks = (N_NODES + 31) / 32;
    int agg_blocks  = (N_NODES + 7) / 8;

    // fork: CSR build + pool counts run concurrently with gemm1
    cudaEventRecord(evFork, 0);
    cudaStreamWaitEvent(s2, evFork, 0);

    zero_all<<<node_blocks, TB, 0, s2>>>(p_deg, p_gsum, p_gcnt);
    hist_dst<<<edge_blocks, TB, 0, s2>>>(edst, p_deg);
    scan_deg<<<1, 1024, 0, s2>>>(p_deg, p_off, p_cur);
    scatter_edges<<<edge_blocks, TB, 0, s2>>>(esrc, edst, p_cur, p_srcs);
    pool_cnt_hist<<<node_blocks, TB, 0, s2>>>(batch, p_gcnt);
    cudaEventRecord(evJoin, s2);

    gemm_alpha_kernel<<<gemm_blocks, TB>>>(x, W1, att_src1, att_dst1, p_h, p_as, p_ad, HEADS);

    cudaStreamWaitEvent(0, evJoin, 0);

    agg_layer1<<<agg_blocks, TB>>>(p_srcs, p_off, p_as, p_ad, p_h,
                                   b1, bn_g, bn_b, bn_m, bn_v, p_mid);

    gemm_alpha_kernel<<<gemm_blocks, TB>>>(p_mid, W2, att_src2, att_dst2, p_h, p_as, p_ad, 1);
    agg_layer2<<<agg_blocks, TB>>>(p_srcs, p_off, p_as, p_ad, p_h, batch, p_gsum);

    classifier<<<GRAPHS, DIM>>>(p_gsum, p_gcnt, b2, Wc1, bc1, Wc2, bc2, out);
}

// round 8
// speedup vs baseline: 2.1787x; 1.1177x over previous
#include <cuda_runtime.h>
#include <cuda_bf16.h>
#include <math.h>

#define N_NODES 50000
#define N_EDGES 800000
#define DIM     128
#define HEADS   8
#define GRAPHS  64
#define NCLASS  10
#define SLOPE   0.2f
#define BN_EPS  1e-5f

// ---------------- scratch (device globals) ----------------------------------
__device__ __nv_bfloat16 g_h[N_NODES * DIM];  // h = X@W in bf16 (message payload)
__device__ float g_mid[N_NODES * DIM];        // layer1 output after BN+ELU (fp32)
__device__ float g_w1r[DIM * DIM];            // W1 rounded to tf32
__device__ float g_w2r[DIM * DIM];            // W2 rounded to tf32
__device__ float g_asrc[N_NODES * HEADS];
__device__ float g_adst[N_NODES * HEADS];
__device__ int   g_deg[N_NODES];
__device__ int   g_off[N_NODES + 1];
__device__ int   g_cur[N_NODES];
__device__ int   g_srcs[N_EDGES];             // CSR-sorted source node ids
__device__ float g_gsum[GRAPHS * DIM];
__device__ float g_gcnt[GRAPHS];

__device__ __forceinline__ float leaky(float x) { return x > 0.f ? x : SLOPE * x; }

__device__ __forceinline__ void bf16x4_unpack(uint2 v, float2& lo, float2& hi)
{
    lo = __bfloat1622float2(*(const __nv_bfloat162*)&v.x);
    hi = __bfloat1622float2(*(const __nv_bfloat162*)&v.y);
}

__device__ __forceinline__ unsigned int f2tf32(float f)
{
    unsigned int u;
    asm("cvt.rna.tf32.f32 %0, %1;" : "=r"(u) : "f"(f));
    return u;
}

// ---------------- W rounding (tf32) ------------------------------------------
__global__ void round_w_tf32(const float* __restrict__ W1, const float* __restrict__ W2,
                             float* __restrict__ W1r, float* __restrict__ W2r)
{
    int i = blockIdx.x * blockDim.x + threadIdx.x;
    if (i < DIM * DIM) {
        W1r[i] = __uint_as_float(f2tf32(W1[i]));
        W2r[i] = __uint_as_float(f2tf32(W2[i]));
    }
}

// ---------------- CSR build --------------------------------------------------
__global__ void zero_all(int* __restrict__ deg, float* __restrict__ gsum,
                         float* __restrict__ gcnt)
{
    int i = blockIdx.x * blockDim.x + threadIdx.x;
    if (i < N_NODES) deg[i] = 0;
    if (i < GRAPHS * DIM) gsum[i] = 0.f;
    if (i < GRAPHS) gcnt[i] = 0.f;
}

__global__ void hist_dst(const int* __restrict__ dst, int* __restrict__ deg)
{
    int e = blockIdx.x * blockDim.x + threadIdx.x;
    if (e < N_EDGES) atomicAdd(&deg[dst[e]], 1);
}

__global__ void scan_deg(const int* __restrict__ deg, int* __restrict__ off,
                         int* __restrict__ cur)
{
    __shared__ int s[1024];
    int t = threadIdx.x;
    const int R = (N_NODES + 1023) / 1024;
    int base = t * R;
    int sum = 0;
    for (int i = 0; i < R; i++) {
        int idx = base + i;
        if (idx < N_NODES) sum += deg[idx];
    }
    s[t] = sum;
    __syncthreads();
    for (int d = 1; d < 1024; d <<= 1) {
        int u = (t >= d) ? s[t - d] : 0;
        __syncthreads();
        s[t] += u;
        __syncthreads();
    }
    int run = s[t] - sum;
    for (int i = 0; i < R; i++) {
        int idx = base + i;
        if (idx < N_NODES) {
            off[idx] = run;
            cur[idx] = run;
            run += deg[idx];
        }
    }
    if (t == 0) off[N_NODES] = N_EDGES;
}

__global__ void scatter_edges(const int* __restrict__ src, const int* __restrict__ dst,
                              int* __restrict__ cur, int* __restrict__ srcs)
{
    int e = blockIdx.x * blockDim.x + threadIdx.x;
    if (e < N_EDGES) {
        int pos = atomicAdd(&cur[dst[e]], 1);
        srcs[pos] = src[e];
    }
}

// ---------------- tensor-core GEMM (h = X @ W, tf32 mma) ---------------------
// 8 warps/block, each warp: 16 rows x 128 cols via mma.m16n8k8.
// fp32 accumulate; H stored bf16; alpha dots computed from accum fragments.
__global__ void __launch_bounds__(256) gemm_mma_kernel(
        const float* __restrict__ X,
        const float* __restrict__ Wr,     // tf32-rounded, [K=128][N=128] row-major
        const float* __restrict__ attS,
        const float* __restrict__ attD,
        __nv_bfloat16* __restrict__ Hout,
        float* __restrict__ aS,
        float* __restrict__ aD,
        int heads)
{
    __shared__ float sS[DIM], sD[DIM];
    int tid  = threadIdx.x;
    int lane = tid & 31;
    int w    = tid >> 5;
    if (tid < DIM) { sS[tid] = attS[tid]; sD[tid] = attD[tid]; }
    __syncthreads();

    int m0 = blockIdx.x * 128 + w * 16;
    if (m0 >= N_NODES) return;          // warp-uniform (N % 16 == 0)

    int kc  = lane & 3;                 // k within 8-step (and +4)
    int nc  = lane >> 2;                // n within 8-tile / row group
    int r1  = m0 + nc;                  // rows lane>>2 and +8
    int r2  = r1 + 8;

    const float* x1 = X + r1 * DIM;
    const float* x2 = X + r2 * DIM;

    float acc[16][4];
#pragma unroll
    for (int nt = 0; nt < 16; nt++) {
        acc[nt][0] = 0.f; acc[nt][1] = 0.f; acc[nt][2] = 0.f; acc[nt][3] = 0.f;
    }

#pragma unroll
    for (int ks = 0; ks < 16; ks++) {
        int k0 = ks * 8;
        unsigned int a0 = f2tf32(x1[k0 + kc]);
        unsigned int a1 = f2tf32(x2[k0 + kc]);
        unsigned int a2 = f2tf32(x1[k0 + kc + 4]);
        unsigned int a3 = f2tf32(x2[k0 + kc + 4]);
        const float* wb0 = Wr + (k0 + kc) * DIM + nc;
        const float* wb1 = wb0 + 4 * DIM;
#pragma unroll
        for (int nt = 0; nt < 16; nt++) {
            unsigned int b0 = __float_as_uint(wb0[nt * 8]);
            unsigned int b1 = __float_as_uint(wb1[nt * 8]);
            asm("mma.sync.aligned.m16n8k8.row.col.f32.tf32.tf32.f32 "
                "{%0,%1,%2,%3}, {%4,%5,%6,%7}, {%8,%9}, {%0,%1,%2,%3};"
                : "+f"(acc[nt][0]), "+f"(acc[nt][1]), "+f"(acc[nt][2]), "+f"(acc[nt][3])
                : "r"(a0), "r"(a1), "r"(a2), "r"(a3), "r"(b0), "r"(b1));
        }
    }

    int cb2 = (lane & 3) * 2;           // col pair base within an 8-tile

#pragma unroll
    for (int rr = 0; rr < 2; rr++) {
        int row = (rr == 0) ? r1 : r2;  // validity warp-uniform
        // store H row slice (bf16 pairs; 4 lanes cover each 8-col tile)
#pragma unroll
        for (int nt = 0; nt < 16; nt++) {
            __nv_bfloat162 p = __floats2bfloat162_rn(acc[nt][rr * 2], acc[nt][rr * 2 + 1]);
            *(__nv_bfloat162*)(Hout + row * DIM + nt * 8 + cb2) = p;
        }
        // alpha dot products
        float tps = 0.f, tpd = 0.f;
#pragma unroll
        for (int h = 0; h < 8; h++) {
            int c0 = h * 16 + cb2;
            float v0 = acc[2 * h][rr * 2],     v1 = acc[2 * h][rr * 2 + 1];
            float v2 = acc[2 * h + 1][rr * 2], v3 = acc[2 * h + 1][rr * 2 + 1];
            float ps = v0 * sS[c0] + v1 * sS[c0 + 1] + v2 * sS[c0 + 8] + v3 * sS[c0 + 9];
            float pd = v0 * sD[c0] + v1 * sD[c0 + 1] + v2 * sD[c0 + 8] + v3 * sD[c0 + 9];
            ps += __shfl_xor_sync(0xffffffff, ps, 1);
            ps += __shfl_xor_sync(0xffffffff, ps, 2);
            pd += __shfl_xor_sync(0xffffffff, pd, 1);
            pd += __shfl_xor_sync(0xffffffff, pd, 2);
            if (heads == HEADS) {
                if ((lane & 3) == 0) {
                    aS[row * HEADS + h] = ps;
                    aD[row * HEADS + h] = pd;
                }
            } else { tps += ps; tpd += pd; }
        }
        if (heads == 1 && (lane & 3) == 0) { aS[row] = tps; aD[row] = tpd; }
    }
}

// ---------------- layer 1 fused aggregation (+bias+BN+ELU) ------------------
__global__ void __launch_bounds__(256) agg_layer1(
        const int* __restrict__ srcs, const int* __restrict__ off,
        const float* __restrict__ aS, const float* __restrict__ aD,
        const __nv_bfloat16* __restrict__ H,
        const float* __restrict__ b1,
        const float* __restrict__ bn_g, const float* __restrict__ bn_b,
        const float* __restrict__ bn_m, const float* __restrict__ bn_v,
        float* __restrict__ out)
{
    int node = blockIdx.x * 8 + (threadIdx.x >> 5);
    if (node >= N_NODES) return;
    int lane = threadIdx.x & 31;
    int h    = lane >> 2;
    const uint2* H4 = (const uint2*)H;

    float aD_h = aD[node * HEADS + h];
    float denA = __expf(leaky(aS[node * HEADS + h] + aD_h));   // self loop
    float2 slo, shi;
    bf16x4_unpack(H4[node * 32 + lane], slo, shi);
    float4 accA = make_float4(slo.x * denA, slo.y * denA, shi.x * denA, shi.y * denA);
    float denB = 0.f;
    float4 accB = make_float4(0.f, 0.f, 0.f, 0.f);

    int beg = off[node], end = off[node + 1];
    int n = end - beg;
    if (n > 0) {
        int last = end - 1;
        int cntB = n >> 1;
        int cntA = n - cntB;
        int iA = beg;
        int iB = min(beg + 1, last);
        int   sA  = srcs[iA],              sB  = srcs[iB];
        float asA = aS[sA * HEADS + h],    asB = aS[sB * HEADS + h];
        uint2 hA  = H4[sA * 32 + lane],    hB  = H4[sB * 32 + lane];
        for (int t = 0; t < cntA; t++) {
            int iA2 = min(iA + 2, last), iB2 = min(iB + 2, last);
            int   sA2  = srcs[iA2],             sB2  = srcs[iB2];
            float asA2 = aS[sA2 * HEADS + h],   asB2 = aS[sB2 * HEADS + h];
            uint2 hA2  = H4[sA2 * 32 + lane],   hB2  = H4[sB2 * 32 + lane];

            float exA = __expf(leaky(asA + aD_h));
            denA += exA;
            float2 lo, hi;
            bf16x4_unpack(hA, lo, hi);
            accA.x = fmaf(lo.x, exA, accA.x);
            accA.y = fmaf(lo.y, exA, accA.y);
            accA.z = fmaf(hi.x, exA, accA.z);
            accA.w = fmaf(hi.y, exA, accA.w);

            if (t < cntB) {
                float exB = __expf(leaky(asB + aD_h));
                denB += exB;
                bf16x4_unpack(hB, lo, hi);
                accB.x = fmaf(lo.x, exB, accB.x);
                accB.y = fmaf(lo.y, exB, accB.y);
                accB.z = fmaf(hi.x, exB, accB.z);
                accB.w = fmaf(hi.y, exB, accB.w);
            }
            iA = iA2; iB = iB2;
            asA = asA2; asB = asB2; hA = hA2; hB = hB2;
        }
    }
    float den = denA + denB;
    float4 acc = make_float4(accA.x + accB.x, accA.y + accB.y,
                             accA.z + accB.z, accA.w + accB.w);
    float inv = 1.f / den;

    float4 bb = ((const float4*)b1)[lane];
    float4 gg = ((const float4*)bn_g)[lane];
    float4 be = ((const float4*)bn_b)[lane];
    float4 mu = ((const float4*)bn_m)[lane];
    float4 va = ((const float4*)bn_v)[lane];
    float4 o;
    o.x = (acc.x * inv + bb.x - mu.x) * gg.x * rsqrtf(va.x + BN_EPS) + be.x;
    o.y = (acc.y * inv + bb.y - mu.y) * gg.y * rsqrtf(va.y + BN_EPS) + be.y;
    o.z = (acc.z * inv + bb.z - mu.z) * gg.z * rsqrtf(va.z + BN_EPS) + be.z;
    o.w = (acc.w * inv + bb.w - mu.w) * gg.w * rsqrtf(va.w + BN_EPS) + be.w;
    o.x = o.x > 0.f ? o.x : expm1f(o.x);
    o.y = o.y > 0.f ? o.y : expm1f(o.y);
    o.z = o.z > 0.f ? o.z : expm1f(o.z);
    o.w = o.w > 0.f ? o.w : expm1f(o.w);
    ((float4*)out)[node * 32 + lane] = o;
}

// ---------------- layer 2 fused aggregation (+pool) -------------------------
__global__ void __launch_bounds__(256) agg_layer2(
        const int* __restrict__ srcs, const int* __restrict__ off,
        const float* __restrict__ aS, const float* __restrict__ aD,
        const __nv_bfloat16* __restrict__ H,
        const int* __restrict__ batch,
        float* __restrict__ gsum)
{
    __shared__ float sacc[8][DIM];
    __shared__ int   sbatch[8];
    int wid  = threadIdx.x >> 5;
    int lane = threadIdx.x & 31;
    int node = blockIdx.x * 8 + wid;
    bool valid = node < N_NODES;
    const uint2* H4 = (const uint2*)H;

    float4 acc = make_float4(0.f, 0.f, 0.f, 0.f);
    int g = -1;
    if (valid) {
        float aDn  = aD[node];
        float denA = __expf(leaky(aS[node] + aDn));   // self loop
        float2 slo, shi;
        bf16x4_unpack(H4[node * 32 + lane], slo, shi);
        float4 accA = make_float4(slo.x * denA, slo.y * denA, shi.x * denA, shi.y * denA);
        float denB = 0.f;
        float4 accB = make_float4(0.f, 0.f, 0.f, 0.f);

        int beg = off[node], end = off[node + 1];
        int n = end - beg;
        if (n > 0) {
            int last = end - 1;
            int cntB = n >> 1;
            int cntA = n - cntB;
            int iA = beg;
            int iB = min(beg + 1, last);
            int   sA  = srcs[iA],           sB  = srcs[iB];
            float asA = aS[sA],             asB = aS[sB];
            uint2 hA  = H4[sA * 32 + lane], hB  = H4[sB * 32 + lane];
            for (int t = 0; t < cntA; t++) {
                int iA2 = min(iA + 2, last), iB2 = min(iB + 2, last);
                int   sA2  = srcs[iA2],            sB2  = srcs[iB2];
                float asA2 = aS[sA2],              asB2 = aS[sB2];
                uint2 hA2  = H4[sA2 * 32 + lane],  hB2  = H4[sB2 * 32 + lane];

                float exA = __expf(leaky(asA + aDn));
                denA += exA;
                float2 lo, hi;
                bf16x4_unpack(hA, lo, hi);
                accA.x = fmaf(lo.x, exA, accA.x);
                accA.y = fmaf(lo.y, exA, accA.y);
                accA.z = fmaf(hi.x, exA, accA.z);
                accA.w = fmaf(hi.y, exA, accA.w);

                if (t < cntB) {
                    float exB = __expf(leaky(asB + aDn));
                    denB += exB;
                    bf16x4_unpack(hB, lo, hi);
                    accB.x = fmaf(lo.x, exB, accB.x);
                    accB.y = fmaf(lo.y, exB, accB.y);
                    accB.z = fmaf(hi.x, exB, accB.z);
                    accB.w = fmaf(hi.y, exB, accB.w);
                }
                iA = iA2; iB = iB2;
                asA = asA2; asB = asB2; hA = hA2; hB = hB2;
            }
        }
        float den = denA + denB;
        float inv = 1.f / den;
        acc.x = (accA.x + accB.x) * inv;
        acc.y = (accA.y + accB.y) * inv;
        acc.z = (accA.z + accB.z) * inv;
        acc.w = (accA.w + accB.w) * inv;
        g = batch[node];
    }
    if (lane == 0) sbatch[wid] = g;
    ((float4*)sacc[wid])[lane] = acc;
    __syncthreads();

    int g0 = sbatch[0];
    bool uniform = (g0 >= 0);
#pragma unroll
    for (int w = 1; w < 8; w++) uniform &= (sbatch[w] == g0);

    if (uniform) {
        if (threadIdx.x < DIM) {
            float v = 0.f;
#pragma unroll
            for (int w = 0; w < 8; w++) v += sacc[w][threadIdx.x];
            atomicAdd(&gsum[g0 * DIM + threadIdx.x], v);
        }
    } else if (valid) {
        float* dp = &gsum[g * DIM + lane * 4];
        atomicAdd(dp + 0, acc.x);
        atomicAdd(dp + 1, acc.y);
        atomicAdd(dp + 2, acc.z);
        atomicAdd(dp + 3, acc.w);
    }
}

// ---------------- pool counts (smem histogram) -------------------------------
__global__ void pool_cnt_hist(const int* __restrict__ batch, float* __restrict__ gcnt)
{
    __shared__ int hist[GRAPHS];
    int t = threadIdx.x;
    if (t < GRAPHS) hist[t] = 0;
    __syncthreads();
    int i = blockIdx.x * blockDim.x + t;
    if (i < N_NODES) atomicAdd(&hist[batch[i]], 1);
    __syncthreads();
    if (t < GRAPHS && hist[t] > 0) atomicAdd(&gcnt[t], (float)hist[t]);
}

// ---------------- classifier MLP ---------------------------------------------
__global__ void classifier(const float* __restrict__ gsum, const float* __restrict__ gcnt,
                           const float* __restrict__ b2,
                           const float* __restrict__ Wc1, const float* __restrict__ bc1,
                           const float* __restrict__ Wc2, const float* __restrict__ bc2,
                           float* __restrict__ out)
{
    __shared__ float emb[DIM];
    __shared__ float z[64];
    int g = blockIdx.x, t = threadIdx.x;
    float cnt = fmaxf(gcnt[g], 1.f);
    emb[t] = gsum[g * DIM + t] / cnt + b2[t];
    __syncthreads();
    if (t < 64) {
        float a = bc1[t];
#pragma unroll 8
        for (int k = 0; k < DIM; k++) a = fmaf(emb[k], Wc1[k * 64 + t], a);
        z[t] = a > 0.f ? a : expm1f(a);
    }
    __syncthreads();
    if (t < NCLASS) {
        float a = bc2[t];
#pragma unroll
        for (int k = 0; k < 64; k++) a = fmaf(z[k], Wc2[k * NCLASS + t], a);
        out[g * NCLASS + t] = a;
    }
}

// ---------------- launch ------------------------------------------------------
extern "C" void kernel_launch(void* const* d_in, const int* in_sizes, int n_in,
                              void* d_out, int out_size)
{
    const float* x        = (const float*)d_in[0];
    const int*   esrc     = (const int*)  d_in[1];
    const int*   edst     = (const int*)  d_in[2];
    const int*   batch    = (const int*)  d_in[3];
    const float* W1       = (const float*)d_in[4];
    const float* b1       = (const float*)d_in[5];
    const float* att_src1 = (const float*)d_in[6];
    const float* att_dst1 = (const float*)d_in[7];
    const float* W2       = (const float*)d_in[8];
    const float* b2       = (const float*)d_in[9];
    const float* att_src2 = (const float*)d_in[10];
    const float* att_dst2 = (const float*)d_in[11];
    const float* bn_g     = (const float*)d_in[12];
    const float* bn_b     = (const float*)d_in[13];
    const float* bn_m     = (const float*)d_in[14];
    const float* bn_v     = (const float*)d_in[15];
    const float* Wc1      = (const float*)d_in[16];
    const float* bc1      = (const float*)d_in[17];
    const float* Wc2      = (const float*)d_in[18];
    const float* bc2      = (const float*)d_in[19];
    float* out = (float*)d_out;

    __nv_bfloat16 *p_h;
    float *p_mid, *p_w1r, *p_w2r, *p_as, *p_ad, *p_gsum, *p_gcnt;
    int *p_deg, *p_off, *p_cur, *p_srcs;
    cudaGetSymbolAddress((void**)&p_h,    g_h);
    cudaGetSymbolAddress((void**)&p_mid,  g_mid);
    cudaGetSymbolAddress((void**)&p_w1r,  g_w1r);
    cudaGetSymbolAddress((void**)&p_w2r,  g_w2r);
    cudaGetSymbolAddress((void**)&p_as,   g_asrc);
    cudaGetSymbolAddress((void**)&p_ad,   g_adst);
    cudaGetSymbolAddress((void**)&p_deg,  g_deg);
    cudaGetSymbolAddress((void**)&p_off,  g_off);
    cudaGetSymbolAddress((void**)&p_cur,  g_cur);
    cudaGetSymbolAddress((void**)&p_srcs, g_srcs);
    cudaGetSymbolAddress((void**)&p_gsum, g_gsum);
    cudaGetSymbolAddress((void**)&p_gcnt, g_gcnt);

    static cudaStream_t s2 = 0;
    static cudaEvent_t evFork = 0, evJoin = 0;
    if (s2 == 0) {
        cudaStreamCreateWithFlags(&s2, cudaStreamNonBlocking);
        cudaEventCreateWithFlags(&evFork, cudaEventDisableTiming);
        cudaEventCreateWithFlags(&evJoin, cudaEventDisableTiming);
    }

    const int TB = 256;
    int node_blocks = (N_NODES + TB - 1) / TB;
    int edge_blocks = (N_EDGES + TB - 1) / TB;
    int gemm_blocks = (N_NODES + 127) / 128;
    int agg_blocks  = (N_NODES + 7) / 8;

    // fork s2 off stream 0
    cudaEventRecord(evFork, 0);
    cudaStreamWaitEvent(s2, evFork, 0);

    // launch order chosen so gemm1 is code launch index 3 (ncu -s5 lands there)
    round_w_tf32<<<(DIM * DIM + TB - 1) / TB, TB>>>(W1, W2, p_w1r, p_w2r);   // 0
    zero_all<<<node_blocks, TB, 0, s2>>>(p_deg, p_gsum, p_gcnt);             // 1
    hist_dst<<<edge_blocks, TB, 0, s2>>>(edst, p_deg);                       // 2
    gemm_mma_kernel<<<gemm_blocks, TB>>>(x, p_w1r, att_src1, att_dst1,       // 3 <- profiled
                                         p_h, p_as, p_ad, HEADS);
    scan_deg<<<1, 1024, 0, s2>>>(p_deg, p_off, p_cur);                       // 4
    scatter_edges<<<edge_blocks, TB, 0, s2>>>(esrc, edst, p_cur, p_srcs);    // 5
    pool_cnt_hist<<<node_blocks, TB, 0, s2>>>(batch, p_gcnt);                // 6
    cudaEventRecord(evJoin, s2);
    cudaStreamWaitEvent(0, evJoin, 0);

    agg_layer1<<<agg_blocks, TB>>>(p_srcs, p_off, p_as, p_ad, p_h,           // 7
                                   b1, bn_g, bn_b, bn_m, bn_v, p_mid);
    gemm_mma_kernel<<<gemm_blocks, TB>>>(p_mid, p_w2r, att_src2, att_dst2,   // 8
                                         p_h, p_as, p_ad, 1);
    agg_layer2<<<agg_blocks, TB>>>(p_srcs, p_off, p_as, p_ad, p_h, batch, p_gsum); // 9
    classifier<<<GRAPHS, DIM>>>(p_gsum, p_gcnt, b2, Wc1, bc1, Wc2, bc2, out);      // 10
}

// round 9
// speedup vs baseline: 2.5363x; 1.1641x over previous
#include <cuda_runtime.h>
#include <cuda_bf16.h>
#include <math.h>

#define N_NODES 50000
#define N_EDGES 800000
#define DIM     128
#define HEADS   8
#define GRAPHS  64
#define NCLASS  10
#define SLOPE   0.2f
#define BN_EPS  1e-5f

// ---------------- scratch (device globals) ----------------------------------
__device__ __nv_bfloat16 g_h[N_NODES * DIM];  // h = X@W in bf16 (message payload)
__device__ float g_mid[N_NODES * DIM];        // layer1 output after BN+ELU (fp32)
__device__ float g_w1p[DIM * DIM];            // W1 tf32, mma-fragment-major
__device__ float g_w2p[DIM * DIM];            // W2 tf32, mma-fragment-major
__device__ float g_asrc[N_NODES * HEADS];
__device__ float g_adst[N_NODES * HEADS];
__device__ int   g_deg[N_NODES];
__device__ int   g_off[N_NODES + 1];
__device__ int   g_cur[N_NODES];
__device__ int   g_srcs[N_EDGES];             // CSR-sorted source node ids
__device__ float g_gsum[GRAPHS * DIM];
__device__ float g_gcnt[GRAPHS];

__device__ __forceinline__ float leaky(float x) { return x > 0.f ? x : SLOPE * x; }

__device__ __forceinline__ void bf16x4_unpack(uint2 v, float2& lo, float2& hi)
{
    lo = __bfloat1622float2(*(const __nv_bfloat162*)&v.x);
    hi = __bfloat1622float2(*(const __nv_bfloat162*)&v.y);
}

__device__ __forceinline__ unsigned int f2tf32(float f)
{
    unsigned int u;
    asm("cvt.rna.tf32.f32 %0, %1;" : "=r"(u) : "f"(f));
    return u;
}

// ---------------- W pack: tf32 + mma-fragment-major ---------------------------
// layout: fragment i = (ks*8 + p)*32 + lane; float4 = {b0(nt=2p), b1(2p), b0(2p+1), b1(2p+1)}
// where kc=lane&3, nc=lane>>2, b0 = W[(ks*8+kc)][nt*8+nc], b1 = W[(ks*8+kc+4)][nt*8+nc]
__global__ void pack_w_tf32(const float* __restrict__ W1, const float* __restrict__ W2,
                            float* __restrict__ P1, float* __restrict__ P2)
{
    int i = blockIdx.x * blockDim.x + threadIdx.x;
    if (i >= 16 * 8 * 32) return;
    int lane = i & 31;
    int p    = (i >> 5) & 7;
    int ks   = i >> 8;
    int kc = lane & 3, nc = lane >> 2;
    int r0 = ks * 8 + kc, r1 = r0 + 4;
    int c0 = (2 * p) * 8 + nc, c1 = (2 * p + 1) * 8 + nc;
    float4 v1, v2;
    v1.x = __uint_as_float(f2tf32(W1[r0 * DIM + c0]));
    v1.y = __uint_as_float(f2tf32(W1[r1 * DIM + c0]));
    v1.z = __uint_as_float(f2tf32(W1[r0 * DIM + c1]));
    v1.w = __uint_as_float(f2tf32(W1[r1 * DIM + c1]));
    v2.x = __uint_as_float(f2tf32(W2[r0 * DIM + c0]));
    v2.y = __uint_as_float(f2tf32(W2[r1 * DIM + c0]));
    v2.z = __uint_as_float(f2tf32(W2[r0 * DIM + c1]));
    v2.w = __uint_as_float(f2tf32(W2[r1 * DIM + c1]));
    ((float4*)P1)[i] = v1;
    ((float4*)P2)[i] = v2;
}

// ---------------- CSR build --------------------------------------------------
__global__ void zero_all(int* __restrict__ deg, float* __restrict__ gsum,
                         float* __restrict__ gcnt)
{
    int i = blockIdx.x * blockDim.x + threadIdx.x;
    if (i < N_NODES) deg[i] = 0;
    if (i < GRAPHS * DIM) gsum[i] = 0.f;
    if (i < GRAPHS) gcnt[i] = 0.f;
}

__global__ void hist_dst(const int* __restrict__ dst, int* __restrict__ deg)
{
    int e = blockIdx.x * blockDim.x + threadIdx.x;
    if (e < N_EDGES) atomicAdd(&deg[dst[e]], 1);
}

__global__ void scan_deg(const int* __restrict__ deg, int* __restrict__ off,
                         int* __restrict__ cur)
{
    __shared__ int s[1024];
    int t = threadIdx.x;
    const int R = (N_NODES + 1023) / 1024;
    int base = t * R;
    int sum = 0;
    for (int i = 0; i < R; i++) {
        int idx = base + i;
        if (idx < N_NODES) sum += deg[idx];
    }
    s[t] = sum;
    __syncthreads();
    for (int d = 1; d < 1024; d <<= 1) {
        int u = (t >= d) ? s[t - d] : 0;
        __syncthreads();
        s[t] += u;
        __syncthreads();
    }
    int run = s[t] - sum;
    for (int i = 0; i < R; i++) {
        int idx = base + i;
        if (idx < N_NODES) {
            off[idx] = run;
            cur[idx] = run;
            run += deg[idx];
        }
    }
    if (t == 0) off[N_NODES] = N_EDGES;
}

__global__ void scatter_edges(const int* __restrict__ src, const int* __restrict__ dst,
                              int* __restrict__ cur, int* __restrict__ srcs)
{
    int e = blockIdx.x * blockDim.x + threadIdx.x;
    if (e < N_EDGES) {
        int pos = atomicAdd(&cur[dst[e]], 1);
        srcs[pos] = src[e];
    }
}

// ---------------- tensor-core GEMM (h = X @ W, tf32 mma) ---------------------
// X tile (128x128) staged in smem (pad 132, conflict-free A reads);
// B via packed fragment-major LDG.128 (L1-resident, coalesced).
__global__ void __launch_bounds__(256, 2) gemm_mma_kernel(
        const float* __restrict__ X,
        const float* __restrict__ Wpack,
        const float* __restrict__ attS,
        const float* __restrict__ attD,
        __nv_bfloat16* __restrict__ Hout,
        float* __restrict__ aS,
        float* __restrict__ aD,
        int heads)
{
    extern __shared__ float xsm[];            // 128 * 132 floats
    __shared__ float sS[DIM], sD[DIM];
    int tid  = threadIdx.x;
    int lane = tid & 31;
    int w    = tid >> 5;
    if (tid < DIM) { sS[tid] = attS[tid]; sD[tid] = attD[tid]; }

    int row0 = blockIdx.x * 128;
    const float4* X4 = (const float4*)X;
#pragma unroll
    for (int j = 0; j < 16; j++) {
        int idx = tid + j * 256;              // 0..4095
        int r = idx >> 5, c = idx & 31;
        float4 v = (row0 + r < N_NODES) ? X4[(row0 + r) * 32 + c]
                                        : make_float4(0.f, 0.f, 0.f, 0.f);
        *(float4*)&xsm[r * 132 + c * 4] = v;
    }
    __syncthreads();

    int m0w = w * 16;
    if (row0 + m0w >= N_NODES) return;        // warp-uniform (50000 % 16 == 0)

    int kc = lane & 3;
    int nc = lane >> 2;
    const float* x1 = xsm + (m0w + nc) * 132;
    const float* x2 = x1 + 8 * 132;

    float acc[16][4];
#pragma unroll
    for (int nt = 0; nt < 16; nt++) {
        acc[nt][0] = 0.f; acc[nt][1] = 0.f; acc[nt][2] = 0.f; acc[nt][3] = 0.f;
    }

    const float4* Wp4 = (const float4*)Wpack;
#pragma unroll
    for (int ks = 0; ks < 16; ks++) {
        int k0 = ks * 8;
        unsigned int a0 = f2tf32(x1[k0 + kc]);
        unsigned int a1 = f2tf32(x2[k0 + kc]);
        unsigned int a2 = f2tf32(x1[k0 + kc + 4]);
        unsigned int a3 = f2tf32(x2[k0 + kc + 4]);
#pragma unroll
        for (int p = 0; p < 8; p++) {
            float4 bb = Wp4[(ks * 8 + p) * 32 + lane];
            asm("mma.sync.aligned.m16n8k8.row.col.f32.tf32.tf32.f32 "
                "{%0,%1,%2,%3}, {%4,%5,%6,%7}, {%8,%9}, {%0,%1,%2,%3};"
                : "+f"(acc[2*p][0]), "+f"(acc[2*p][1]), "+f"(acc[2*p][2]), "+f"(acc[2*p][3])
                : "r"(a0), "r"(a1), "r"(a2), "r"(a3),
                  "r"(__float_as_uint(bb.x)), "r"(__float_as_uint(bb.y)));
            asm("mma.sync.aligned.m16n8k8.row.col.f32.tf32.tf32.f32 "
                "{%0,%1,%2,%3}, {%4,%5,%6,%7}, {%8,%9}, {%0,%1,%2,%3};"
                : "+f"(acc[2*p+1][0]), "+f"(acc[2*p+1][1]), "+f"(acc[2*p+1][2]), "+f"(acc[2*p+1][3])
                : "r"(a0), "r"(a1), "r"(a2), "r"(a3),
                  "r"(__float_as_uint(bb.z)), "r"(__float_as_uint(bb.w)));
        }
    }

    int cb2 = (lane & 3) * 2;
    int r1 = row0 + m0w + nc;
    int r2 = r1 + 8;

#pragma unroll
    for (int rr = 0; rr < 2; rr++) {
        int row = (rr == 0) ? r1 : r2;
#pragma unroll
        for (int nt = 0; nt < 16; nt++) {
            __nv_bfloat162 pr = __floats2bfloat162_rn(acc[nt][rr * 2], acc[nt][rr * 2 + 1]);
            *(__nv_bfloat162*)(Hout + row * DIM + nt * 8 + cb2) = pr;
        }
        float tps = 0.f, tpd = 0.f;
#pragma unroll
        for (int h = 0; h < 8; h++) {
            int c0 = h * 16 + cb2;
            float v0 = acc[2 * h][rr * 2],     v1 = acc[2 * h][rr * 2 + 1];
            float v2 = acc[2 * h + 1][rr * 2], v3 = acc[2 * h + 1][rr * 2 + 1];
            float ps = v0 * sS[c0] + v1 * sS[c0 + 1] + v2 * sS[c0 + 8] + v3 * sS[c0 + 9];
            float pd = v0 * sD[c0] + v1 * sD[c0 + 1] + v2 * sD[c0 + 8] + v3 * sD[c0 + 9];
            ps += __shfl_xor_sync(0xffffffff, ps, 1);
            ps += __shfl_xor_sync(0xffffffff, ps, 2);
            pd += __shfl_xor_sync(0xffffffff, pd, 1);
            pd += __shfl_xor_sync(0xffffffff, pd, 2);
            if (heads == HEADS) {
                if ((lane & 3) == 0) {
                    aS[row * HEADS + h] = ps;
                    aD[row * HEADS + h] = pd;
                }
            } else { tps += ps; tpd += pd; }
        }
        if (heads == 1 && (lane & 3) == 0) { aS[row] = tps; aD[row] = tpd; }
    }
}

// ---------------- layer 1 fused aggregation (+bias+BN+ELU) ------------------
__global__ void __launch_bounds__(256) agg_layer1(
        const int* __restrict__ srcs, const int* __restrict__ off,
        const float* __restrict__ aS, const float* __restrict__ aD,
        const __nv_bfloat16* __restrict__ H,
        const float* __restrict__ b1,
        const float* __restrict__ bn_g, const float* __restrict__ bn_b,
        const float* __restrict__ bn_m, const float* __restrict__ bn_v,
        float* __restrict__ out)
{
    int node = blockIdx.x * 8 + (threadIdx.x >> 5);
    if (node >= N_NODES) return;
    int lane = threadIdx.x & 31;
    int h    = lane >> 2;
    const uint2* H4 = (const uint2*)H;

    float aD_h = aD[node * HEADS + h];
    float denA = __expf(leaky(aS[node * HEADS + h] + aD_h));   // self loop
    float2 slo, shi;
    bf16x4_unpack(H4[node * 32 + lane], slo, shi);
    float4 accA = make_float4(slo.x * denA, slo.y * denA, shi.x * denA, shi.y * denA);
    float denB = 0.f;
    float4 accB = make_float4(0.f, 0.f, 0.f, 0.f);

    int beg = off[node], end = off[node + 1];
    int n = end - beg;
    if (n > 0) {
        int last = end - 1;
        int cntB = n >> 1;
        int cntA = n - cntB;
        int iA = beg;
        int iB = min(beg + 1, last);
        int   sA  = srcs[iA],              sB  = srcs[iB];
        float asA = aS[sA * HEADS + h],    asB = aS[sB * HEADS + h];
        uint2 hA  = H4[sA * 32 + lane],    hB  = H4[sB * 32 + lane];
        for (int t = 0; t < cntA; t++) {
            int iA2 = min(iA + 2, last), iB2 = min(iB + 2, last);
            int   sA2  = srcs[iA2],             sB2  = srcs[iB2];
            float asA2 = aS[sA2 * HEADS + h],   asB2 = aS[sB2 * HEADS + h];
            uint2 hA2  = H4[sA2 * 32 + lane],   hB2  = H4[sB2 * 32 + lane];

            float exA = __expf(leaky(asA + aD_h));
            denA += exA;
            float2 lo, hi;
            bf16x4_unpack(hA, lo, hi);
            accA.x = fmaf(lo.x, exA, accA.x);
            accA.y = fmaf(lo.y, exA, accA.y);
            accA.z = fmaf(hi.x, exA, accA.z);
            accA.w = fmaf(hi.y, exA, accA.w);

            if (t < cntB) {
                float exB = __expf(leaky(asB + aD_h));
                denB += exB;
                bf16x4_unpack(hB, lo, hi);
                accB.x = fmaf(lo.x, exB, accB.x);
                accB.y = fmaf(lo.y, exB, accB.y);
                accB.z = fmaf(hi.x, exB, accB.z);
                accB.w = fmaf(hi.y, exB, accB.w);
            }
            iA = iA2; iB = iB2;
            asA = asA2; asB = asB2; hA = hA2; hB = hB2;
        }
    }
    float den = denA + denB;
    float4 acc = make_float4(accA.x + accB.x, accA.y + accB.y,
                             accA.z + accB.z, accA.w + accB.w);
    float inv = 1.f / den;

    float4 bb = ((const float4*)b1)[lane];
    float4 gg = ((const float4*)bn_g)[lane];
    float4 be = ((const float4*)bn_b)[lane];
    float4 mu = ((const float4*)bn_m)[lane];
    float4 va = ((const float4*)bn_v)[lane];
    float4 o;
    o.x = (acc.x * inv + bb.x - mu.x) * gg.x * rsqrtf(va.x + BN_EPS) + be.x;
    o.y = (acc.y * inv + bb.y - mu.y) * gg.y * rsqrtf(va.y + BN_EPS) + be.y;
    o.z = (acc.z * inv + bb.z - mu.z) * gg.z * rsqrtf(va.z + BN_EPS) + be.z;
    o.w = (acc.w * inv + bb.w - mu.w) * gg.w * rsqrtf(va.w + BN_EPS) + be.w;
    o.x = o.x > 0.f ? o.x : expm1f(o.x);
    o.y = o.y > 0.f ? o.y : expm1f(o.y);
    o.z = o.z > 0.f ? o.z : expm1f(o.z);
    o.w = o.w > 0.f ? o.w : expm1f(o.w);
    ((float4*)out)[node * 32 + lane] = o;
}

// ---------------- layer 2 fused aggregation (+pool) -------------------------
__global__ void __launch_bounds__(256) agg_layer2(
        const int* __restrict__ srcs, const int* __restrict__ off,
        const float* __restrict__ aS, const float* __restrict__ aD,
        const __nv_bfloat16* __restrict__ H,
        const int* __restrict__ batch,
        float* __restrict__ gsum)
{
    __shared__ float sacc[8][DIM];
    __shared__ int   sbatch[8];
    int wid  = threadIdx.x >> 5;
    int lane = threadIdx.x & 31;
    int node = blockIdx.x * 8 + wid;
    bool valid = node < N_NODES;
    const uint2* H4 = (const uint2*)H;

    float4 acc = make_float4(0.f, 0.f, 0.f, 0.f);
    int g = -1;
    if (valid) {
        float aDn  = aD[node];
        float denA = __expf(leaky(aS[node] + aDn));   // self loop
        float2 slo, shi;
        bf16x4_unpack(H4[node * 32 + lane], slo, shi);
        float4 accA = make_float4(slo.x * denA, slo.y * denA, shi.x * denA, shi.y * denA);
        float denB = 0.f;
        float4 accB = make_float4(0.f, 0.f, 0.f, 0.f);

        int beg = off[node], end = off[node + 1];
        int n = end - beg;
        if (n > 0) {
            int last = end - 1;
            int cntB = n >> 1;
            int cntA = n - cntB;
            int iA = beg;
            int iB = min(beg + 1, last);
            int   sA  = srcs[iA],           sB  = srcs[iB];
            float asA = aS[sA],             asB = aS[sB];
            uint2 hA  = H4[sA * 32 + lane], hB  = H4[sB * 32 + lane];
            for (int t = 0; t < cntA; t++) {
                int iA2 = min(iA + 2, last), iB2 = min(iB + 2, last);
                int   sA2  = srcs[iA2],            sB2  = srcs[iB2];
                float asA2 = aS[sA2],              asB2 = aS[sB2];
                uint2 hA2  = H4[sA2 * 32 + lane],  hB2  = H4[sB2 * 32 + lane];

                float exA = __expf(leaky(asA + aDn));
                denA += exA;
                float2 lo, hi;
                bf16x4_unpack(hA, lo, hi);
                accA.x = fmaf(lo.x, exA, accA.x);
                accA.y = fmaf(lo.y, exA, accA.y);
                accA.z = fmaf(hi.x, exA, accA.z);
                accA.w = fmaf(hi.y, exA, accA.w);

                if (t < cntB) {
                    float exB = __expf(leaky(asB + aDn));
                    denB += exB;
                    bf16x4_unpack(hB, lo, hi);
                    accB.x = fmaf(lo.x, exB, accB.x);
                    accB.y = fmaf(lo.y, exB, accB.y);
                    accB.z = fmaf(hi.x, exB, accB.z);
                    accB.w = fmaf(hi.y, exB, accB.w);
                }
                iA = iA2; iB = iB2;
                asA = asA2; asB = asB2; hA = hA2; hB = hB2;
            }
        }
        float den = denA + denB;
        float inv = 1.f / den;
        acc.x = (accA.x + accB.x) * inv;
        acc.y = (accA.y + accB.y) * inv;
        acc.z = (accA.z + accB.z) * inv;
        acc.w = (accA.w + accB.w) * inv;
        g = batch[node];
    }
    if (lane == 0) sbatch[wid] = g;
    ((float4*)sacc[wid])[lane] = acc;
    __syncthreads();

    int g0 = sbatch[0];
    bool uniform = (g0 >= 0);
#pragma unroll
    for (int w = 1; w < 8; w++) uniform &= (sbatch[w] == g0);

    if (uniform) {
        if (threadIdx.x < DIM) {
            float v = 0.f;
#pragma unroll
            for (int w = 0; w < 8; w++) v += sacc[w][threadIdx.x];
            atomicAdd(&gsum[g0 * DIM + threadIdx.x], v);
        }
    } else if (valid) {
        float* dp = &gsum[g * DIM + lane * 4];
        atomicAdd(dp + 0, acc.x);
        atomicAdd(dp + 1, acc.y);
        atomicAdd(dp + 2, acc.z);
        atomicAdd(dp + 3, acc.w);
    }
}

// ---------------- pool counts (smem histogram) -------------------------------
__global__ void pool_cnt_hist(const int* __restrict__ batch, float* __restrict__ gcnt)
{
    __shared__ int hist[GRAPHS];
    int t = threadIdx.x;
    if (t < GRAPHS) hist[t] = 0;
    __syncthreads();
    int i = blockIdx.x * blockDim.x + t;
    if (i < N_NODES) atomicAdd(&hist[batch[i]], 1);
    __syncthreads();
    if (t < GRAPHS && hist[t] > 0) atomicAdd(&gcnt[t], (float)hist[t]);
}

// ---------------- classifier MLP ---------------------------------------------
__global__ void classifier(const float* __restrict__ gsum, const float* __restrict__ gcnt,
                           const float* __restrict__ b2,
                           const float* __restrict__ Wc1, const float* __restrict__ bc1,
                           const float* __restrict__ Wc2, const float* __restrict__ bc2,
                           float* __restrict__ out)
{
    __shared__ float emb[DIM];
    __shared__ float z[64];
    int g = blockIdx.x, t = threadIdx.x;
    float cnt = fmaxf(gcnt[g], 1.f);
    emb[t] = gsum[g * DIM + t] / cnt + b2[t];
    __syncthreads();
    if (t < 64) {
        float a = bc1[t];
#pragma unroll 8
        for (int k = 0; k < DIM; k++) a = fmaf(emb[k], Wc1[k * 64 + t], a);
        z[t] = a > 0.f ? a : expm1f(a);
    }
    __syncthreads();
    if (t < NCLASS) {
        float a = bc2[t];
#pragma unroll
        for (int k = 0; k < 64; k++) a = fmaf(z[k], Wc2[k * NCLASS + t], a);
        out[g * NCLASS + t] = a;
    }
}

// ---------------- launch ------------------------------------------------------
extern "C" void kernel_launch(void* const* d_in, const int* in_sizes, int n_in,
                              void* d_out, int out_size)
{
    const float* x        = (const float*)d_in[0];
    const int*   esrc     = (const int*)  d_in[1];
    const int*   edst     = (const int*)  d_in[2];
    const int*   batch    = (const int*)  d_in[3];
    const float* W1       = (const float*)d_in[4];
    const float* b1       = (const float*)d_in[5];
    const float* att_src1 = (const float*)d_in[6];
    const float* att_dst1 = (const float*)d_in[7];
    const float* W2       = (const float*)d_in[8];
    const float* b2       = (const float*)d_in[9];
    const float* att_src2 = (const float*)d_in[10];
    const float* att_dst2 = (const float*)d_in[11];
    const float* bn_g     = (const float*)d_in[12];
    const float* bn_b     = (const float*)d_in[13];
    const float* bn_m     = (const float*)d_in[14];
    const float* bn_v     = (const float*)d_in[15];
    const float* Wc1      = (const float*)d_in[16];
    const float* bc1      = (const float*)d_in[17];
    const float* Wc2      = (const float*)d_in[18];
    const float* bc2      = (const float*)d_in[19];
    float* out = (float*)d_out;

    __nv_bfloat16 *p_h;
    float *p_mid, *p_w1p, *p_w2p, *p_as, *p_ad, *p_gsum, *p_gcnt;
    int *p_deg, *p_off, *p_cur, *p_srcs;
    cudaGetSymbolAddress((void**)&p_h,    g_h);
    cudaGetSymbolAddress((void**)&p_mid,  g_mid);
    cudaGetSymbolAddress((void**)&p_w1p,  g_w1p);
    cudaGetSymbolAddress((void**)&p_w2p,  g_w2p);
    cudaGetSymbolAddress((void**)&p_as,   g_asrc);
    cudaGetSymbolAddress((void**)&p_ad,   g_adst);
    cudaGetSymbolAddress((void**)&p_deg,  g_deg);
    cudaGetSymbolAddress((void**)&p_off,  g_off);
    cudaGetSymbolAddress((void**)&p_cur,  g_cur);
    cudaGetSymbolAddress((void**)&p_srcs, g_srcs);
    cudaGetSymbolAddress((void**)&p_gsum, g_gsum);
    cudaGetSymbolAddress((void**)&p_gcnt, g_gcnt);

    static cudaStream_t s2 = 0;
    static cudaEvent_t evFork = 0, evJoin = 0;
    const int XSMEM = 128 * 132 * (int)sizeof(float);
    if (s2 == 0) {
        cudaStreamCreateWithFlags(&s2, cudaStreamNonBlocking);
        cudaEventCreateWithFlags(&evFork, cudaEventDisableTiming);
        cudaEventCreateWithFlags(&evJoin, cudaEventDisableTiming);
        cudaFuncSetAttribute(gemm_mma_kernel,
                             cudaFuncAttributeMaxDynamicSharedMemorySize, XSMEM);
    }

    const int TB = 256;
    int node_blocks = (N_NODES + TB - 1) / TB;
    int edge_blocks = (N_EDGES + TB - 1) / TB;
    int gemm_blocks = (N_NODES + 127) / 128;
    int agg_blocks  = (N_NODES + 7) / 8;

    // fork s2 off stream 0
    cudaEventRecord(evFork, 0);
    cudaStreamWaitEvent(s2, evFork, 0);

    // launch order: gemm1 stays at code launch index 3 (profiled)
    pack_w_tf32<<<(16 * 8 * 32 + TB - 1) / TB, TB>>>(W1, W2, p_w1p, p_w2p);  // 0
    zero_all<<<node_blocks, TB, 0, s2>>>(p_deg, p_gsum, p_gcnt);             // 1
    hist_dst<<<edge_blocks, TB, 0, s2>>>(edst, p_deg);                       // 2
    gemm_mma_kernel<<<gemm_blocks, TB, XSMEM>>>(x, p_w1p, att_src1, att_dst1,// 3 <- profiled
                                                p_h, p_as, p_ad, HEADS);
    scan_deg<<<1, 1024, 0, s2>>>(p_deg, p_off, p_cur);                       // 4
    scatter_edges<<<edge_blocks, TB, 0, s2>>>(esrc, edst, p_cur, p_srcs);    // 5
    pool_cnt_hist<<<node_blocks, TB, 0, s2>>>(batch, p_gcnt);                // 6
    cudaEventRecord(evJoin, s2);
    cudaStreamWaitEvent(0, evJoin, 0);

    agg_layer1<<<agg_blocks, TB>>>(p_srcs, p_off, p_as, p_ad, p_h,           // 7
                                   b1, bn_g, bn_b, bn_m, bn_v, p_mid);
    gemm_mma_kernel<<<gemm_blocks, TB, XSMEM>>>(p_mid, p_w2p, att_src2,      // 8
                                                att_dst2, p_h, p_as, p_ad, 1);
    agg_layer2<<<agg_blocks, TB>>>(p_srcs, p_off, p_as, p_ad, p_h, batch, p_gsum); // 9
    classifier<<<GRAPHS, DIM>>>(p_gsum, p_gcnt, b2, Wc1, bc1, Wc2, bc2, out);      // 10
}

// round 10
// speedup vs baseline: 2.9991x; 1.1825x over previous
#include <cuda_runtime.h>
#include <cuda_bf16.h>
#include <math.h>

#define N_NODES 50000
#define N_EDGES 800000
#define DIM     128
#define HEADS   8
#define GRAPHS  64
#define NCLASS  10
#define SLOPE   0.2f
#define BN_EPS  1e-5f
#define NB_CSR  132

// ---------------- scratch (device globals) ----------------------------------
__device__ __nv_bfloat16 g_h[N_NODES * DIM];  // h = X@W in bf16 (message payload)
__device__ float g_mid[N_NODES * DIM];        // layer1 output after BN+ELU (fp32)
__device__ float g_w1p[DIM * DIM];            // W1 tf32, mma-fragment-major
__device__ float g_w2p[DIM * DIM];            // W2 tf32, mma-fragment-major
__device__ float g_asrc[N_NODES * HEADS];
__device__ float g_adst[N_NODES * HEADS];
__device__ int   g_deg[N_NODES];
__device__ int   g_off[N_NODES + 1];
__device__ int   g_cur[N_NODES];
__device__ int   g_srcs[N_EDGES];             // CSR-sorted source node ids
__device__ float g_gsum[GRAPHS * DIM];
__device__ float g_gcnt[GRAPHS];
__device__ int   g_barcnt = 0;
__device__ int   g_bargen = 0;
__device__ int   g_bsum[NB_CSR];

__device__ __forceinline__ float leaky(float x) { return x > 0.f ? x : SLOPE * x; }

__device__ __forceinline__ void bf16x4_unpack(uint2 v, float2& lo, float2& hi)
{
    lo = __bfloat1622float2(*(const __nv_bfloat162*)&v.x);
    hi = __bfloat1622float2(*(const __nv_bfloat162*)&v.y);
}

__device__ __forceinline__ unsigned int f2tf32(float f)
{
    unsigned int u;
    asm("cvt.rna.tf32.f32 %0, %1;" : "=r"(u) : "f"(f));
    return u;
}

// sense-reversing grid barrier (all NB_CSR blocks resident)
__device__ __forceinline__ void grid_barrier()
{
    __syncthreads();
    if (threadIdx.x == 0) {
        __threadfence();
        int gen = ((volatile int*)&g_bargen)[0];
        if (atomicAdd(&g_barcnt, 1) == (int)gridDim.x - 1) {
            g_barcnt = 0;
            __threadfence();
            atomicAdd(&g_bargen, 1);
        } else {
            while (((volatile int*)&g_bargen)[0] == gen) { }
        }
        __threadfence();
    }
    __syncthreads();
}

// ---------------- fused CSR build + zeroing + pool counts --------------------
__global__ void __launch_bounds__(256) build_csr(
        const int* __restrict__ esrc, const int* __restrict__ edst,
        const int* __restrict__ batch,
        int* __restrict__ deg, int* __restrict__ off, int* __restrict__ cur,
        int* __restrict__ srcs, float* __restrict__ gsum, float* __restrict__ gcnt)
{
    __shared__ int sm[256];
    __shared__ int bh[GRAPHS];
    int t   = threadIdx.x;
    int gid = blockIdx.x * 256 + t;
    const int stride = NB_CSR * 256;

    // phase 0: zero deg, gsum, gcnt, smem batch hist
    for (int i = gid; i < N_NODES; i += stride) deg[i] = 0;
    for (int i = gid; i < GRAPHS * DIM; i += stride) gsum[i] = 0.f;
    if (gid < GRAPHS) gcnt[gid] = 0.f;
    if (t < GRAPHS) bh[t] = 0;
    grid_barrier();                                    // B1

    // phase 1: degree histogram + batch histogram
    for (int e = gid; e < N_EDGES; e += stride) atomicAdd(&deg[edst[e]], 1);
    for (int i = gid; i < N_NODES; i += stride) atomicAdd(&bh[batch[i]], 1);
    __syncthreads();
    if (t < GRAPHS && bh[t] > 0) atomicAdd(&gcnt[t], (float)bh[t]);
    grid_barrier();                                    // B2

    // phase 2: scan (2 nodes per thread)
    int i0 = gid * 2, i1 = gid * 2 + 1;
    int d0 = (i0 < N_NODES) ? deg[i0] : 0;
    int d1 = (i1 < N_NODES) ? deg[i1] : 0;
    int msum = d0 + d1;
    sm[t] = msum;
    __syncthreads();
    for (int d = 1; d < 256; d <<= 1) {
        int u = (t >= d) ? sm[t - d] : 0;
        __syncthreads();
        sm[t] += u;
        __syncthreads();
    }
    if (t == 255) g_bsum[blockIdx.x] = sm[255];
    int texcl = sm[t] - msum;
    grid_barrier();                                    // B3
    if (blockIdx.x == 0 && t == 0) {
        int run = 0;
        for (int i = 0; i < NB_CSR; i++) { int v = g_bsum[i]; g_bsum[i] = run; run += v; }
    }
    grid_barrier();                                    // B4
    int base = g_bsum[blockIdx.x] + texcl;
    if (i0 < N_NODES) { off[i0] = base;      cur[i0] = base; }
    if (i1 < N_NODES) { off[i1] = base + d0; cur[i1] = base + d0; }
    if (gid == 0) off[N_NODES] = N_EDGES;
    grid_barrier();                                    // B5

    // phase 3: scatter edges (CSR stores src directly)
    for (int e = gid; e < N_EDGES; e += stride) {
        int pos = atomicAdd(&cur[edst[e]], 1);
        srcs[pos] = esrc[e];
    }
}

// ---------------- W pack: tf32 + mma-fragment-major ---------------------------
__global__ void pack_w_tf32(const float* __restrict__ W1, const float* __restrict__ W2,
                            float* __restrict__ P1, float* __restrict__ P2)
{
    int i = blockIdx.x * blockDim.x + threadIdx.x;
    if (i >= 16 * 8 * 32) return;
    int lane = i & 31;
    int p    = (i >> 5) & 7;
    int ks   = i >> 8;
    int kc = lane & 3, nc = lane >> 2;
    int r0 = ks * 8 + kc, r1 = r0 + 4;
    int c0 = (2 * p) * 8 + nc, c1 = (2 * p + 1) * 8 + nc;
    float4 v1, v2;
    v1.x = __uint_as_float(f2tf32(W1[r0 * DIM + c0]));
    v1.y = __uint_as_float(f2tf32(W1[r1 * DIM + c0]));
    v1.z = __uint_as_float(f2tf32(W1[r0 * DIM + c1]));
    v1.w = __uint_as_float(f2tf32(W1[r1 * DIM + c1]));
    v2.x = __uint_as_float(f2tf32(W2[r0 * DIM + c0]));
    v2.y = __uint_as_float(f2tf32(W2[r1 * DIM + c0]));
    v2.z = __uint_as_float(f2tf32(W2[r0 * DIM + c1]));
    v2.w = __uint_as_float(f2tf32(W2[r1 * DIM + c1]));
    ((float4*)P1)[i] = v1;
    ((float4*)P2)[i] = v2;
}

// ---------------- tensor-core GEMM (h = X @ W, tf32 mma) ---------------------
__global__ void __launch_bounds__(256, 2) gemm_mma_kernel(
        const float* __restrict__ X,
        const float* __restrict__ Wpack,
        const float* __restrict__ attS,
        const float* __restrict__ attD,
        __nv_bfloat16* __restrict__ Hout,
        float* __restrict__ aS,
        float* __restrict__ aD,
        int heads)
{
    extern __shared__ float xsm[];            // 128 * 132 floats
    __shared__ float sS[DIM], sD[DIM];
    int tid  = threadIdx.x;
    int lane = tid & 31;
    int w    = tid >> 5;
    if (tid < DIM) { sS[tid] = attS[tid]; sD[tid] = attD[tid]; }

    int row0 = blockIdx.x * 128;
    const float4* X4 = (const float4*)X;
#pragma unroll
    for (int j = 0; j < 16; j++) {
        int idx = tid + j * 256;
        int r = idx >> 5, c = idx & 31;
        float4 v = (row0 + r < N_NODES) ? X4[(row0 + r) * 32 + c]
                                        : make_float4(0.f, 0.f, 0.f, 0.f);
        *(float4*)&xsm[r * 132 + c * 4] = v;
    }
    __syncthreads();

    int m0w = w * 16;
    if (row0 + m0w >= N_NODES) return;

    int kc = lane & 3;
    int nc = lane >> 2;
    const float* x1 = xsm + (m0w + nc) * 132;
    const float* x2 = x1 + 8 * 132;

    float acc[16][4];
#pragma unroll
    for (int nt = 0; nt < 16; nt++) {
        acc[nt][0] = 0.f; acc[nt][1] = 0.f; acc[nt][2] = 0.f; acc[nt][3] = 0.f;
    }

    const float4* Wp4 = (const float4*)Wpack;
#pragma unroll
    for (int ks = 0; ks < 16; ks++) {
        int k0 = ks * 8;
        unsigned int a0 = f2tf32(x1[k0 + kc]);
        unsigned int a1 = f2tf32(x2[k0 + kc]);
        unsigned int a2 = f2tf32(x1[k0 + kc + 4]);
        unsigned int a3 = f2tf32(x2[k0 + kc + 4]);
#pragma unroll
        for (int p = 0; p < 8; p++) {
            float4 bb = Wp4[(ks * 8 + p) * 32 + lane];
            asm("mma.sync.aligned.m16n8k8.row.col.f32.tf32.tf32.f32 "
                "{%0,%1,%2,%3}, {%4,%5,%6,%7}, {%8,%9}, {%0,%1,%2,%3};"
                : "+f"(acc[2*p][0]), "+f"(acc[2*p][1]), "+f"(acc[2*p][2]), "+f"(acc[2*p][3])
                : "r"(a0), "r"(a1), "r"(a2), "r"(a3),
                  "r"(__float_as_uint(bb.x)), "r"(__float_as_uint(bb.y)));
            asm("mma.sync.aligned.m16n8k8.row.col.f32.tf32.tf32.f32 "
                "{%0,%1,%2,%3}, {%4,%5,%6,%7}, {%8,%9}, {%0,%1,%2,%3};"
                : "+f"(acc[2*p+1][0]), "+f"(acc[2*p+1][1]), "+f"(acc[2*p+1][2]), "+f"(acc[2*p+1][3])
                : "r"(a0), "r"(a1), "r"(a2), "r"(a3),
                  "r"(__float_as_uint(bb.z)), "r"(__float_as_uint(bb.w)));
        }
    }

    int cb2 = (lane & 3) * 2;
    int r1 = row0 + m0w + nc;
    int r2 = r1 + 8;

#pragma unroll
    for (int rr = 0; rr < 2; rr++) {
        int row = (rr == 0) ? r1 : r2;
#pragma unroll
        for (int nt = 0; nt < 16; nt++) {
            __nv_bfloat162 pr = __floats2bfloat162_rn(acc[nt][rr * 2], acc[nt][rr * 2 + 1]);
            *(__nv_bfloat162*)(Hout + row * DIM + nt * 8 + cb2) = pr;
        }
        float tps = 0.f, tpd = 0.f;
#pragma unroll
        for (int h = 0; h < 8; h++) {
            int c0 = h * 16 + cb2;
            float v0 = acc[2 * h][rr * 2],     v1 = acc[2 * h][rr * 2 + 1];
            float v2 = acc[2 * h + 1][rr * 2], v3 = acc[2 * h + 1][rr * 2 + 1];
            float ps = v0 * sS[c0] + v1 * sS[c0 + 1] + v2 * sS[c0 + 8] + v3 * sS[c0 + 9];
            float pd = v0 * sD[c0] + v1 * sD[c0 + 1] + v2 * sD[c0 + 8] + v3 * sD[c0 + 9];
            ps += __shfl_xor_sync(0xffffffff, ps, 1);
            ps += __shfl_xor_sync(0xffffffff, ps, 2);
            pd += __shfl_xor_sync(0xffffffff, pd, 1);
            pd += __shfl_xor_sync(0xffffffff, pd, 2);
            if (heads == HEADS) {
                if ((lane & 3) == 0) {
                    aS[row * HEADS + h] = ps;
                    aD[row * HEADS + h] = pd;
                }
            } else { tps += ps; tpd += pd; }
        }
        if (heads == 1 && (lane & 3) == 0) { aS[row] = tps; aD[row] = tpd; }
    }
}

// ---------------- layer 1 fused aggregation (+bias+BN+ELU) ------------------
// one warp per dst node; 4 interleaved edge chains, each prefetched 1 deep.
__global__ void __launch_bounds__(256) agg_layer1(
        const int* __restrict__ srcs, const int* __restrict__ off,
        const float* __restrict__ aS, const float* __restrict__ aD,
        const __nv_bfloat16* __restrict__ H,
        const float* __restrict__ b1,
        const float* __restrict__ bn_g, const float* __restrict__ bn_b,
        const float* __restrict__ bn_m, const float* __restrict__ bn_v,
        float* __restrict__ out)
{
    int node = blockIdx.x * 8 + (threadIdx.x >> 5);
    if (node >= N_NODES) return;
    int lane = threadIdx.x & 31;
    int h    = lane >> 2;
    const uint2* H4 = (const uint2*)H;

    float aD_h = aD[node * HEADS + h];
    float den0 = __expf(leaky(aS[node * HEADS + h] + aD_h));   // self loop
    float2 slo, shi;
    bf16x4_unpack(H4[node * 32 + lane], slo, shi);
    float4 accc[4];
    float  denc[4];
    accc[0] = make_float4(slo.x * den0, slo.y * den0, shi.x * den0, shi.y * den0);
    denc[0] = den0;
#pragma unroll
    for (int c = 1; c < 4; c++) {
        accc[c] = make_float4(0.f, 0.f, 0.f, 0.f);
        denc[c] = 0.f;
    }

    int beg = off[node], end = off[node + 1];
    int n = end - beg;
    if (n > 0) {
        int last = end - 1;
        int cnt0 = (n + 3) >> 2;
        int   idx[4];
        float as[4];
        uint2 hv[4];
#pragma unroll
        for (int c = 0; c < 4; c++) {
            int i = min(beg + c, last);
            int s = srcs[i];
            as[c] = aS[s * HEADS + h];
            hv[c] = H4[s * 32 + lane];
            idx[c] = i;
        }
        for (int t = 0; t < cnt0; t++) {
            float asn[4];
            uint2 hn[4];
#pragma unroll
            for (int c = 0; c < 4; c++) {
                int i2 = min(idx[c] + 4, last);
                int s2 = srcs[i2];
                asn[c] = aS[s2 * HEADS + h];
                hn[c]  = H4[s2 * 32 + lane];
                idx[c] = i2;
            }
#pragma unroll
            for (int c = 0; c < 4; c++) {
                if (c + 4 * t < n) {
                    float ex = __expf(leaky(as[c] + aD_h));
                    denc[c] += ex;
                    float2 lo, hi;
                    bf16x4_unpack(hv[c], lo, hi);
                    accc[c].x = fmaf(lo.x, ex, accc[c].x);
                    accc[c].y = fmaf(lo.y, ex, accc[c].y);
                    accc[c].z = fmaf(hi.x, ex, accc[c].z);
                    accc[c].w = fmaf(hi.y, ex, accc[c].w);
                }
                as[c] = asn[c]; hv[c] = hn[c];
            }
        }
    }
    float den = (denc[0] + denc[1]) + (denc[2] + denc[3]);
    float4 acc;
    acc.x = (accc[0].x + accc[1].x) + (accc[2].x + accc[3].x);
    acc.y = (accc[0].y + accc[1].y) + (accc[2].y + accc[3].y);
    acc.z = (accc[0].z + accc[1].z) + (accc[2].z + accc[3].z);
    acc.w = (accc[0].w + accc[1].w) + (accc[2].w + accc[3].w);
    float inv = 1.f / den;

    float4 bb = ((const float4*)b1)[lane];
    float4 gg = ((const float4*)bn_g)[lane];
    float4 be = ((const float4*)bn_b)[lane];
    float4 mu = ((const float4*)bn_m)[lane];
    float4 va = ((const float4*)bn_v)[lane];
    float4 o;
    o.x = (acc.x * inv + bb.x - mu.x) * gg.x * rsqrtf(va.x + BN_EPS) + be.x;
    o.y = (acc.y * inv + bb.y - mu.y) * gg.y * rsqrtf(va.y + BN_EPS) + be.y;
    o.z = (acc.z * inv + bb.z - mu.z) * gg.z * rsqrtf(va.z + BN_EPS) + be.z;
    o.w = (acc.w * inv + bb.w - mu.w) * gg.w * rsqrtf(va.w + BN_EPS) + be.w;
    o.x = o.x > 0.f ? o.x : expm1f(o.x);
    o.y = o.y > 0.f ? o.y : expm1f(o.y);
    o.z = o.z > 0.f ? o.z : expm1f(o.z);
    o.w = o.w > 0.f ? o.w : expm1f(o.w);
    ((float4*)out)[node * 32 + lane] = o;
}

// ---------------- layer 2 fused aggregation (+pool) -------------------------
__global__ void __launch_bounds__(256) agg_layer2(
        const int* __restrict__ srcs, const int* __restrict__ off,
        const float* __restrict__ aS, const float* __restrict__ aD,
        const __nv_bfloat16* __restrict__ H,
        const int* __restrict__ batch,
        float* __restrict__ gsum)
{
    __shared__ float sacc[8][DIM];
    __shared__ int   sbatch[8];
    int wid  = threadIdx.x >> 5;
    int lane = threadIdx.x & 31;
    int node = blockIdx.x * 8 + wid;
    bool valid = node < N_NODES;
    const uint2* H4 = (const uint2*)H;

    float4 acc = make_float4(0.f, 0.f, 0.f, 0.f);
    int g = -1;
    if (valid) {
        float aDn  = aD[node];
        float den0 = __expf(leaky(aS[node] + aDn));   // self loop
        float2 slo, shi;
        bf16x4_unpack(H4[node * 32 + lane], slo, shi);
        float4 accc[4];
        float  denc[4];
        accc[0] = make_float4(slo.x * den0, slo.y * den0, shi.x * den0, shi.y * den0);
        denc[0] = den0;
#pragma unroll
        for (int c = 1; c < 4; c++) {
            accc[c] = make_float4(0.f, 0.f, 0.f, 0.f);
            denc[c] = 0.f;
        }

        int beg = off[node], end = off[node + 1];
        int n = end - beg;
        if (n > 0) {
            int last = end - 1;
            int cnt0 = (n + 3) >> 2;
            int   idx[4];
            float as[4];
            uint2 hv[4];
#pragma unroll
            for (int c = 0; c < 4; c++) {
                int i = min(beg + c, last);
                int s = srcs[i];
                as[c] = aS[s];
                hv[c] = H4[s * 32 + lane];
                idx[c] = i;
            }
            for (int t = 0; t < cnt0; t++) {
                float asn[4];
                uint2 hn[4];
#pragma unroll
                for (int c = 0; c < 4; c++) {
                    int i2 = min(idx[c] + 4, last);
                    int s2 = srcs[i2];
                    asn[c] = aS[s2];
                    hn[c]  = H4[s2 * 32 + lane];
                    idx[c] = i2;
                }
#pragma unroll
                for (int c = 0; c < 4; c++) {
                    if (c + 4 * t < n) {
                        float ex = __expf(leaky(as[c] + aDn));
                        denc[c] += ex;
                        float2 lo, hi;
                        bf16x4_unpack(hv[c], lo, hi);
                        accc[c].x = fmaf(lo.x, ex, accc[c].x);
                        accc[c].y = fmaf(lo.y, ex, accc[c].y);
                        accc[c].z = fmaf(hi.x, ex, accc[c].z);
                        accc[c].w = fmaf(hi.y, ex, accc[c].w);
                    }
                    as[c] = asn[c]; hv[c] = hn[c];
                }
            }
        }
        float den = (denc[0] + denc[1]) + (denc[2] + denc[3]);
        float inv = 1.f / den;
        acc.x = ((accc[0].x + accc[1].x) + (accc[2].x + accc[3].x)) * inv;
        acc.y = ((accc[0].y + accc[1].y) + (accc[2].y + accc[3].y)) * inv;
        acc.z = ((accc[0].z + accc[1].z) + (accc[2].z + accc[3].z)) * inv;
        acc.w = ((accc[0].w + accc[1].w) + (accc[2].w + accc[3].w)) * inv;
        g = batch[node];
    }
    if (lane == 0) sbatch[wid] = g;
    ((float4*)sacc[wid])[lane] = acc;
    __syncthreads();

    int g0 = sbatch[0];
    bool uniform = (g0 >= 0);
#pragma unroll
    for (int w = 1; w < 8; w++) uniform &= (sbatch[w] == g0);

    if (uniform) {
        if (threadIdx.x < DIM) {
            float v = 0.f;
#pragma unroll
            for (int w = 0; w < 8; w++) v += sacc[w][threadIdx.x];
            atomicAdd(&gsum[g0 * DIM + threadIdx.x], v);
        }
    } else if (valid) {
        float* dp = &gsum[g * DIM + lane * 4];
        atomicAdd(dp + 0, acc.x);
        atomicAdd(dp + 1, acc.y);
        atomicAdd(dp + 2, acc.z);
        atomicAdd(dp + 3, acc.w);
    }
}

// ---------------- classifier MLP ---------------------------------------------
__global__ void classifier(const float* __restrict__ gsum, const float* __restrict__ gcnt,
                           const float* __restrict__ b2,
                           const float* __restrict__ Wc1, const float* __restrict__ bc1,
                           const float* __restrict__ Wc2, const float* __restrict__ bc2,
                           float* __restrict__ out)
{
    __shared__ float emb[DIM];
    __shared__ float z[64];
    int g = blockIdx.x, t = threadIdx.x;
    float cnt = fmaxf(gcnt[g], 1.f);
    emb[t] = gsum[g * DIM + t] / cnt + b2[t];
    __syncthreads();
    if (t < 64) {
        float a = bc1[t];
#pragma unroll 8
        for (int k = 0; k < DIM; k++) a = fmaf(emb[k], Wc1[k * 64 + t], a);
        z[t] = a > 0.f ? a : expm1f(a);
    }
    __syncthreads();
    if (t < NCLASS) {
        float a = bc2[t];
#pragma unroll
        for (int k = 0; k < 64; k++) a = fmaf(z[k], Wc2[k * NCLASS + t], a);
        out[g * NCLASS + t] = a;
    }
}

// ---------------- launch ------------------------------------------------------
extern "C" void kernel_launch(void* const* d_in, const int* in_sizes, int n_in,
                              void* d_out, int out_size)
{
    const float* x        = (const float*)d_in[0];
    const int*   esrc     = (const int*)  d_in[1];
    const int*   edst     = (const int*)  d_in[2];
    const int*   batch    = (const int*)  d_in[3];
    const float* W1       = (const float*)d_in[4];
    const float* b1       = (const float*)d_in[5];
    const float* att_src1 = (const float*)d_in[6];
    const float* att_dst1 = (const float*)d_in[7];
    const float* W2       = (const float*)d_in[8];
    const float* b2       = (const float*)d_in[9];
    const float* att_src2 = (const float*)d_in[10];
    const float* att_dst2 = (const float*)d_in[11];
    const float* bn_g     = (const float*)d_in[12];
    const float* bn_b     = (const float*)d_in[13];
    const float* bn_m     = (const float*)d_in[14];
    const float* bn_v     = (const float*)d_in[15];
    const float* Wc1      = (const float*)d_in[16];
    const float* bc1      = (const float*)d_in[17];
    const float* Wc2      = (const float*)d_in[18];
    const float* bc2      = (const float*)d_in[19];
    float* out = (float*)d_out;

    __nv_bfloat16 *p_h;
    float *p_mid, *p_w1p, *p_w2p, *p_as, *p_ad, *p_gsum, *p_gcnt;
    int *p_deg, *p_off, *p_cur, *p_srcs;
    cudaGetSymbolAddress((void**)&p_h,    g_h);
    cudaGetSymbolAddress((void**)&p_mid,  g_mid);
    cudaGetSymbolAddress((void**)&p_w1p,  g_w1p);
    cudaGetSymbolAddress((void**)&p_w2p,  g_w2p);
    cudaGetSymbolAddress((void**)&p_as,   g_asrc);
    cudaGetSymbolAddress((void**)&p_ad,   g_adst);
    cudaGetSymbolAddress((void**)&p_deg,  g_deg);
    cudaGetSymbolAddress((void**)&p_off,  g_off);
    cudaGetSymbolAddress((void**)&p_cur,  g_cur);
    cudaGetSymbolAddress((void**)&p_srcs, g_srcs);
    cudaGetSymbolAddress((void**)&p_gsum, g_gsum);
    cudaGetSymbolAddress((void**)&p_gcnt, g_gcnt);

    static cudaStream_t s2 = 0;
    static cudaEvent_t evFork = 0, evJoin = 0;
    const int XSMEM = 128 * 132 * (int)sizeof(float);
    if (s2 == 0) {
        cudaStreamCreateWithFlags(&s2, cudaStreamNonBlocking);
        cudaEventCreateWithFlags(&evFork, cudaEventDisableTiming);
        cudaEventCreateWithFlags(&evJoin, cudaEventDisableTiming);
        cudaFuncSetAttribute(gemm_mma_kernel,
                             cudaFuncAttributeMaxDynamicSharedMemorySize, XSMEM);
    }

    const int TB = 256;
    int gemm_blocks = (N_NODES + 127) / 128;
    int agg_blocks  = (N_NODES + 7) / 8;

    // fork: fused CSR build runs concurrently with pack_w + gemm1
    cudaEventRecord(evFork, 0);
    cudaStreamWaitEvent(s2, evFork, 0);

    build_csr<<<NB_CSR, TB, 0, s2>>>(esrc, edst, batch, p_deg, p_off, p_cur,  // 0
                                     p_srcs, p_gsum, p_gcnt);
    cudaEventRecord(evJoin, s2);

    pack_w_tf32<<<(16 * 8 * 32 + TB - 1) / TB, TB>>>(W1, W2, p_w1p, p_w2p);   // 1
    gemm_mma_kernel<<<gemm_blocks, TB, XSMEM>>>(x, p_w1p, att_src1, att_dst1, // 2
                                                p_h, p_as, p_ad, HEADS);
    cudaStreamWaitEvent(0, evJoin, 0);

    agg_layer1<<<agg_blocks, TB>>>(p_srcs, p_off, p_as, p_ad, p_h,            // 3 <- profiled
                                   b1, bn_g, bn_b, bn_m, bn_v, p_mid);
    gemm_mma_kernel<<<gemm_blocks, TB, XSMEM>>>(p_mid, p_w2p, att_src2,       // 4
                                                att_dst2, p_h, p_as, p_ad, 1);
    agg_layer2<<<agg_blocks, TB>>>(p_srcs, p_off, p_as, p_ad, p_h, batch, p_gsum); // 5
    classifier<<<GRAPHS, DIM>>>(p_gsum, p_gcnt, b2, Wc1, bc1, Wc2, bc2, out);      // 6
}

// round 11
// speedup vs baseline: 3.5354x; 1.1788x over previous
#include <cuda_runtime.h>
#include <cuda_bf16.h>
#include <math.h>

#define N_NODES 50000
#define N_EDGES 800000
#define DIM     128
#define HEADS   8
#define GRAPHS  64
#define NCLASS  10
#define SLOPE   0.2f
#define BN_EPS  1e-5f
#define NB_CSR  132
#define MAX_PADDED (N_EDGES + 4 * N_NODES)

// ---------------- scratch (device globals) ----------------------------------
__device__ __nv_bfloat16 g_h[(N_NODES + 1) * DIM];  // +1: sentinel row (zero-init)
__device__ float g_mid[N_NODES * DIM];
__device__ float g_w1p[DIM * DIM];
__device__ float g_w2p[DIM * DIM];
__device__ float g_asrc[(N_NODES + 1) * HEADS];     // +1: sentinel scores
__device__ float g_adst[N_NODES * HEADS];
__device__ int   g_deg[N_NODES];
__device__ int   g_off[N_NODES + 1];
__device__ int   g_cur[N_NODES];
__device__ int   g_srcs[MAX_PADDED];
__device__ float g_gsum[GRAPHS * DIM];
__device__ float g_gcnt[GRAPHS];
__device__ int   g_barcnt = 0;
__device__ int   g_bargen = 0;
__device__ int   g_bsum[NB_CSR];

__device__ __forceinline__ float leaky(float x) { return fmaxf(x, SLOPE * x); }

__device__ __forceinline__ void bf16x4_unpack(uint2 v, float2& lo, float2& hi)
{
    lo = __bfloat1622float2(*(const __nv_bfloat162*)&v.x);
    hi = __bfloat1622float2(*(const __nv_bfloat162*)&v.y);
}

__device__ __forceinline__ unsigned int f2tf32(float f)
{
    unsigned int u;
    asm("cvt.rna.tf32.f32 %0, %1;" : "=r"(u) : "f"(f));
    return u;
}

// sense-reversing grid barrier (all NB_CSR blocks resident)
__device__ __forceinline__ void grid_barrier()
{
    __syncthreads();
    if (threadIdx.x == 0) {
        __threadfence();
        int gen = ((volatile int*)&g_bargen)[0];
        if (atomicAdd(&g_barcnt, 1) == (int)gridDim.x - 1) {
            g_barcnt = 0;
            __threadfence();
            atomicAdd(&g_bargen, 1);
        } else {
            while (((volatile int*)&g_bargen)[0] == gen) { }
        }
        __threadfence();
    }
    __syncthreads();
}

// ---------------- fused CSR build (padded to 4) + zeroing + pool counts ------
__global__ void __launch_bounds__(256) build_csr(
        const int* __restrict__ esrc, const int* __restrict__ edst,
        const int* __restrict__ batch,
        int* __restrict__ deg, int* __restrict__ off, int* __restrict__ cur,
        int* __restrict__ srcs, float* __restrict__ gsum, float* __restrict__ gcnt)
{
    __shared__ int sm[256];
    __shared__ int bh[GRAPHS];
    int t   = threadIdx.x;
    int gid = blockIdx.x * 256 + t;
    const int stride = NB_CSR * 256;

    for (int i = gid; i < N_NODES; i += stride) deg[i] = 0;
    for (int i = gid; i < GRAPHS * DIM; i += stride) gsum[i] = 0.f;
    if (gid < GRAPHS) gcnt[gid] = 0.f;
    if (t < GRAPHS) bh[t] = 0;
    grid_barrier();                                    // B1

    for (int e = gid; e < N_EDGES; e += stride) atomicAdd(&deg[edst[e]], 1);
    for (int i = gid; i < N_NODES; i += stride) atomicAdd(&bh[batch[i]], 1);
    __syncthreads();
    if (t < GRAPHS && bh[t] > 0) atomicAdd(&gcnt[t], (float)bh[t]);
    grid_barrier();                                    // B2

    // scan over PADDED degrees (pad to multiple of 4)
    int i0 = gid * 2, i1 = gid * 2 + 1;
    int d0 = (i0 < N_NODES) ? deg[i0] : 0;
    int d1 = (i1 < N_NODES) ? deg[i1] : 0;
    int p0 = (d0 + 3) & ~3;
    int p1 = (d1 + 3) & ~3;
    int msum = p0 + p1;
    sm[t] = msum;
    __syncthreads();
    for (int d = 1; d < 256; d <<= 1) {
        int u = (t >= d) ? sm[t - d] : 0;
        __syncthreads();
        sm[t] += u;
        __syncthreads();
    }
    if (t == 255) g_bsum[blockIdx.x] = sm[255];
    int texcl = sm[t] - msum;
    grid_barrier();                                    // B3
    if (blockIdx.x == 0 && t == 0) {
        int run = 0;
        for (int i = 0; i < NB_CSR; i++) { int v = g_bsum[i]; g_bsum[i] = run; run += v; }
        off[N_NODES] = run;                            // total padded size
    }
    grid_barrier();                                    // B4
    int base = g_bsum[blockIdx.x] + texcl;
    if (i0 < N_NODES) { off[i0] = base;      cur[i0] = base; }
    if (i1 < N_NODES) { off[i1] = base + p0; cur[i1] = base + p0; }
    grid_barrier();                                    // B5

    // scatter edges + fill sentinel padding
    for (int e = gid; e < N_EDGES; e += stride) {
        int pos = atomicAdd(&cur[edst[e]], 1);
        srcs[pos] = esrc[e];
    }
    for (int i = gid; i < N_NODES; i += stride) {
        int st = off[i] + deg[i], en = off[i + 1];
        for (int j = st; j < en; j++) srcs[j] = N_NODES;
    }
}

// ---------------- W pack: tf32 + mma-fragment-major ---------------------------
__global__ void pack_w_tf32(const float* __restrict__ W1, const float* __restrict__ W2,
                            float* __restrict__ P1, float* __restrict__ P2)
{
    int i = blockIdx.x * blockDim.x + threadIdx.x;
    if (i >= 16 * 8 * 32) return;
    int lane = i & 31;
    int p    = (i >> 5) & 7;
    int ks   = i >> 8;
    int kc = lane & 3, nc = lane >> 2;
    int r0 = ks * 8 + kc, r1 = r0 + 4;
    int c0 = (2 * p) * 8 + nc, c1 = (2 * p + 1) * 8 + nc;
    float4 v1, v2;
    v1.x = __uint_as_float(f2tf32(W1[r0 * DIM + c0]));
    v1.y = __uint_as_float(f2tf32(W1[r1 * DIM + c0]));
    v1.z = __uint_as_float(f2tf32(W1[r0 * DIM + c1]));
    v1.w = __uint_as_float(f2tf32(W1[r1 * DIM + c1]));
    v2.x = __uint_as_float(f2tf32(W2[r0 * DIM + c0]));
    v2.y = __uint_as_float(f2tf32(W2[r1 * DIM + c0]));
    v2.z = __uint_as_float(f2tf32(W2[r0 * DIM + c1]));
    v2.w = __uint_as_float(f2tf32(W2[r1 * DIM + c1]));
    ((float4*)P1)[i] = v1;
    ((float4*)P2)[i] = v2;
}

// ---------------- tensor-core GEMM (h = X @ W, tf32 mma) ---------------------
__global__ void __launch_bounds__(256, 2) gemm_mma_kernel(
        const float* __restrict__ X,
        const float* __restrict__ Wpack,
        const float* __restrict__ attS,
        const float* __restrict__ attD,
        __nv_bfloat16* __restrict__ Hout,
        float* __restrict__ aS,
        float* __restrict__ aD,
        int heads)
{
    extern __shared__ float xsm[];            // 128 * 132 floats
    __shared__ float sS[DIM], sD[DIM];
    int tid  = threadIdx.x;
    int lane = tid & 31;
    int w    = tid >> 5;
    if (tid < DIM) { sS[tid] = attS[tid]; sD[tid] = attD[tid]; }

    // sentinel scores: padding edges contribute exp(-inf) = 0
    if (blockIdx.x == 0 && tid < heads) aS[N_NODES * heads + tid] = -1e4f;

    int row0 = blockIdx.x * 128;
    const float4* X4 = (const float4*)X;
#pragma unroll
    for (int j = 0; j < 16; j++) {
        int idx = tid + j * 256;
        int r = idx >> 5, c = idx & 31;
        float4 v = (row0 + r < N_NODES) ? X4[(row0 + r) * 32 + c]
                                        : make_float4(0.f, 0.f, 0.f, 0.f);
        *(float4*)&xsm[r * 132 + c * 4] = v;
    }
    __syncthreads();

    int m0w = w * 16;
    if (row0 + m0w >= N_NODES) return;

    int kc = lane & 3;
    int nc = lane >> 2;
    const float* x1 = xsm + (m0w + nc) * 132;
    const float* x2 = x1 + 8 * 132;

    float acc[16][4];
#pragma unroll
    for (int nt = 0; nt < 16; nt++) {
        acc[nt][0] = 0.f; acc[nt][1] = 0.f; acc[nt][2] = 0.f; acc[nt][3] = 0.f;
    }

    const float4* Wp4 = (const float4*)Wpack;
#pragma unroll
    for (int ks = 0; ks < 16; ks++) {
        int k0 = ks * 8;
        unsigned int a0 = f2tf32(x1[k0 + kc]);
        unsigned int a1 = f2tf32(x2[k0 + kc]);
        unsigned int a2 = f2tf32(x1[k0 + kc + 4]);
        unsigned int a3 = f2tf32(x2[k0 + kc + 4]);
#pragma unroll
        for (int p = 0; p < 8; p++) {
            float4 bb = Wp4[(ks * 8 + p) * 32 + lane];
            asm("mma.sync.aligned.m16n8k8.row.col.f32.tf32.tf32.f32 "
                "{%0,%1,%2,%3}, {%4,%5,%6,%7}, {%8,%9}, {%0,%1,%2,%3};"
                : "+f"(acc[2*p][0]), "+f"(acc[2*p][1]), "+f"(acc[2*p][2]), "+f"(acc[2*p][3])
                : "r"(a0), "r"(a1), "r"(a2), "r"(a3),
                  "r"(__float_as_uint(bb.x)), "r"(__float_as_uint(bb.y)));
            asm("mma.sync.aligned.m16n8k8.row.col.f32.tf32.tf32.f32 "
                "{%0,%1,%2,%3}, {%4,%5,%6,%7}, {%8,%9}, {%0,%1,%2,%3};"
                : "+f"(acc[2*p+1][0]), "+f"(acc[2*p+1][1]), "+f"(acc[2*p+1][2]), "+f"(acc[2*p+1][3])
                : "r"(a0), "r"(a1), "r"(a2), "r"(a3),
                  "r"(__float_as_uint(bb.z)), "r"(__float_as_uint(bb.w)));
        }
    }

    int cb2 = (lane & 3) * 2;
    int r1 = row0 + m0w + nc;
    int r2 = r1 + 8;

#pragma unroll
    for (int rr = 0; rr < 2; rr++) {
        int row = (rr == 0) ? r1 : r2;
#pragma unroll
        for (int nt = 0; nt < 16; nt++) {
            __nv_bfloat162 pr = __floats2bfloat162_rn(acc[nt][rr * 2], acc[nt][rr * 2 + 1]);
            *(__nv_bfloat162*)(Hout + row * DIM + nt * 8 + cb2) = pr;
        }
        float tps = 0.f, tpd = 0.f;
#pragma unroll
        for (int h = 0; h < 8; h++) {
            int c0 = h * 16 + cb2;
            float v0 = acc[2 * h][rr * 2],     v1 = acc[2 * h][rr * 2 + 1];
            float v2 = acc[2 * h + 1][rr * 2], v3 = acc[2 * h + 1][rr * 2 + 1];
            float ps = v0 * sS[c0] + v1 * sS[c0 + 1] + v2 * sS[c0 + 8] + v3 * sS[c0 + 9];
            float pd = v0 * sD[c0] + v1 * sD[c0 + 1] + v2 * sD[c0 + 8] + v3 * sD[c0 + 9];
            ps += __shfl_xor_sync(0xffffffff, ps, 1);
            ps += __shfl_xor_sync(0xffffffff, ps, 2);
            pd += __shfl_xor_sync(0xffffffff, pd, 1);
            pd += __shfl_xor_sync(0xffffffff, pd, 2);
            if (heads == HEADS) {
                if ((lane & 3) == 0) {
                    aS[row * HEADS + h] = ps;
                    aD[row * HEADS + h] = pd;
                }
            } else { tps += ps; tpd += pd; }
        }
        if (heads == 1 && (lane & 3) == 0) { aS[row] = tps; aD[row] = tpd; }
    }
}

// ---------------- layer 1 fused aggregation (+bias+BN+ELU) ------------------
// one warp per dst node; padded CSR, no predication, 4-edge flat unroll.
__global__ void __launch_bounds__(256) agg_layer1(
        const int* __restrict__ srcs, const int* __restrict__ off,
        const float* __restrict__ aS, const float* __restrict__ aD,
        const __nv_bfloat16* __restrict__ H,
        const float* __restrict__ b1,
        const float* __restrict__ bn_g, const float* __restrict__ bn_b,
        const float* __restrict__ bn_m, const float* __restrict__ bn_v,
        float* __restrict__ out)
{
    int node = blockIdx.x * 8 + (threadIdx.x >> 5);
    if (node >= N_NODES) return;
    int lane = threadIdx.x & 31;
    int h    = lane >> 2;
    const uint2* H4 = (const uint2*)H;

    float aD_h = aD[node * HEADS + h];
    float den  = __expf(leaky(aS[node * HEADS + h] + aD_h));   // self loop
    float2 slo, shi;
    bf16x4_unpack(H4[node * 32 + lane], slo, shi);
    float4 acc = make_float4(slo.x * den, slo.y * den, shi.x * den, shi.y * den);

    int beg = off[node], end = off[node + 1];
    for (int i = beg; i < end; i += 4) {
        int4 s4 = *(const int4*)(srcs + i);
        float a0 = aS[s4.x * HEADS + h];
        float a1 = aS[s4.y * HEADS + h];
        float a2 = aS[s4.z * HEADS + h];
        float a3 = aS[s4.w * HEADS + h];
        uint2 h0 = H4[s4.x * 32 + lane];
        uint2 h1 = H4[s4.y * 32 + lane];
        uint2 h2 = H4[s4.z * 32 + lane];
        uint2 h3 = H4[s4.w * 32 + lane];
        float e0 = __expf(leaky(a0 + aD_h));
        float e1 = __expf(leaky(a1 + aD_h));
        float e2 = __expf(leaky(a2 + aD_h));
        float e3 = __expf(leaky(a3 + aD_h));
        den += (e0 + e1) + (e2 + e3);
        float2 lo, hi;
        bf16x4_unpack(h0, lo, hi);
        acc.x = fmaf(lo.x, e0, acc.x); acc.y = fmaf(lo.y, e0, acc.y);
        acc.z = fmaf(hi.x, e0, acc.z); acc.w = fmaf(hi.y, e0, acc.w);
        bf16x4_unpack(h1, lo, hi);
        acc.x = fmaf(lo.x, e1, acc.x); acc.y = fmaf(lo.y, e1, acc.y);
        acc.z = fmaf(hi.x, e1, acc.z); acc.w = fmaf(hi.y, e1, acc.w);
        bf16x4_unpack(h2, lo, hi);
        acc.x = fmaf(lo.x, e2, acc.x); acc.y = fmaf(lo.y, e2, acc.y);
        acc.z = fmaf(hi.x, e2, acc.z); acc.w = fmaf(hi.y, e2, acc.w);
        bf16x4_unpack(h3, lo, hi);
        acc.x = fmaf(lo.x, e3, acc.x); acc.y = fmaf(lo.y, e3, acc.y);
        acc.z = fmaf(hi.x, e3, acc.z); acc.w = fmaf(hi.y, e3, acc.w);
    }
    float inv = 1.f / den;

    float4 bb = ((const float4*)b1)[lane];
    float4 gg = ((const float4*)bn_g)[lane];
    float4 be = ((const float4*)bn_b)[lane];
    float4 mu = ((const float4*)bn_m)[lane];
    float4 va = ((const float4*)bn_v)[lane];
    float4 o;
    o.x = (acc.x * inv + bb.x - mu.x) * gg.x * rsqrtf(va.x + BN_EPS) + be.x;
    o.y = (acc.y * inv + bb.y - mu.y) * gg.y * rsqrtf(va.y + BN_EPS) + be.y;
    o.z = (acc.z * inv + bb.z - mu.z) * gg.z * rsqrtf(va.z + BN_EPS) + be.z;
    o.w = (acc.w * inv + bb.w - mu.w) * gg.w * rsqrtf(va.w + BN_EPS) + be.w;
    o.x = o.x > 0.f ? o.x : expm1f(o.x);
    o.y = o.y > 0.f ? o.y : expm1f(o.y);
    o.z = o.z > 0.f ? o.z : expm1f(o.z);
    o.w = o.w > 0.f ? o.w : expm1f(o.w);
    ((float4*)out)[node * 32 + lane] = o;
}

// ---------------- layer 2 fused aggregation (+pool) -------------------------
__global__ void __launch_bounds__(256) agg_layer2(
        const int* __restrict__ srcs, const int* __restrict__ off,
        const float* __restrict__ aS, const float* __restrict__ aD,
        const __nv_bfloat16* __restrict__ H,
        const int* __restrict__ batch,
        float* __restrict__ gsum)
{
    __shared__ float sacc[8][DIM];
    __shared__ int   sbatch[8];
    int wid  = threadIdx.x >> 5;
    int lane = threadIdx.x & 31;
    int node = blockIdx.x * 8 + wid;
    bool valid = node < N_NODES;
    const uint2* H4 = (const uint2*)H;

    float4 acc = make_float4(0.f, 0.f, 0.f, 0.f);
    int g = -1;
    if (valid) {
        float aDn = aD[node];
        float den = __expf(leaky(aS[node] + aDn));   // self loop
        float2 slo, shi;
        bf16x4_unpack(H4[node * 32 + lane], slo, shi);
        acc = make_float4(slo.x * den, slo.y * den, shi.x * den, shi.y * den);

        int beg = off[node], end = off[node + 1];
        for (int i = beg; i < end; i += 4) {
            int4 s4 = *(const int4*)(srcs + i);
            float a0 = aS[s4.x];
            float a1 = aS[s4.y];
            float a2 = aS[s4.z];
            float a3 = aS[s4.w];
            uint2 h0 = H4[s4.x * 32 + lane];
            uint2 h1 = H4[s4.y * 32 + lane];
            uint2 h2 = H4[s4.z * 32 + lane];
            uint2 h3 = H4[s4.w * 32 + lane];
            float e0 = __expf(leaky(a0 + aDn));
            float e1 = __expf(leaky(a1 + aDn));
            float e2 = __expf(leaky(a2 + aDn));
            float e3 = __expf(leaky(a3 + aDn));
            den += (e0 + e1) + (e2 + e3);
            float2 lo, hi;
            bf16x4_unpack(h0, lo, hi);
            acc.x = fmaf(lo.x, e0, acc.x); acc.y = fmaf(lo.y, e0, acc.y);
            acc.z = fmaf(hi.x, e0, acc.z); acc.w = fmaf(hi.y, e0, acc.w);
            bf16x4_unpack(h1, lo, hi);
            acc.x = fmaf(lo.x, e1, acc.x); acc.y = fmaf(lo.y, e1, acc.y);
            acc.z = fmaf(hi.x, e1, acc.z); acc.w = fmaf(hi.y, e1, acc.w);
            bf16x4_unpack(h2, lo, hi);
            acc.x = fmaf(lo.x, e2, acc.x); acc.y = fmaf(lo.y, e2, acc.y);
            acc.z = fmaf(hi.x, e2, acc.z); acc.w = fmaf(hi.y, e2, acc.w);
            bf16x4_unpack(h3, lo, hi);
            acc.x = fmaf(lo.x, e3, acc.x); acc.y = fmaf(lo.y, e3, acc.y);
            acc.z = fmaf(hi.x, e3, acc.z); acc.w = fmaf(hi.y, e3, acc.w);
        }
        float inv = 1.f / den;
        acc.x *= inv; acc.y *= inv; acc.z *= inv; acc.w *= inv;
        g = batch[node];
    }
    if (lane == 0) sbatch[wid] = g;
    ((float4*)sacc[wid])[lane] = acc;
    __syncthreads();

    int g0 = sbatch[0];
    bool uniform = (g0 >= 0);
#pragma unroll
    for (int w = 1; w < 8; w++) uniform &= (sbatch[w] == g0);

    if (uniform) {
        if (threadIdx.x < DIM) {
            float v = 0.f;
#pragma unroll
            for (int w = 0; w < 8; w++) v += sacc[w][threadIdx.x];
            atomicAdd(&gsum[g0 * DIM + threadIdx.x], v);
        }
    } else if (valid) {
        float* dp = &gsum[g * DIM + lane * 4];
        atomicAdd(dp + 0, acc.x);
        atomicAdd(dp + 1, acc.y);
        atomicAdd(dp + 2, acc.z);
        atomicAdd(dp + 3, acc.w);
    }
}

// ---------------- classifier MLP ---------------------------------------------
__global__ void classifier(const float* __restrict__ gsum, const float* __restrict__ gcnt,
                           const float* __restrict__ b2,
                           const float* __restrict__ Wc1, const float* __restrict__ bc1,
                           const float* __restrict__ Wc2, const float* __restrict__ bc2,
                           float* __restrict__ out)
{
    __shared__ float emb[DIM];
    __shared__ float z[64];
    int g = blockIdx.x, t = threadIdx.x;
    float cnt = fmaxf(gcnt[g], 1.f);
    emb[t] = gsum[g * DIM + t] / cnt + b2[t];
    __syncthreads();
    if (t < 64) {
        float a = bc1[t];
#pragma unroll 8
        for (int k = 0; k < DIM; k++) a = fmaf(emb[k], Wc1[k * 64 + t], a);
        z[t] = a > 0.f ? a : expm1f(a);
    }
    __syncthreads();
    if (t < NCLASS) {
        float a = bc2[t];
#pragma unroll
        for (int k = 0; k < 64; k++) a = fmaf(z[k], Wc2[k * NCLASS + t], a);
        out[g * NCLASS + t] = a;
    }
}

// ---------------- launch ------------------------------------------------------
extern "C" void kernel_launch(void* const* d_in, const int* in_sizes, int n_in,
                              void* d_out, int out_size)
{
    const float* x        = (const float*)d_in[0];
    const int*   esrc     = (const int*)  d_in[1];
    const int*   edst     = (const int*)  d_in[2];
    const int*   batch    = (const int*)  d_in[3];
    const float* W1       = (const float*)d_in[4];
    const float* b1       = (const float*)d_in[5];
    const float* att_src1 = (const float*)d_in[6];
    const float* att_dst1 = (const float*)d_in[7];
    const float* W2       = (const float*)d_in[8];
    const float* b2       = (const float*)d_in[9];
    const float* att_src2 = (const float*)d_in[10];
    const float* att_dst2 = (const float*)d_in[11];
    const float* bn_g     = (const float*)d_in[12];
    const float* bn_b     = (const float*)d_in[13];
    const float* bn_m     = (const float*)d_in[14];
    const float* bn_v     = (const float*)d_in[15];
    const float* Wc1      = (const float*)d_in[16];
    const float* bc1      = (const float*)d_in[17];
    const float* Wc2      = (const float*)d_in[18];
    const float* bc2      = (const float*)d_in[19];
    float* out = (float*)d_out;

    __nv_bfloat16 *p_h;
    float *p_mid, *p_w1p, *p_w2p, *p_as, *p_ad, *p_gsum, *p_gcnt;
    int *p_deg, *p_off, *p_cur, *p_srcs;
    cudaGetSymbolAddress((void**)&p_h,    g_h);
    cudaGetSymbolAddress((void**)&p_mid,  g_mid);
    cudaGetSymbolAddress((void**)&p_w1p,  g_w1p);
    cudaGetSymbolAddress((void**)&p_w2p,  g_w2p);
    cudaGetSymbolAddress((void**)&p_as,   g_asrc);
    cudaGetSymbolAddress((void**)&p_ad,   g_adst);
    cudaGetSymbolAddress((void**)&p_deg,  g_deg);
    cudaGetSymbolAddress((void**)&p_off,  g_off);
    cudaGetSymbolAddress((void**)&p_cur,  g_cur);
    cudaGetSymbolAddress((void**)&p_srcs, g_srcs);
    cudaGetSymbolAddress((void**)&p_gsum, g_gsum);
    cudaGetSymbolAddress((void**)&p_gcnt, g_gcnt);

    static cudaStream_t s2 = 0;
    static cudaEvent_t evFork = 0, evJoin = 0;
    const int XSMEM = 128 * 132 * (int)sizeof(float);
    if (s2 == 0) {
        cudaStreamCreateWithFlags(&s2, cudaStreamNonBlocking);
        cudaEventCreateWithFlags(&evFork, cudaEventDisableTiming);
        cudaEventCreateWithFlags(&evJoin, cudaEventDisableTiming);
        cudaFuncSetAttribute(gemm_mma_kernel,
                             cudaFuncAttributeMaxDynamicSharedMemorySize, XSMEM);
    }

    const int TB = 256;
    int gemm_blocks = (N_NODES + 127) / 128;
    int agg_blocks  = (N_NODES + 7) / 8;

    // fork: fused CSR build runs concurrently with pack_w + gemm1
    cudaEventRecord(evFork, 0);
    cudaStreamWaitEvent(s2, evFork, 0);

    build_csr<<<NB_CSR, TB, 0, s2>>>(esrc, edst, batch, p_deg, p_off, p_cur,  // 0
                                     p_srcs, p_gsum, p_gcnt);
    cudaEventRecord(evJoin, s2);

    pack_w_tf32<<<(16 * 8 * 32 + TB - 1) / TB, TB>>>(W1, W2, p_w1p, p_w2p);   // 1
    gemm_mma_kernel<<<gemm_blocks, TB, XSMEM>>>(x, p_w1p, att_src1, att_dst1, // 2
                                                p_h, p_as, p_ad, HEADS);
    cudaStreamWaitEvent(0, evJoin, 0);

    agg_layer1<<<agg_blocks, TB>>>(p_srcs, p_off, p_as, p_ad, p_h,            // 3 <- profiled
                                   b1, bn_g, bn_b, bn_m, bn_v, p_mid);
    gemm_mma_kernel<<<gemm_blocks, TB, XSMEM>>>(p_mid, p_w2p, att_src2,       // 4
                                                att_dst2, p_h, p_as, p_ad, 1);
    agg_layer2<<<agg_blocks, TB>>>(p_srcs, p_off, p_as, p_ad, p_h, batch, p_gsum); // 5
    classifier<<<GRAPHS, DIM>>>(p_gsum, p_gcnt, b2, Wc1, bc1, Wc2, bc2, out);      // 6
}

// round 12
// speedup vs baseline: 3.6706x; 1.0382x over previous
#include <cuda_runtime.h>
#include <cuda_bf16.h>
#include <math.h>

#define N_NODES 50000
#define N_EDGES 800000
#define DIM     128
#define HEADS   8
#define GRAPHS  64
#define NCLASS  10
#define SLOPE   0.2f
#define BN_EPS  1e-5f
#define NB_CSR  132
#define MAX_PADDED (N_EDGES + 4 * N_NODES)

// ---------------- scratch (device globals) ----------------------------------
__device__ __nv_bfloat16 g_h[(N_NODES + 1) * DIM];  // +1: sentinel row (zero-init)
__device__ float g_mid[N_NODES * DIM];
__device__ float g_w1p[DIM * DIM];
__device__ float g_w2p[DIM * DIM];
__device__ float g_asrc[(N_NODES + 1) * HEADS];     // +1: sentinel scores
__device__ float g_adst[N_NODES * HEADS];
__device__ int   g_deg[N_NODES];
__device__ int   g_off[N_NODES + 1];
__device__ int   g_cur[N_NODES];
__device__ int   g_srcs[MAX_PADDED];                // stores src*16 (uint4 H index)
__device__ int   g_sentq[4];                        // sentinel quad {N_NODES*16 x4}
__device__ float g_gsum[GRAPHS * DIM];
__device__ float g_gcnt[GRAPHS];
__device__ int   g_barcnt = 0;
__device__ int   g_bargen = 0;
__device__ int   g_bsum[NB_CSR];

__device__ __forceinline__ float leaky(float x) { return fmaxf(x, SLOPE * x); }

__device__ __forceinline__ void bf16x8_unpack(uint4 v, float2& f0, float2& f1,
                                              float2& f2, float2& f3)
{
    f0 = __bfloat1622float2(*(const __nv_bfloat162*)&v.x);
    f1 = __bfloat1622float2(*(const __nv_bfloat162*)&v.y);
    f2 = __bfloat1622float2(*(const __nv_bfloat162*)&v.z);
    f3 = __bfloat1622float2(*(const __nv_bfloat162*)&v.w);
}

__device__ __forceinline__ unsigned int f2tf32(float f)
{
    unsigned int u;
    asm("cvt.rna.tf32.f32 %0, %1;" : "=r"(u) : "f"(f));
    return u;
}

// sense-reversing grid barrier (all NB_CSR blocks resident)
__device__ __forceinline__ void grid_barrier()
{
    __syncthreads();
    if (threadIdx.x == 0) {
        __threadfence();
        int gen = ((volatile int*)&g_bargen)[0];
        if (atomicAdd(&g_barcnt, 1) == (int)gridDim.x - 1) {
            g_barcnt = 0;
            __threadfence();
            atomicAdd(&g_bargen, 1);
        } else {
            while (((volatile int*)&g_bargen)[0] == gen) { }
        }
        __threadfence();
    }
    __syncthreads();
}

// ---------------- fused CSR build (padded to 4, src*16) + pool counts --------
__global__ void __launch_bounds__(256) build_csr(
        const int* __restrict__ esrc, const int* __restrict__ edst,
        const int* __restrict__ batch,
        int* __restrict__ deg, int* __restrict__ off, int* __restrict__ cur,
        int* __restrict__ srcs, float* __restrict__ gsum, float* __restrict__ gcnt)
{
    __shared__ int sm[256];
    __shared__ int bh[GRAPHS];
    int t   = threadIdx.x;
    int gid = blockIdx.x * 256 + t;
    const int stride = NB_CSR * 256;

    for (int i = gid; i < N_NODES; i += stride) deg[i] = 0;
    for (int i = gid; i < GRAPHS * DIM; i += stride) gsum[i] = 0.f;
    if (gid < GRAPHS) gcnt[gid] = 0.f;
    if (gid < 4) g_sentq[gid] = N_NODES * 16;
    if (t < GRAPHS) bh[t] = 0;
    grid_barrier();                                    // B1

    for (int e = gid; e < N_EDGES; e += stride) atomicAdd(&deg[edst[e]], 1);
    for (int i = gid; i < N_NODES; i += stride) atomicAdd(&bh[batch[i]], 1);
    __syncthreads();
    if (t < GRAPHS && bh[t] > 0) atomicAdd(&gcnt[t], (float)bh[t]);
    grid_barrier();                                    // B2

    int i0 = gid * 2, i1 = gid * 2 + 1;
    int d0 = (i0 < N_NODES) ? deg[i0] : 0;
    int d1 = (i1 < N_NODES) ? deg[i1] : 0;
    int p0 = (d0 + 3) & ~3;
    int p1 = (d1 + 3) & ~3;
    int msum = p0 + p1;
    sm[t] = msum;
    __syncthreads();
    for (int d = 1; d < 256; d <<= 1) {
        int u = (t >= d) ? sm[t - d] : 0;
        __syncthreads();
        sm[t] += u;
        __syncthreads();
    }
    if (t == 255) g_bsum[blockIdx.x] = sm[255];
    int texcl = sm[t] - msum;
    grid_barrier();                                    // B3
    if (blockIdx.x == 0 && t == 0) {
        int run = 0;
        for (int i = 0; i < NB_CSR; i++) { int v = g_bsum[i]; g_bsum[i] = run; run += v; }
        off[N_NODES] = run;
    }
    grid_barrier();                                    // B4
    int base = g_bsum[blockIdx.x] + texcl;
    if (i0 < N_NODES) { off[i0] = base;      cur[i0] = base; }
    if (i1 < N_NODES) { off[i1] = base + p0; cur[i1] = base + p0; }
    grid_barrier();                                    // B5

    for (int e = gid; e < N_EDGES; e += stride) {
        int pos = atomicAdd(&cur[edst[e]], 1);
        srcs[pos] = esrc[e] * 16;                     // pre-scaled uint4 index
    }
    for (int i = gid; i < N_NODES; i += stride) {
        int st = off[i] + deg[i], en = off[i + 1];
        for (int j = st; j < en; j++) srcs[j] = N_NODES * 16;
    }
}

// ---------------- W pack: tf32 + mma-fragment-major ---------------------------
__global__ void pack_w_tf32(const float* __restrict__ W1, const float* __restrict__ W2,
                            float* __restrict__ P1, float* __restrict__ P2)
{
    int i = blockIdx.x * blockDim.x + threadIdx.x;
    if (i >= 16 * 8 * 32) return;
    int lane = i & 31;
    int p    = (i >> 5) & 7;
    int ks   = i >> 8;
    int kc = lane & 3, nc = lane >> 2;
    int r0 = ks * 8 + kc, r1 = r0 + 4;
    int c0 = (2 * p) * 8 + nc, c1 = (2 * p + 1) * 8 + nc;
    float4 v1, v2;
    v1.x = __uint_as_float(f2tf32(W1[r0 * DIM + c0]));
    v1.y = __uint_as_float(f2tf32(W1[r1 * DIM + c0]));
    v1.z = __uint_as_float(f2tf32(W1[r0 * DIM + c1]));
    v1.w = __uint_as_float(f2tf32(W1[r1 * DIM + c1]));
    v2.x = __uint_as_float(f2tf32(W2[r0 * DIM + c0]));
    v2.y = __uint_as_float(f2tf32(W2[r1 * DIM + c0]));
    v2.z = __uint_as_float(f2tf32(W2[r0 * DIM + c1]));
    v2.w = __uint_as_float(f2tf32(W2[r1 * DIM + c1]));
    ((float4*)P1)[i] = v1;
    ((float4*)P2)[i] = v2;
}

// ---------------- tensor-core GEMM (h = X @ W, tf32 mma) ---------------------
__global__ void __launch_bounds__(256, 2) gemm_mma_kernel(
        const float* __restrict__ X,
        const float* __restrict__ Wpack,
        const float* __restrict__ attS,
        const float* __restrict__ attD,
        __nv_bfloat16* __restrict__ Hout,
        float* __restrict__ aS,
        float* __restrict__ aD,
        int heads)
{
    extern __shared__ float xsm[];            // 128 * 132 floats
    __shared__ float sS[DIM], sD[DIM];
    int tid  = threadIdx.x;
    int lane = tid & 31;
    int w    = tid >> 5;
    if (tid < DIM) { sS[tid] = attS[tid]; sD[tid] = attD[tid]; }

    // sentinel scores: padding edges contribute exp(-1e4) = 0
    if (blockIdx.x == 0 && tid < heads) aS[N_NODES * heads + tid] = -1e4f;

    int row0 = blockIdx.x * 128;
    const float4* X4 = (const float4*)X;
#pragma unroll
    for (int j = 0; j < 16; j++) {
        int idx = tid + j * 256;
        int r = idx >> 5, c = idx & 31;
        float4 v = (row0 + r < N_NODES) ? X4[(row0 + r) * 32 + c]
                                        : make_float4(0.f, 0.f, 0.f, 0.f);
        *(float4*)&xsm[r * 132 + c * 4] = v;
    }
    __syncthreads();

    int m0w = w * 16;
    if (row0 + m0w >= N_NODES) return;

    int kc = lane & 3;
    int nc = lane >> 2;
    const float* x1 = xsm + (m0w + nc) * 132;
    const float* x2 = x1 + 8 * 132;

    float acc[16][4];
#pragma unroll
    for (int nt = 0; nt < 16; nt++) {
        acc[nt][0] = 0.f; acc[nt][1] = 0.f; acc[nt][2] = 0.f; acc[nt][3] = 0.f;
    }

    const float4* Wp4 = (const float4*)Wpack;
#pragma unroll
    for (int ks = 0; ks < 16; ks++) {
        int k0 = ks * 8;
        unsigned int a0 = f2tf32(x1[k0 + kc]);
        unsigned int a1 = f2tf32(x2[k0 + kc]);
        unsigned int a2 = f2tf32(x1[k0 + kc + 4]);
        unsigned int a3 = f2tf32(x2[k0 + kc + 4]);
#pragma unroll
        for (int p = 0; p < 8; p++) {
            float4 bb = Wp4[(ks * 8 + p) * 32 + lane];
            asm("mma.sync.aligned.m16n8k8.row.col.f32.tf32.tf32.f32 "
                "{%0,%1,%2,%3}, {%4,%5,%6,%7}, {%8,%9}, {%0,%1,%2,%3};"
                : "+f"(acc[2*p][0]), "+f"(acc[2*p][1]), "+f"(acc[2*p][2]), "+f"(acc[2*p][3])
                : "r"(a0), "r"(a1), "r"(a2), "r"(a3),
                  "r"(__float_as_uint(bb.x)), "r"(__float_as_uint(bb.y)));
            asm("mma.sync.aligned.m16n8k8.row.col.f32.tf32.tf32.f32 "
                "{%0,%1,%2,%3}, {%4,%5,%6,%7}, {%8,%9}, {%0,%1,%2,%3};"
                : "+f"(acc[2*p+1][0]), "+f"(acc[2*p+1][1]), "+f"(acc[2*p+1][2]), "+f"(acc[2*p+1][3])
                : "r"(a0), "r"(a1), "r"(a2), "r"(a3),
                  "r"(__float_as_uint(bb.z)), "r"(__float_as_uint(bb.w)));
        }
    }

    int cb2 = (lane & 3) * 2;
    int r1 = row0 + m0w + nc;
    int r2 = r1 + 8;

#pragma unroll
    for (int rr = 0; rr < 2; rr++) {
        int row = (rr == 0) ? r1 : r2;
#pragma unroll
        for (int nt = 0; nt < 16; nt++) {
            __nv_bfloat162 pr = __floats2bfloat162_rn(acc[nt][rr * 2], acc[nt][rr * 2 + 1]);
            *(__nv_bfloat162*)(Hout + row * DIM + nt * 8 + cb2) = pr;
        }
        float tps = 0.f, tpd = 0.f;
#pragma unroll
        for (int h = 0; h < 8; h++) {
            int c0 = h * 16 + cb2;
            float v0 = acc[2 * h][rr * 2],     v1 = acc[2 * h][rr * 2 + 1];
            float v2 = acc[2 * h + 1][rr * 2], v3 = acc[2 * h + 1][rr * 2 + 1];
            float ps = v0 * sS[c0] + v1 * sS[c0 + 1] + v2 * sS[c0 + 8] + v3 * sS[c0 + 9];
            float pd = v0 * sD[c0] + v1 * sD[c0 + 1] + v2 * sD[c0 + 8] + v3 * sD[c0 + 9];
            ps += __shfl_xor_sync(0xffffffff, ps, 1);
            ps += __shfl_xor_sync(0xffffffff, ps, 2);
            pd += __shfl_xor_sync(0xffffffff, pd, 1);
            pd += __shfl_xor_sync(0xffffffff, pd, 2);
            if (heads == HEADS) {
                if ((lane & 3) == 0) {
                    aS[row * HEADS + h] = ps;
                    aD[row * HEADS + h] = pd;
                }
            } else { tps += ps; tpd += pd; }
        }
        if (heads == 1 && (lane & 3) == 0) { aS[row] = tps; aD[row] = tpd; }
    }
}

// ---------------- layer 1 fused aggregation (+bias+BN+ELU) ------------------
// TWO nodes per warp (16 lanes each, 8 channels/lane via uint4=8 bf16).
// padded CSR with pre-scaled src*16; out-of-range halves read sentinel quad.
__global__ void __launch_bounds__(256) agg_layer1(
        const int* __restrict__ srcs, const int* __restrict__ off,
        const float* __restrict__ aS, const float* __restrict__ aD,
        const __nv_bfloat16* __restrict__ H,
        const float* __restrict__ b1,
        const float* __restrict__ bn_g, const float* __restrict__ bn_b,
        const float* __restrict__ bn_m, const float* __restrict__ bn_v,
        float* __restrict__ out)
{
    int wid  = threadIdx.x >> 5;
    int lane = threadIdx.x & 31;
    int q    = lane & 15;                 // channel partition within node
    int half = lane >> 4;
    int node = blockIdx.x * 16 + wid * 2 + half;   // 50000 = 3125 * 16, always valid
    int h    = q >> 1;                    // head (16 ch per head = 2 lanes)
    const uint4* H4 = (const uint4*)H;

    float aD_h = aD[node * HEADS + h];
    float den  = __expf(leaky(aS[node * HEADS + h] + aD_h));   // self loop
    float2 u0, u1, u2, u3;
    bf16x8_unpack(H4[node * 16 + q], u0, u1, u2, u3);
    float a0 = u0.x * den, a1 = u0.y * den, a2 = u1.x * den, a3 = u1.y * den;
    float a4 = u2.x * den, a5 = u2.y * den, a6 = u3.x * den, a7 = u3.y * den;

    int beg = off[node];
    int n   = off[node + 1] - beg;        // multiple of 4
    int noth = __shfl_xor_sync(0xffffffff, n, 16);
    int nmax = max(n, noth);

    for (int i = 0; i < nmax; i += 4) {
        const int4* sp = (i < n) ? (const int4*)(srcs + beg + i)
                                 : (const int4*)g_sentq;
        int4 s4 = *sp;                    // values are src*16
        float s0 = aS[(s4.x >> 1) + h];
        float s1 = aS[(s4.y >> 1) + h];
        float s2 = aS[(s4.z >> 1) + h];
        float s3 = aS[(s4.w >> 1) + h];
        uint4 h0 = H4[s4.x + q];
        uint4 h1 = H4[s4.y + q];
        uint4 h2 = H4[s4.z + q];
        uint4 h3 = H4[s4.w + q];
        float e0 = __expf(leaky(s0 + aD_h));
        float e1 = __expf(leaky(s1 + aD_h));
        float e2 = __expf(leaky(s2 + aD_h));
        float e3 = __expf(leaky(s3 + aD_h));
        den += (e0 + e1) + (e2 + e3);
        float2 f0, f1, f2, f3;
        bf16x8_unpack(h0, f0, f1, f2, f3);
        a0 = fmaf(f0.x, e0, a0); a1 = fmaf(f0.y, e0, a1);
        a2 = fmaf(f1.x, e0, a2); a3 = fmaf(f1.y, e0, a3);
        a4 = fmaf(f2.x, e0, a4); a5 = fmaf(f2.y, e0, a5);
        a6 = fmaf(f3.x, e0, a6); a7 = fmaf(f3.y, e0, a7);
        bf16x8_unpack(h1, f0, f1, f2, f3);
        a0 = fmaf(f0.x, e1, a0); a1 = fmaf(f0.y, e1, a1);
        a2 = fmaf(f1.x, e1, a2); a3 = fmaf(f1.y, e1, a3);
        a4 = fmaf(f2.x, e1, a4); a5 = fmaf(f2.y, e1, a5);
        a6 = fmaf(f3.x, e1, a6); a7 = fmaf(f3.y, e1, a7);
        bf16x8_unpack(h2, f0, f1, f2, f3);
        a0 = fmaf(f0.x, e2, a0); a1 = fmaf(f0.y, e2, a1);
        a2 = fmaf(f1.x, e2, a2); a3 = fmaf(f1.y, e2, a3);
        a4 = fmaf(f2.x, e2, a4); a5 = fmaf(f2.y, e2, a5);
        a6 = fmaf(f3.x, e2, a6); a7 = fmaf(f3.y, e2, a7);
        bf16x8_unpack(h3, f0, f1, f2, f3);
        a0 = fmaf(f0.x, e3, a0); a1 = fmaf(f0.y, e3, a1);
        a2 = fmaf(f1.x, e3, a2); a3 = fmaf(f1.y, e3, a3);
        a4 = fmaf(f2.x, e3, a4); a5 = fmaf(f2.y, e3, a5);
        a6 = fmaf(f3.x, e3, a6); a7 = fmaf(f3.y, e3, a7);
    }
    float inv = 1.f / den;

    // epilogue over this lane's 8 channels (cols q*8 .. q*8+7)
    const float4* B1 = (const float4*)b1;
    const float4* GG = (const float4*)bn_g;
    const float4* BE = (const float4*)bn_b;
    const float4* MU = (const float4*)bn_m;
    const float4* VA = (const float4*)bn_v;
    float4* O = (float4*)out;
    float r[8] = {a0, a1, a2, a3, a4, a5, a6, a7};
#pragma unroll
    for (int p = 0; p < 2; p++) {
        float4 bb = B1[q * 2 + p];
        float4 gg = GG[q * 2 + p];
        float4 be = BE[q * 2 + p];
        float4 mu = MU[q * 2 + p];
        float4 va = VA[q * 2 + p];
        float4 o;
        o.x = (r[p*4+0] * inv + bb.x - mu.x) * gg.x * rsqrtf(va.x + BN_EPS) + be.x;
        o.y = (r[p*4+1] * inv + bb.y - mu.y) * gg.y * rsqrtf(va.y + BN_EPS) + be.y;
        o.z = (r[p*4+2] * inv + bb.z - mu.z) * gg.z * rsqrtf(va.z + BN_EPS) + be.z;
        o.w = (r[p*4+3] * inv + bb.w - mu.w) * gg.w * rsqrtf(va.w + BN_EPS) + be.w;
        o.x = o.x > 0.f ? o.x : expm1f(o.x);
        o.y = o.y > 0.f ? o.y : expm1f(o.y);
        o.z = o.z > 0.f ? o.z : expm1f(o.z);
        o.w = o.w > 0.f ? o.w : expm1f(o.w);
        O[node * 32 + q * 2 + p] = o;
    }
}

// ---------------- layer 2 fused aggregation (+pool) -------------------------
__global__ void __launch_bounds__(256) agg_layer2(
        const int* __restrict__ srcs, const int* __restrict__ off,
        const float* __restrict__ aS, const float* __restrict__ aD,
        const __nv_bfloat16* __restrict__ H,
        const int* __restrict__ batch,
        float* __restrict__ gsum)
{
    __shared__ float sacc[16][DIM];
    __shared__ int   sbatch[16];
    int wid  = threadIdx.x >> 5;
    int lane = threadIdx.x & 31;
    int q    = lane & 15;
    int half = lane >> 4;
    int node = blockIdx.x * 16 + wid * 2 + half;   // always valid
    int nl   = wid * 2 + half;                     // node slot in block
    const uint4* H4 = (const uint4*)H;

    float aDn = aD[node];
    float den = __expf(leaky(aS[node] + aDn));     // self loop
    float2 u0, u1, u2, u3;
    bf16x8_unpack(H4[node * 16 + q], u0, u1, u2, u3);
    float a0 = u0.x * den, a1 = u0.y * den, a2 = u1.x * den, a3 = u1.y * den;
    float a4 = u2.x * den, a5 = u2.y * den, a6 = u3.x * den, a7 = u3.y * den;

    int beg = off[node];
    int n   = off[node + 1] - beg;
    int noth = __shfl_xor_sync(0xffffffff, n, 16);
    int nmax = max(n, noth);

    for (int i = 0; i < nmax; i += 4) {
        const int4* sp = (i < n) ? (const int4*)(srcs + beg + i)
                                 : (const int4*)g_sentq;
        int4 s4 = *sp;
        float s0 = aS[s4.x >> 4];
        float s1 = aS[s4.y >> 4];
        float s2 = aS[s4.z >> 4];
        float s3 = aS[s4.w >> 4];
        uint4 h0 = H4[s4.x + q];
        uint4 h1 = H4[s4.y + q];
        uint4 h2 = H4[s4.z + q];
        uint4 h3 = H4[s4.w + q];
        float e0 = __expf(leaky(s0 + aDn));
        float e1 = __expf(leaky(s1 + aDn));
        float e2 = __expf(leaky(s2 + aDn));
        float e3 = __expf(leaky(s3 + aDn));
        den += (e0 + e1) + (e2 + e3);
        float2 f0, f1, f2, f3;
        bf16x8_unpack(h0, f0, f1, f2, f3);
        a0 = fmaf(f0.x, e0, a0); a1 = fmaf(f0.y, e0, a1);
        a2 = fmaf(f1.x, e0, a2); a3 = fmaf(f1.y, e0, a3);
        a4 = fmaf(f2.x, e0, a4); a5 = fmaf(f2.y, e0, a5);
        a6 = fmaf(f3.x, e0, a6); a7 = fmaf(f3.y, e0, a7);
        bf16x8_unpack(h1, f0, f1, f2, f3);
        a0 = fmaf(f0.x, e1, a0); a1 = fmaf(f0.y, e1, a1);
        a2 = fmaf(f1.x, e1, a2); a3 = fmaf(f1.y, e1, a3);
        a4 = fmaf(f2.x, e1, a4); a5 = fmaf(f2.y, e1, a5);
        a6 = fmaf(f3.x, e1, a6); a7 = fmaf(f3.y, e1, a7);
        bf16x8_unpack(h2, f0, f1, f2, f3);
        a0 = fmaf(f0.x, e2, a0); a1 = fmaf(f0.y, e2, a1);
        a2 = fmaf(f1.x, e2, a2); a3 = fmaf(f1.y, e2, a3);
        a4 = fmaf(f2.x, e2, a4); a5 = fmaf(f2.y, e2, a5);
        a6 = fmaf(f3.x, e2, a6); a7 = fmaf(f3.y, e2, a7);
        bf16x8_unpack(h3, f0, f1, f2, f3);
        a0 = fmaf(f0.x, e3, a0); a1 = fmaf(f0.y, e3, a1);
        a2 = fmaf(f1.x, e3, a2); a3 = fmaf(f1.y, e3, a3);
        a4 = fmaf(f2.x, e3, a4); a5 = fmaf(f2.y, e3, a5);
        a6 = fmaf(f3.x, e3, a6); a7 = fmaf(f3.y, e3, a7);
    }
    float inv = 1.f / den;
    a0 *= inv; a1 *= inv; a2 *= inv; a3 *= inv;
    a4 *= inv; a5 *= inv; a6 *= inv; a7 *= inv;
    int g = batch[node];

    if (q == 0) sbatch[nl] = g;
    float* sr = &sacc[nl][q * 8];
    sr[0] = a0; sr[1] = a1; sr[2] = a2; sr[3] = a3;
    sr[4] = a4; sr[5] = a5; sr[6] = a6; sr[7] = a7;
    __syncthreads();

    int g0 = sbatch[0];
    bool uniform = true;
#pragma unroll
    for (int w = 1; w < 16; w++) uniform &= (sbatch[w] == g0);

    if (uniform) {
        if (threadIdx.x < DIM) {
            float v = 0.f;
#pragma unroll
            for (int w = 0; w < 16; w++) v += sacc[w][threadIdx.x];
            atomicAdd(&gsum[g0 * DIM + threadIdx.x], v);
        }
    } else {
        float* dp = &gsum[g * DIM + q * 8];
        atomicAdd(dp + 0, a0); atomicAdd(dp + 1, a1);
        atomicAdd(dp + 2, a2); atomicAdd(dp + 3, a3);
        atomicAdd(dp + 4, a4); atomicAdd(dp + 5, a5);
        atomicAdd(dp + 6, a6); atomicAdd(dp + 7, a7);
    }
}

// ---------------- classifier MLP ---------------------------------------------
__global__ void classifier(const float* __restrict__ gsum, const float* __restrict__ gcnt,
                           const float* __restrict__ b2,
                           const float* __restrict__ Wc1, const float* __restrict__ bc1,
                           const float* __restrict__ Wc2, const float* __restrict__ bc2,
                           float* __restrict__ out)
{
    __shared__ float emb[DIM];
    __shared__ float z[64];
    int g = blockIdx.x, t = threadIdx.x;
    float cnt = fmaxf(gcnt[g], 1.f);
    emb[t] = gsum[g * DIM + t] / cnt + b2[t];
    __syncthreads();
    if (t < 64) {
        float a = bc1[t];
#pragma unroll 8
        for (int k = 0; k < DIM; k++) a = fmaf(emb[k], Wc1[k * 64 + t], a);
        z[t] = a > 0.f ? a : expm1f(a);
    }
    __syncthreads();
    if (t < NCLASS) {
        float a = bc2[t];
#pragma unroll
        for (int k = 0; k < 64; k++) a = fmaf(z[k], Wc2[k * NCLASS + t], a);
        out[g * NCLASS + t] = a;
    }
}

// ---------------- launch ------------------------------------------------------
extern "C" void kernel_launch(void* const* d_in, const int* in_sizes, int n_in,
                              void* d_out, int out_size)
{
    const float* x        = (const float*)d_in[0];
    const int*   esrc     = (const int*)  d_in[1];
    const int*   edst     = (const int*)  d_in[2];
    const int*   batch    = (const int*)  d_in[3];
    const float* W1       = (const float*)d_in[4];
    const float* b1       = (const float*)d_in[5];
    const float* att_src1 = (const float*)d_in[6];
    const float* att_dst1 = (const float*)d_in[7];
    const float* W2       = (const float*)d_in[8];
    const float* b2       = (const float*)d_in[9];
    const float* att_src2 = (const float*)d_in[10];
    const float* att_dst2 = (const float*)d_in[11];
    const float* bn_g     = (const float*)d_in[12];
    const float* bn_b     = (const float*)d_in[13];
    const float* bn_m     = (const float*)d_in[14];
    const float* bn_v     = (const float*)d_in[15];
    const float* Wc1      = (const float*)d_in[16];
    const float* bc1      = (const float*)d_in[17];
    const float* Wc2      = (const float*)d_in[18];
    const float* bc2      = (const float*)d_in[19];
    float* out = (float*)d_out;

    __nv_bfloat16 *p_h;
    float *p_mid, *p_w1p, *p_w2p, *p_as, *p_ad, *p_gsum, *p_gcnt;
    int *p_deg, *p_off, *p_cur, *p_srcs;
    cudaGetSymbolAddress((void**)&p_h,    g_h);
    cudaGetSymbolAddress((void**)&p_mid,  g_mid);
    cudaGetSymbolAddress((void**)&p_w1p,  g_w1p);
    cudaGetSymbolAddress((void**)&p_w2p,  g_w2p);
    cudaGetSymbolAddress((void**)&p_as,   g_asrc);
    cudaGetSymbolAddress((void**)&p_ad,   g_adst);
    cudaGetSymbolAddress((void**)&p_deg,  g_deg);
    cudaGetSymbolAddress((void**)&p_off,  g_off);
    cudaGetSymbolAddress((void**)&p_cur,  g_cur);
    cudaGetSymbolAddress((void**)&p_srcs, g_srcs);
    cudaGetSymbolAddress((void**)&p_gsum, g_gsum);
    cudaGetSymbolAddress((void**)&p_gcnt, g_gcnt);

    static cudaStream_t s2 = 0;
    static cudaEvent_t evFork = 0, evJoin = 0;
    const int XSMEM = 128 * 132 * (int)sizeof(float);
    if (s2 == 0) {
        cudaStreamCreateWithFlags(&s2, cudaStreamNonBlocking);
        cudaEventCreateWithFlags(&evFork, cudaEventDisableTiming);
        cudaEventCreateWithFlags(&evJoin, cudaEventDisableTiming);
        cudaFuncSetAttribute(gemm_mma_kernel,
                             cudaFuncAttributeMaxDynamicSharedMemorySize, XSMEM);
    }

    const int TB = 256;
    int gemm_blocks = (N_NODES + 127) / 128;
    int agg_blocks  = N_NODES / 16;           // 3125 (50000 % 16 == 0)

    cudaEventRecord(evFork, 0);
    cudaStreamWaitEvent(s2, evFork, 0);

    build_csr<<<NB_CSR, TB, 0, s2>>>(esrc, edst, batch, p_deg, p_off, p_cur,  // 0
                                     p_srcs, p_gsum, p_gcnt);
    cudaEventRecord(evJoin, s2);

    pack_w_tf32<<<(16 * 8 * 32 + TB - 1) / TB, TB>>>(W1, W2, p_w1p, p_w2p);   // 1
    gemm_mma_kernel<<<gemm_blocks, TB, XSMEM>>>(x, p_w1p, att_src1, att_dst1, // 2
                                                p_h, p_as, p_ad, HEADS);
    cudaStreamWaitEvent(0, evJoin, 0);

    agg_layer1<<<agg_blocks, TB>>>(p_srcs, p_off, p_as, p_ad, p_h,            // 3 <- profiled
                                   b1, bn_g, bn_b, bn_m, bn_v, p_mid);
    gemm_mma_kernel<<<gemm_blocks, TB, XSMEM>>>(p_mid, p_w2p, att_src2,       // 4
                                                att_dst2, p_h, p_as, p_ad, 1);
    agg_layer2<<<agg_blocks, TB>>>(p_srcs, p_off, p_as, p_ad, p_h, batch, p_gsum); // 5
    classifier<<<GRAPHS, DIM>>>(p_gsum, p_gcnt, b2, Wc1, bc1, Wc2, bc2, out);      // 6
}

// round 13
// speedup vs baseline: 3.7555x; 1.0231x over previous
#include <cuda_runtime.h>
#include <cuda_bf16.h>
#include <math.h>

#define N_NODES 50000
#define N_EDGES 800000
#define DIM     128
#define HEADS   8
#define GRAPHS  64
#define NCLASS  10
#define SLOPE   0.2f
#define BN_EPS  1e-5f
#define NB_CSR  132
#define MAX_PADDED (N_EDGES + 4 * N_NODES)

// ---------------- scratch (device globals) ----------------------------------
__device__ __nv_bfloat16 g_h[(N_NODES + 1) * DIM];  // +1: sentinel row (zero-init)
__device__ float g_mid[N_NODES * DIM];
__device__ float g_w1p[DIM * DIM];
__device__ float g_w2p[DIM * DIM];
__device__ float g_asrc[(N_NODES + 1) * HEADS];     // +1: sentinel scores
__device__ float g_adst[N_NODES * HEADS];
__device__ int   g_deg[N_NODES];
__device__ int   g_off[N_NODES + 1];
__device__ int   g_cur[N_NODES];
__device__ int   g_srcs[MAX_PADDED];                // stores src*16 (uint4 H index)
__device__ int   g_sentq[4];                        // sentinel quad {N_NODES*16 x4}
__device__ float g_gsum[GRAPHS * DIM];
__device__ float g_gcnt[GRAPHS];
__device__ int   g_barcnt = 0;
__device__ int   g_bargen = 0;
__device__ int   g_bsum[NB_CSR];

__device__ __forceinline__ float leaky(float x) { return fmaxf(x, SLOPE * x); }

__device__ __forceinline__ void bf16x8_unpack(uint4 v, float2& f0, float2& f1,
                                              float2& f2, float2& f3)
{
    f0 = __bfloat1622float2(*(const __nv_bfloat162*)&v.x);
    f1 = __bfloat1622float2(*(const __nv_bfloat162*)&v.y);
    f2 = __bfloat1622float2(*(const __nv_bfloat162*)&v.z);
    f3 = __bfloat1622float2(*(const __nv_bfloat162*)&v.w);
}

__device__ __forceinline__ unsigned int f2tf32(float f)
{
    unsigned int u;
    asm("cvt.rna.tf32.f32 %0, %1;" : "=r"(u) : "f"(f));
    return u;
}

// sense-reversing grid barrier (all NB_CSR blocks resident)
__device__ __forceinline__ void grid_barrier()
{
    __syncthreads();
    if (threadIdx.x == 0) {
        __threadfence();
        int gen = ((volatile int*)&g_bargen)[0];
        if (atomicAdd(&g_barcnt, 1) == (int)gridDim.x - 1) {
            g_barcnt = 0;
            __threadfence();
            atomicAdd(&g_bargen, 1);
        } else {
            while (((volatile int*)&g_bargen)[0] == gen) { }
        }
        __threadfence();
    }
    __syncthreads();
}

// ---------------- fused CSR build (padded to 4, src*16) + pool counts --------
__global__ void __launch_bounds__(256) build_csr(
        const int* __restrict__ esrc, const int* __restrict__ edst,
        const int* __restrict__ batch,
        int* __restrict__ deg, int* __restrict__ off, int* __restrict__ cur,
        int* __restrict__ srcs, float* __restrict__ gsum, float* __restrict__ gcnt)
{
    __shared__ int sm[256];
    __shared__ int bh[GRAPHS];
    int t   = threadIdx.x;
    int gid = blockIdx.x * 256 + t;
    const int stride = NB_CSR * 256;

    for (int i = gid; i < N_NODES; i += stride) deg[i] = 0;
    for (int i = gid; i < GRAPHS * DIM; i += stride) gsum[i] = 0.f;
    if (gid < GRAPHS) gcnt[gid] = 0.f;
    if (gid < 4) g_sentq[gid] = N_NODES * 16;
    if (t < GRAPHS) bh[t] = 0;
    grid_barrier();                                    // B1

    for (int e = gid; e < N_EDGES; e += stride) atomicAdd(&deg[edst[e]], 1);
    for (int i = gid; i < N_NODES; i += stride) atomicAdd(&bh[batch[i]], 1);
    __syncthreads();
    if (t < GRAPHS && bh[t] > 0) atomicAdd(&gcnt[t], (float)bh[t]);
    grid_barrier();                                    // B2

    int i0 = gid * 2, i1 = gid * 2 + 1;
    int d0 = (i0 < N_NODES) ? deg[i0] : 0;
    int d1 = (i1 < N_NODES) ? deg[i1] : 0;
    int p0 = (d0 + 3) & ~3;
    int p1 = (d1 + 3) & ~3;
    int msum = p0 + p1;
    sm[t] = msum;
    __syncthreads();
    for (int d = 1; d < 256; d <<= 1) {
        int u = (t >= d) ? sm[t - d] : 0;
        __syncthreads();
        sm[t] += u;
        __syncthreads();
    }
    if (t == 255) g_bsum[blockIdx.x] = sm[255];
    int texcl = sm[t] - msum;
    grid_barrier();                                    // B3
    if (blockIdx.x == 0 && t == 0) {
        int run = 0;
        for (int i = 0; i < NB_CSR; i++) { int v = g_bsum[i]; g_bsum[i] = run; run += v; }
        off[N_NODES] = run;
    }
    grid_barrier();                                    // B4
    int base = g_bsum[blockIdx.x] + texcl;
    if (i0 < N_NODES) { off[i0] = base;      cur[i0] = base; }
    if (i1 < N_NODES) { off[i1] = base + p0; cur[i1] = base + p0; }
    grid_barrier();                                    // B5

    for (int e = gid; e < N_EDGES; e += stride) {
        int pos = atomicAdd(&cur[edst[e]], 1);
        srcs[pos] = esrc[e] * 16;                     // pre-scaled uint4 index
    }
    for (int i = gid; i < N_NODES; i += stride) {
        int st = off[i] + deg[i], en = off[i + 1];
        for (int j = st; j < en; j++) srcs[j] = N_NODES * 16;
    }
}

// ---------------- W pack: tf32 + mma-fragment-major ---------------------------
__global__ void pack_w_tf32(const float* __restrict__ W1, const float* __restrict__ W2,
                            float* __restrict__ P1, float* __restrict__ P2)
{
    int i = blockIdx.x * blockDim.x + threadIdx.x;
    if (i >= 16 * 8 * 32) return;
    int lane = i & 31;
    int p    = (i >> 5) & 7;
    int ks   = i >> 8;
    int kc = lane & 3, nc = lane >> 2;
    int r0 = ks * 8 + kc, r1 = r0 + 4;
    int c0 = (2 * p) * 8 + nc, c1 = (2 * p + 1) * 8 + nc;
    float4 v1, v2;
    v1.x = __uint_as_float(f2tf32(W1[r0 * DIM + c0]));
    v1.y = __uint_as_float(f2tf32(W1[r1 * DIM + c0]));
    v1.z = __uint_as_float(f2tf32(W1[r0 * DIM + c1]));
    v1.w = __uint_as_float(f2tf32(W1[r1 * DIM + c1]));
    v2.x = __uint_as_float(f2tf32(W2[r0 * DIM + c0]));
    v2.y = __uint_as_float(f2tf32(W2[r1 * DIM + c0]));
    v2.z = __uint_as_float(f2tf32(W2[r0 * DIM + c1]));
    v2.w = __uint_as_float(f2tf32(W2[r1 * DIM + c1]));
    ((float4*)P1)[i] = v1;
    ((float4*)P2)[i] = v2;
}

// ---------------- tensor-core GEMM (h = X @ W, tf32 mma) ---------------------
__global__ void __launch_bounds__(256, 2) gemm_mma_kernel(
        const float* __restrict__ X,
        const float* __restrict__ Wpack,
        const float* __restrict__ attS,
        const float* __restrict__ attD,
        __nv_bfloat16* __restrict__ Hout,
        float* __restrict__ aS,
        float* __restrict__ aD,
        int heads)
{
    extern __shared__ float xsm[];            // 128 * 132 floats
    __shared__ float sS[DIM], sD[DIM];
    int tid  = threadIdx.x;
    int lane = tid & 31;
    int w    = tid >> 5;
    if (tid < DIM) { sS[tid] = attS[tid]; sD[tid] = attD[tid]; }

    // sentinel scores: padding edges contribute exp(-1e4) = 0
    if (blockIdx.x == 0 && tid < heads) aS[N_NODES * heads + tid] = -1e4f;

    int row0 = blockIdx.x * 128;
    const float4* X4 = (const float4*)X;
#pragma unroll
    for (int j = 0; j < 16; j++) {
        int idx = tid + j * 256;
        int r = idx >> 5, c = idx & 31;
        float4 v = (row0 + r < N_NODES) ? X4[(row0 + r) * 32 + c]
                                        : make_float4(0.f, 0.f, 0.f, 0.f);
        *(float4*)&xsm[r * 132 + c * 4] = v;
    }
    __syncthreads();

    int m0w = w * 16;
    if (row0 + m0w >= N_NODES) return;

    int kc = lane & 3;
    int nc = lane >> 2;
    const float* x1 = xsm + (m0w + nc) * 132;
    const float* x2 = x1 + 8 * 132;

    float acc[16][4];
#pragma unroll
    for (int nt = 0; nt < 16; nt++) {
        acc[nt][0] = 0.f; acc[nt][1] = 0.f; acc[nt][2] = 0.f; acc[nt][3] = 0.f;
    }

    const float4* Wp4 = (const float4*)Wpack;
#pragma unroll
    for (int ks = 0; ks < 16; ks++) {
        int k0 = ks * 8;
        unsigned int a0 = f2tf32(x1[k0 + kc]);
        unsigned int a1 = f2tf32(x2[k0 + kc]);
        unsigned int a2 = f2tf32(x1[k0 + kc + 4]);
        unsigned int a3 = f2tf32(x2[k0 + kc + 4]);
#pragma unroll
        for (int p = 0; p < 8; p++) {
            float4 bb = Wp4[(ks * 8 + p) * 32 + lane];
            asm("mma.sync.aligned.m16n8k8.row.col.f32.tf32.tf32.f32 "
                "{%0,%1,%2,%3}, {%4,%5,%6,%7}, {%8,%9}, {%0,%1,%2,%3};"
                : "+f"(acc[2*p][0]), "+f"(acc[2*p][1]), "+f"(acc[2*p][2]), "+f"(acc[2*p][3])
                : "r"(a0), "r"(a1), "r"(a2), "r"(a3),
                  "r"(__float_as_uint(bb.x)), "r"(__float_as_uint(bb.y)));
            asm("mma.sync.aligned.m16n8k8.row.col.f32.tf32.tf32.f32 "
                "{%0,%1,%2,%3}, {%4,%5,%6,%7}, {%8,%9}, {%0,%1,%2,%3};"
                : "+f"(acc[2*p+1][0]), "+f"(acc[2*p+1][1]), "+f"(acc[2*p+1][2]), "+f"(acc[2*p+1][3])
                : "r"(a0), "r"(a1), "r"(a2), "r"(a3),
                  "r"(__float_as_uint(bb.z)), "r"(__float_as_uint(bb.w)));
        }
    }

    int cb2 = (lane & 3) * 2;
    int r1 = row0 + m0w + nc;
    int r2 = r1 + 8;

#pragma unroll
    for (int rr = 0; rr < 2; rr++) {
        int row = (rr == 0) ? r1 : r2;
#pragma unroll
        for (int nt = 0; nt < 16; nt++) {
            __nv_bfloat162 pr = __floats2bfloat162_rn(acc[nt][rr * 2], acc[nt][rr * 2 + 1]);
            *(__nv_bfloat162*)(Hout + row * DIM + nt * 8 + cb2) = pr;
        }
        float tps = 0.f, tpd = 0.f;
#pragma unroll
        for (int h = 0; h < 8; h++) {
            int c0 = h * 16 + cb2;
            float v0 = acc[2 * h][rr * 2],     v1 = acc[2 * h][rr * 2 + 1];
            float v2 = acc[2 * h + 1][rr * 2], v3 = acc[2 * h + 1][rr * 2 + 1];
            float ps = v0 * sS[c0] + v1 * sS[c0 + 1] + v2 * sS[c0 + 8] + v3 * sS[c0 + 9];
            float pd = v0 * sD[c0] + v1 * sD[c0 + 1] + v2 * sD[c0 + 8] + v3 * sD[c0 + 9];
            ps += __shfl_xor_sync(0xffffffff, ps, 1);
            ps += __shfl_xor_sync(0xffffffff, ps, 2);
            pd += __shfl_xor_sync(0xffffffff, pd, 1);
            pd += __shfl_xor_sync(0xffffffff, pd, 2);
            if (heads == HEADS) {
                if ((lane & 3) == 0) {
                    aS[row * HEADS + h] = ps;
                    aD[row * HEADS + h] = pd;
                }
            } else { tps += ps; tpd += pd; }
        }
        if (heads == 1 && (lane & 3) == 0) { aS[row] = tps; aD[row] = tpd; }
    }
}

// ---------------- layer 1 fused aggregation (+bias+BN+ELU) ------------------
// TWO nodes per warp; padded CSR; occupancy-forced (6 blocks/SM).
__global__ void __launch_bounds__(256, 6) agg_layer1(
        const int* __restrict__ srcs, const int* __restrict__ off,
        const float* __restrict__ aS, const float* __restrict__ aD,
        const __nv_bfloat16* __restrict__ H,
        const float* __restrict__ b1,
        const float* __restrict__ bn_g, const float* __restrict__ bn_b,
        const float* __restrict__ bn_m, const float* __restrict__ bn_v,
        float* __restrict__ out)
{
    int wid  = threadIdx.x >> 5;
    int lane = threadIdx.x & 31;
    int q    = lane & 15;                 // channel partition within node
    int half = lane >> 4;
    int node = blockIdx.x * 16 + wid * 2 + half;   // 50000 = 3125 * 16, always valid
    int h    = q >> 1;                    // head (16 ch per head = 2 lanes)
    const uint4* H4 = (const uint4*)H;

    float aD_h = aD[node * HEADS + h];
    float den  = __expf(leaky(aS[node * HEADS + h] + aD_h));   // self loop
    float2 u0, u1, u2, u3;
    bf16x8_unpack(H4[node * 16 + q], u0, u1, u2, u3);
    float a0 = u0.x * den, a1 = u0.y * den, a2 = u1.x * den, a3 = u1.y * den;
    float a4 = u2.x * den, a5 = u2.y * den, a6 = u3.x * den, a7 = u3.y * den;

    int beg = off[node];
    int n   = off[node + 1] - beg;        // multiple of 4
    int noth = __shfl_xor_sync(0xffffffff, n, 16);
    int nmax = max(n, noth);

    for (int i = 0; i < nmax; i += 4) {
        const int4* sp = (i < n) ? (const int4*)(srcs + beg + i)
                                 : (const int4*)g_sentq;
        int4 s4 = *sp;                    // values are src*16
        float s0 = aS[(s4.x >> 1) + h];
        float s1 = aS[(s4.y >> 1) + h];
        float s2 = aS[(s4.z >> 1) + h];
        float s3 = aS[(s4.w >> 1) + h];
        uint4 h0 = H4[s4.x + q];
        uint4 h1 = H4[s4.y + q];
        uint4 h2 = H4[s4.z + q];
        uint4 h3 = H4[s4.w + q];
        float e0 = __expf(leaky(s0 + aD_h));
        float e1 = __expf(leaky(s1 + aD_h));
        float e2 = __expf(leaky(s2 + aD_h));
        float e3 = __expf(leaky(s3 + aD_h));
        den += (e0 + e1) + (e2 + e3);
        float2 f0, f1, f2, f3;
        bf16x8_unpack(h0, f0, f1, f2, f3);
        a0 = fmaf(f0.x, e0, a0); a1 = fmaf(f0.y, e0, a1);
        a2 = fmaf(f1.x, e0, a2); a3 = fmaf(f1.y, e0, a3);
        a4 = fmaf(f2.x, e0, a4); a5 = fmaf(f2.y, e0, a5);
        a6 = fmaf(f3.x, e0, a6); a7 = fmaf(f3.y, e0, a7);
        bf16x8_unpack(h1, f0, f1, f2, f3);
        a0 = fmaf(f0.x, e1, a0); a1 = fmaf(f0.y, e1, a1);
        a2 = fmaf(f1.x, e1, a2); a3 = fmaf(f1.y, e1, a3);
        a4 = fmaf(f2.x, e1, a4); a5 = fmaf(f2.y, e1, a5);
        a6 = fmaf(f3.x, e1, a6); a7 = fmaf(f3.y, e1, a7);
        bf16x8_unpack(h2, f0, f1, f2, f3);
        a0 = fmaf(f0.x, e2, a0); a1 = fmaf(f0.y, e2, a1);
        a2 = fmaf(f1.x, e2, a2); a3 = fmaf(f1.y, e2, a3);
        a4 = fmaf(f2.x, e2, a4); a5 = fmaf(f2.y, e2, a5);
        a6 = fmaf(f3.x, e2, a6); a7 = fmaf(f3.y, e2, a7);
        bf16x8_unpack(h3, f0, f1, f2, f3);
        a0 = fmaf(f0.x, e3, a0); a1 = fmaf(f0.y, e3, a1);
        a2 = fmaf(f1.x, e3, a2); a3 = fmaf(f1.y, e3, a3);
        a4 = fmaf(f2.x, e3, a4); a5 = fmaf(f2.y, e3, a5);
        a6 = fmaf(f3.x, e3, a6); a7 = fmaf(f3.y, e3, a7);
    }
    float inv = 1.f / den;

    // epilogue over this lane's 8 channels (cols q*8 .. q*8+7)
    const float4* B1 = (const float4*)b1;
    const float4* GG = (const float4*)bn_g;
    const float4* BE = (const float4*)bn_b;
    const float4* MU = (const float4*)bn_m;
    const float4* VA = (const float4*)bn_v;
    float4* O = (float4*)out;
    float r[8] = {a0, a1, a2, a3, a4, a5, a6, a7};
#pragma unroll
    for (int p = 0; p < 2; p++) {
        float4 bb = B1[q * 2 + p];
        float4 gg = GG[q * 2 + p];
        float4 be = BE[q * 2 + p];
        float4 mu = MU[q * 2 + p];
        float4 va = VA[q * 2 + p];
        float4 o;
        o.x = (r[p*4+0] * inv + bb.x - mu.x) * gg.x * rsqrtf(va.x + BN_EPS) + be.x;
        o.y = (r[p*4+1] * inv + bb.y - mu.y) * gg.y * rsqrtf(va.y + BN_EPS) + be.y;
        o.z = (r[p*4+2] * inv + bb.z - mu.z) * gg.z * rsqrtf(va.z + BN_EPS) + be.z;
        o.w = (r[p*4+3] * inv + bb.w - mu.w) * gg.w * rsqrtf(va.w + BN_EPS) + be.w;
        o.x = o.x > 0.f ? o.x : expm1f(o.x);
        o.y = o.y > 0.f ? o.y : expm1f(o.y);
        o.z = o.z > 0.f ? o.z : expm1f(o.z);
        o.w = o.w > 0.f ? o.w : expm1f(o.w);
        O[node * 32 + q * 2 + p] = o;
    }
}

// ---------------- layer 2 fused aggregation (+pool) -------------------------
__global__ void __launch_bounds__(256, 6) agg_layer2(
        const int* __restrict__ srcs, const int* __restrict__ off,
        const float* __restrict__ aS, const float* __restrict__ aD,
        const __nv_bfloat16* __restrict__ H,
        const int* __restrict__ batch,
        float* __restrict__ gsum)
{
    __shared__ float sacc[16][DIM];
    __shared__ int   sbatch[16];
    int wid  = threadIdx.x >> 5;
    int lane = threadIdx.x & 31;
    int q    = lane & 15;
    int half = lane >> 4;
    int node = blockIdx.x * 16 + wid * 2 + half;   // always valid
    int nl   = wid * 2 + half;                     // node slot in block
    const uint4* H4 = (const uint4*)H;

    float aDn = aD[node];
    float den = __expf(leaky(aS[node] + aDn));     // self loop
    float2 u0, u1, u2, u3;
    bf16x8_unpack(H4[node * 16 + q], u0, u1, u2, u3);
    float a0 = u0.x * den, a1 = u0.y * den, a2 = u1.x * den, a3 = u1.y * den;
    float a4 = u2.x * den, a5 = u2.y * den, a6 = u3.x * den, a7 = u3.y * den;

    int beg = off[node];
    int n   = off[node + 1] - beg;
    int noth = __shfl_xor_sync(0xffffffff, n, 16);
    int nmax = max(n, noth);

    for (int i = 0; i < nmax; i += 4) {
        const int4* sp = (i < n) ? (const int4*)(srcs + beg + i)
                                 : (const int4*)g_sentq;
        int4 s4 = *sp;
        float s0 = aS[s4.x >> 4];
        float s1 = aS[s4.y >> 4];
        float s2 = aS[s4.z >> 4];
        float s3 = aS[s4.w >> 4];
        uint4 h0 = H4[s4.x + q];
        uint4 h1 = H4[s4.y + q];
        uint4 h2 = H4[s4.z + q];
        uint4 h3 = H4[s4.w + q];
        float e0 = __expf(leaky(s0 + aDn));
        float e1 = __expf(leaky(s1 + aDn));
        float e2 = __expf(leaky(s2 + aDn));
        float e3 = __expf(leaky(s3 + aDn));
        den += (e0 + e1) + (e2 + e3);
        float2 f0, f1, f2, f3;
        bf16x8_unpack(h0, f0, f1, f2, f3);
        a0 = fmaf(f0.x, e0, a0); a1 = fmaf(f0.y, e0, a1);
        a2 = fmaf(f1.x, e0, a2); a3 = fmaf(f1.y, e0, a3);
        a4 = fmaf(f2.x, e0, a4); a5 = fmaf(f2.y, e0, a5);
        a6 = fmaf(f3.x, e0, a6); a7 = fmaf(f3.y, e0, a7);
        bf16x8_unpack(h1, f0, f1, f2, f3);
        a0 = fmaf(f0.x, e1, a0); a1 = fmaf(f0.y, e1, a1);
        a2 = fmaf(f1.x, e1, a2); a3 = fmaf(f1.y, e1, a3);
        a4 = fmaf(f2.x, e1, a4); a5 = fmaf(f2.y, e1, a5);
        a6 = fmaf(f3.x, e1, a6); a7 = fmaf(f3.y, e1, a7);
        bf16x8_unpack(h2, f0, f1, f2, f3);
        a0 = fmaf(f0.x, e2, a0); a1 = fmaf(f0.y, e2, a1);
        a2 = fmaf(f1.x, e2, a2); a3 = fmaf(f1.y, e2, a3);
        a4 = fmaf(f2.x, e2, a4); a5 = fmaf(f2.y, e2, a5);
        a6 = fmaf(f3.x, e2, a6); a7 = fmaf(f3.y, e2, a7);
        bf16x8_unpack(h3, f0, f1, f2, f3);
        a0 = fmaf(f0.x, e3, a0); a1 = fmaf(f0.y, e3, a1);
        a2 = fmaf(f1.x, e3, a2); a3 = fmaf(f1.y, e3, a3);
        a4 = fmaf(f2.x, e3, a4); a5 = fmaf(f2.y, e3, a5);
        a6 = fmaf(f3.x, e3, a6); a7 = fmaf(f3.y, e3, a7);
    }
    float inv = 1.f / den;
    a0 *= inv; a1 *= inv; a2 *= inv; a3 *= inv;
    a4 *= inv; a5 *= inv; a6 *= inv; a7 *= inv;
    int g = batch[node];

    if (q == 0) sbatch[nl] = g;
    float* sr = &sacc[nl][q * 8];
    sr[0] = a0; sr[1] = a1; sr[2] = a2; sr[3] = a3;
    sr[4] = a4; sr[5] = a5; sr[6] = a6; sr[7] = a7;
    __syncthreads();

    int g0 = sbatch[0];
    bool uniform = true;
#pragma unroll
    for (int w = 1; w < 16; w++) uniform &= (sbatch[w] == g0);

    if (uniform) {
        if (threadIdx.x < DIM) {
            float v = 0.f;
#pragma unroll
            for (int w = 0; w < 16; w++) v += sacc[w][threadIdx.x];
            atomicAdd(&gsum[g0 * DIM + threadIdx.x], v);
        }
    } else {
        float* dp = &gsum[g * DIM + q * 8];
        atomicAdd(dp + 0, a0); atomicAdd(dp + 1, a1);
        atomicAdd(dp + 2, a2); atomicAdd(dp + 3, a3);
        atomicAdd(dp + 4, a4); atomicAdd(dp + 5, a5);
        atomicAdd(dp + 6, a6); atomicAdd(dp + 7, a7);
    }
}

// ---------------- classifier MLP ---------------------------------------------
__global__ void classifier(const float* __restrict__ gsum, const float* __restrict__ gcnt,
                           const float* __restrict__ b2,
                           const float* __restrict__ Wc1, const float* __restrict__ bc1,
                           const float* __restrict__ Wc2, const float* __restrict__ bc2,
                           float* __restrict__ out)
{
    __shared__ float emb[DIM];
    __shared__ float z[64];
    int g = blockIdx.x, t = threadIdx.x;
    float cnt = fmaxf(gcnt[g], 1.f);
    emb[t] = gsum[g * DIM + t] / cnt + b2[t];
    __syncthreads();
    if (t < 64) {
        float a = bc1[t];
#pragma unroll 8
        for (int k = 0; k < DIM; k++) a = fmaf(emb[k], Wc1[k * 64 + t], a);
        z[t] = a > 0.f ? a : expm1f(a);
    }
    __syncthreads();
    if (t < NCLASS) {
        float a = bc2[t];
#pragma unroll
        for (int k = 0; k < 64; k++) a = fmaf(z[k], Wc2[k * NCLASS + t], a);
        out[g * NCLASS + t] = a;
    }
}

// ---------------- launch ------------------------------------------------------
extern "C" void kernel_launch(void* const* d_in, const int* in_sizes, int n_in,
                              void* d_out, int out_size)
{
    const float* x        = (const float*)d_in[0];
    const int*   esrc     = (const int*)  d_in[1];
    const int*   edst     = (const int*)  d_in[2];
    const int*   batch    = (const int*)  d_in[3];
    const float* W1       = (const float*)d_in[4];
    const float* b1       = (const float*)d_in[5];
    const float* att_src1 = (const float*)d_in[6];
    const float* att_dst1 = (const float*)d_in[7];
    const float* W2       = (const float*)d_in[8];
    const float* b2       = (const float*)d_in[9];
    const float* att_src2 = (const float*)d_in[10];
    const float* att_dst2 = (const float*)d_in[11];
    const float* bn_g     = (const float*)d_in[12];
    const float* bn_b     = (const float*)d_in[13];
    const float* bn_m     = (const float*)d_in[14];
    const float* bn_v     = (const float*)d_in[15];
    const float* Wc1      = (const float*)d_in[16];
    const float* bc1      = (const float*)d_in[17];
    const float* Wc2      = (const float*)d_in[18];
    const float* bc2      = (const float*)d_in[19];
    float* out = (float*)d_out;

    __nv_bfloat16 *p_h;
    float *p_mid, *p_w1p, *p_w2p, *p_as, *p_ad, *p_gsum, *p_gcnt;
    int *p_deg, *p_off, *p_cur, *p_srcs;
    cudaGetSymbolAddress((void**)&p_h,    g_h);
    cudaGetSymbolAddress((void**)&p_mid,  g_mid);
    cudaGetSymbolAddress((void**)&p_w1p,  g_w1p);
    cudaGetSymbolAddress((void**)&p_w2p,  g_w2p);
    cudaGetSymbolAddress((void**)&p_as,   g_asrc);
    cudaGetSymbolAddress((void**)&p_ad,   g_adst);
    cudaGetSymbolAddress((void**)&p_deg,  g_deg);
    cudaGetSymbolAddress((void**)&p_off,  g_off);
    cudaGetSymbolAddress((void**)&p_cur,  g_cur);
    cudaGetSymbolAddress((void**)&p_srcs, g_srcs);
    cudaGetSymbolAddress((void**)&p_gsum, g_gsum);
    cudaGetSymbolAddress((void**)&p_gcnt, g_gcnt);

    static cudaStream_t s2 = 0;
    static cudaEvent_t evFork = 0, evJoin = 0;
    const int XSMEM = 128 * 132 * (int)sizeof(float);
    if (s2 == 0) {
        cudaStreamCreateWithFlags(&s2, cudaStreamNonBlocking);
        cudaEventCreateWithFlags(&evFork, cudaEventDisableTiming);
        cudaEventCreateWithFlags(&evJoin, cudaEventDisableTiming);
        cudaFuncSetAttribute(gemm_mma_kernel,
                             cudaFuncAttributeMaxDynamicSharedMemorySize, XSMEM);
    }

    const int TB = 256;
    int gemm_blocks = (N_NODES + 127) / 128;
    int agg_blocks  = N_NODES / 16;           // 3125 (50000 % 16 == 0)

    cudaEventRecord(evFork, 0);
    cudaStreamWaitEvent(s2, evFork, 0);

    build_csr<<<NB_CSR, TB, 0, s2>>>(esrc, edst, batch, p_deg, p_off, p_cur,  // 0
                                     p_srcs, p_gsum, p_gcnt);
    cudaEventRecord(evJoin, s2);

    pack_w_tf32<<<(16 * 8 * 32 + TB - 1) / TB, TB>>>(W1, W2, p_w1p, p_w2p);   // 1
    gemm_mma_kernel<<<gemm_blocks, TB, XSMEM>>>(x, p_w1p, att_src1, att_dst1, // 2
                                                p_h, p_as, p_ad, HEADS);
    cudaStreamWaitEvent(0, evJoin, 0);

    agg_layer1<<<agg_blocks, TB>>>(p_srcs, p_off, p_as, p_ad, p_h,            // 3 <- profiled
                                   b1, bn_g, bn_b, bn_m, bn_v, p_mid);
    gemm_mma_kernel<<<gemm_blocks, TB, XSMEM>>>(p_mid, p_w2p, att_src2,       // 4
                                                att_dst2, p_h, p_as, p_ad, 1);
    agg_layer2<<<agg_blocks, TB>>>(p_srcs, p_off, p_as, p_ad, p_h, batch, p_gsum); // 5
    classifier<<<GRAPHS, DIM>>>(p_gsum, p_gcnt, b2, Wc1, bc1, Wc2, bc2, out);      // 6
}

// round 14
// speedup vs baseline: 3.7740x; 1.0049x over previous
#include <cuda_runtime.h>
#include <cuda_bf16.h>
#include <math.h>

#define N_NODES 50000
#define N_EDGES 800000
#define DIM     128
#define HEADS   8
#define GRAPHS  64
#define NCLASS  10
#define SLOPE   0.2f
#define BN_EPS  1e-5f
#define NB_CSR  132
#define MAX_PADDED (N_EDGES + 4 * N_NODES)

// ---------------- scratch (device globals) ----------------------------------
__device__ __nv_bfloat16 g_h[(N_NODES + 1) * DIM];  // +1: sentinel row (zero-init)
__device__ __nv_bfloat16 g_midb[N_NODES * DIM];     // layer1 output, bf16
__device__ float g_w1p[DIM * DIM];
__device__ float g_w2p[DIM * DIM];
__device__ float g_asrc[(N_NODES + 1) * HEADS];     // +1: sentinel scores
__device__ float g_adst[N_NODES * HEADS];
__device__ int   g_deg[N_NODES];
__device__ int   g_off[N_NODES + 1];
__device__ int   g_cur[N_NODES];
__device__ int   g_srcs[MAX_PADDED];                // stores src*16 (uint4 H index)
__device__ int   g_sentq[4];                        // sentinel quad {N_NODES*16 x4}
__device__ float g_gsum[GRAPHS * DIM];
__device__ float g_gcnt[GRAPHS];
__device__ int   g_barcnt = 0;
__device__ int   g_bargen = 0;
__device__ int   g_bsum[NB_CSR];

__device__ __forceinline__ float leaky(float x) { return fmaxf(x, SLOPE * x); }

__device__ __forceinline__ void bf16x8_unpack(uint4 v, float2& f0, float2& f1,
                                              float2& f2, float2& f3)
{
    f0 = __bfloat1622float2(*(const __nv_bfloat162*)&v.x);
    f1 = __bfloat1622float2(*(const __nv_bfloat162*)&v.y);
    f2 = __bfloat1622float2(*(const __nv_bfloat162*)&v.z);
    f3 = __bfloat1622float2(*(const __nv_bfloat162*)&v.w);
}

__device__ __forceinline__ unsigned int f2tf32(float f)
{
    unsigned int u;
    asm("cvt.rna.tf32.f32 %0, %1;" : "=r"(u) : "f"(f));
    return u;
}

// sense-reversing grid barrier (all NB_CSR blocks resident)
__device__ __forceinline__ void grid_barrier()
{
    __syncthreads();
    if (threadIdx.x == 0) {
        __threadfence();
        int gen = ((volatile int*)&g_bargen)[0];
        if (atomicAdd(&g_barcnt, 1) == (int)gridDim.x - 1) {
            g_barcnt = 0;
            __threadfence();
            atomicAdd(&g_bargen, 1);
        } else {
            while (((volatile int*)&g_bargen)[0] == gen) { }
        }
        __threadfence();
    }
    __syncthreads();
}

// ---------------- fused CSR build (padded to 4, src*16) + pool counts --------
__global__ void __launch_bounds__(256) build_csr(
        const int* __restrict__ esrc, const int* __restrict__ edst,
        const int* __restrict__ batch,
        int* __restrict__ deg, int* __restrict__ off, int* __restrict__ cur,
        int* __restrict__ srcs, float* __restrict__ gsum, float* __restrict__ gcnt)
{
    __shared__ int sm[256];
    __shared__ int bh[GRAPHS];
    int t   = threadIdx.x;
    int gid = blockIdx.x * 256 + t;
    const int stride = NB_CSR * 256;

    for (int i = gid; i < N_NODES; i += stride) deg[i] = 0;
    for (int i = gid; i < GRAPHS * DIM; i += stride) gsum[i] = 0.f;
    if (gid < GRAPHS) gcnt[gid] = 0.f;
    if (gid < 4) g_sentq[gid] = N_NODES * 16;
    if (t < GRAPHS) bh[t] = 0;
    grid_barrier();                                    // B1

    for (int e = gid; e < N_EDGES; e += stride) atomicAdd(&deg[edst[e]], 1);
    for (int i = gid; i < N_NODES; i += stride) atomicAdd(&bh[batch[i]], 1);
    __syncthreads();
    if (t < GRAPHS && bh[t] > 0) atomicAdd(&gcnt[t], (float)bh[t]);
    grid_barrier();                                    // B2

    int i0 = gid * 2, i1 = gid * 2 + 1;
    int d0 = (i0 < N_NODES) ? deg[i0] : 0;
    int d1 = (i1 < N_NODES) ? deg[i1] : 0;
    int p0 = (d0 + 3) & ~3;
    int p1 = (d1 + 3) & ~3;
    int msum = p0 + p1;
    sm[t] = msum;
    __syncthreads();
    for (int d = 1; d < 256; d <<= 1) {
        int u = (t >= d) ? sm[t - d] : 0;
        __syncthreads();
        sm[t] += u;
        __syncthreads();
    }
    if (t == 255) g_bsum[blockIdx.x] = sm[255];
    int texcl = sm[t] - msum;
    grid_barrier();                                    // B3
    if (blockIdx.x == 0 && t == 0) {
        int run = 0;
        for (int i = 0; i < NB_CSR; i++) { int v = g_bsum[i]; g_bsum[i] = run; run += v; }
        off[N_NODES] = run;
    }
    grid_barrier();                                    // B4
    int base = g_bsum[blockIdx.x] + texcl;
    if (i0 < N_NODES) { off[i0] = base;      cur[i0] = base; }
    if (i1 < N_NODES) { off[i1] = base + p0; cur[i1] = base + p0; }
    grid_barrier();                                    // B5

    for (int e = gid; e < N_EDGES; e += stride) {
        int pos = atomicAdd(&cur[edst[e]], 1);
        srcs[pos] = esrc[e] * 16;                     // pre-scaled uint4 index
    }
    for (int i = gid; i < N_NODES; i += stride) {
        int st = off[i] + deg[i], en = off[i + 1];
        for (int j = st; j < en; j++) srcs[j] = N_NODES * 16;
    }
}

// ---------------- W pack: tf32 + mma-fragment-major ---------------------------
__global__ void pack_w_tf32(const float* __restrict__ W1, const float* __restrict__ W2,
                            float* __restrict__ P1, float* __restrict__ P2)
{
    int i = blockIdx.x * blockDim.x + threadIdx.x;
    if (i >= 16 * 8 * 32) return;
    int lane = i & 31;
    int p    = (i >> 5) & 7;
    int ks   = i >> 8;
    int kc = lane & 3, nc = lane >> 2;
    int r0 = ks * 8 + kc, r1 = r0 + 4;
    int c0 = (2 * p) * 8 + nc, c1 = (2 * p + 1) * 8 + nc;
    float4 v1, v2;
    v1.x = __uint_as_float(f2tf32(W1[r0 * DIM + c0]));
    v1.y = __uint_as_float(f2tf32(W1[r1 * DIM + c0]));
    v1.z = __uint_as_float(f2tf32(W1[r0 * DIM + c1]));
    v1.w = __uint_as_float(f2tf32(W1[r1 * DIM + c1]));
    v2.x = __uint_as_float(f2tf32(W2[r0 * DIM + c0]));
    v2.y = __uint_as_float(f2tf32(W2[r1 * DIM + c0]));
    v2.z = __uint_as_float(f2tf32(W2[r0 * DIM + c1]));
    v2.w = __uint_as_float(f2tf32(W2[r1 * DIM + c1]));
    ((float4*)P1)[i] = v1;
    ((float4*)P2)[i] = v2;
}

// ---------------- tensor-core GEMM (h = X @ W, tf32 mma) ---------------------
// in_bf16: input rows are bf16 (g_midb); otherwise fp32.
__global__ void __launch_bounds__(256, 2) gemm_mma_kernel(
        const float* __restrict__ X,
        const float* __restrict__ Wpack,
        const float* __restrict__ attS,
        const float* __restrict__ attD,
        __nv_bfloat16* __restrict__ Hout,
        float* __restrict__ aS,
        float* __restrict__ aD,
        int heads, int in_bf16)
{
    extern __shared__ float xsm[];            // 128 * 132 floats
    __shared__ float sS[DIM], sD[DIM];
    int tid  = threadIdx.x;
    int lane = tid & 31;
    int w    = tid >> 5;
    if (tid < DIM) { sS[tid] = attS[tid]; sD[tid] = attD[tid]; }

    // sentinel scores: padding edges contribute exp(-1e4) = 0
    if (blockIdx.x == 0 && tid < heads) aS[N_NODES * heads + tid] = -1e4f;

    int row0 = blockIdx.x * 128;
    if (!in_bf16) {
        const float4* X4 = (const float4*)X;
#pragma unroll
        for (int j = 0; j < 16; j++) {
            int idx = tid + j * 256;
            int r = idx >> 5, c = idx & 31;
            float4 v = (row0 + r < N_NODES) ? X4[(row0 + r) * 32 + c]
                                            : make_float4(0.f, 0.f, 0.f, 0.f);
            *(float4*)&xsm[r * 132 + c * 4] = v;
        }
    } else {
        const uint4* Xb = (const uint4*)X;
#pragma unroll
        for (int j = 0; j < 8; j++) {
            int idx = tid + j * 256;              // 0..2047
            int r = idx >> 4, c = idx & 15;
            uint4 v = (row0 + r < N_NODES) ? Xb[(row0 + r) * 16 + c]
                                           : make_uint4(0, 0, 0, 0);
            float2 f0, f1, f2, f3;
            bf16x8_unpack(v, f0, f1, f2, f3);
            *(float4*)&xsm[r * 132 + c * 8]     = make_float4(f0.x, f0.y, f1.x, f1.y);
            *(float4*)&xsm[r * 132 + c * 8 + 4] = make_float4(f2.x, f2.y, f3.x, f3.y);
        }
    }
    __syncthreads();

    int m0w = w * 16;
    if (row0 + m0w >= N_NODES) return;

    int kc = lane & 3;
    int nc = lane >> 2;
    const float* x1 = xsm + (m0w + nc) * 132;
    const float* x2 = x1 + 8 * 132;

    float acc[16][4];
#pragma unroll
    for (int nt = 0; nt < 16; nt++) {
        acc[nt][0] = 0.f; acc[nt][1] = 0.f; acc[nt][2] = 0.f; acc[nt][3] = 0.f;
    }

    const float4* Wp4 = (const float4*)Wpack;
#pragma unroll
    for (int ks = 0; ks < 16; ks++) {
        int k0 = ks * 8;
        unsigned int a0 = f2tf32(x1[k0 + kc]);
        unsigned int a1 = f2tf32(x2[k0 + kc]);
        unsigned int a2 = f2tf32(x1[k0 + kc + 4]);
        unsigned int a3 = f2tf32(x2[k0 + kc + 4]);
#pragma unroll
        for (int p = 0; p < 8; p++) {
            float4 bb = Wp4[(ks * 8 + p) * 32 + lane];
            asm("mma.sync.aligned.m16n8k8.row.col.f32.tf32.tf32.f32 "
                "{%0,%1,%2,%3}, {%4,%5,%6,%7}, {%8,%9}, {%0,%1,%2,%3};"
                : "+f"(acc[2*p][0]), "+f"(acc[2*p][1]), "+f"(acc[2*p][2]), "+f"(acc[2*p][3])
                : "r"(a0), "r"(a1), "r"(a2), "r"(a3),
                  "r"(__float_as_uint(bb.x)), "r"(__float_as_uint(bb.y)));
            asm("mma.sync.aligned.m16n8k8.row.col.f32.tf32.tf32.f32 "
                "{%0,%1,%2,%3}, {%4,%5,%6,%7}, {%8,%9}, {%0,%1,%2,%3};"
                : "+f"(acc[2*p+1][0]), "+f"(acc[2*p+1][1]), "+f"(acc[2*p+1][2]), "+f"(acc[2*p+1][3])
                : "r"(a0), "r"(a1), "r"(a2), "r"(a3),
                  "r"(__float_as_uint(bb.z)), "r"(__float_as_uint(bb.w)));
        }
    }

    int cb2 = (lane & 3) * 2;
    int r1 = row0 + m0w + nc;
    int r2 = r1 + 8;

#pragma unroll
    for (int rr = 0; rr < 2; rr++) {
        int row = (rr == 0) ? r1 : r2;
#pragma unroll
        for (int nt = 0; nt < 16; nt++) {
            __nv_bfloat162 pr = __floats2bfloat162_rn(acc[nt][rr * 2], acc[nt][rr * 2 + 1]);
            *(__nv_bfloat162*)(Hout + row * DIM + nt * 8 + cb2) = pr;
        }
        float tps = 0.f, tpd = 0.f;
#pragma unroll
        for (int h = 0; h < 8; h++) {
            int c0 = h * 16 + cb2;
            float v0 = acc[2 * h][rr * 2],     v1 = acc[2 * h][rr * 2 + 1];
            float v2 = acc[2 * h + 1][rr * 2], v3 = acc[2 * h + 1][rr * 2 + 1];
            float ps = v0 * sS[c0] + v1 * sS[c0 + 1] + v2 * sS[c0 + 8] + v3 * sS[c0 + 9];
            float pd = v0 * sD[c0] + v1 * sD[c0 + 1] + v2 * sD[c0 + 8] + v3 * sD[c0 + 9];
            ps += __shfl_xor_sync(0xffffffff, ps, 1);
            ps += __shfl_xor_sync(0xffffffff, ps, 2);
            pd += __shfl_xor_sync(0xffffffff, pd, 1);
            pd += __shfl_xor_sync(0xffffffff, pd, 2);
            if (heads == HEADS) {
                if ((lane & 3) == 0) {
                    aS[row * HEADS + h] = ps;
                    aD[row * HEADS + h] = pd;
                }
            } else { tps += ps; tpd += pd; }
        }
        if (heads == 1 && (lane & 3) == 0) { aS[row] = tps; aD[row] = tpd; }
    }
}

// ---------------- agg edge-quad bodies ----------------------------------------
#define AGG1_QUAD(s4)                                                          \
    do {                                                                       \
        float s0 = aS[((s4).x >> 1) + h];                                      \
        float s1 = aS[((s4).y >> 1) + h];                                      \
        float s2 = aS[((s4).z >> 1) + h];                                      \
        float s3 = aS[((s4).w >> 1) + h];                                      \
        uint4 h0 = H4[(s4).x + q];                                             \
        uint4 h1 = H4[(s4).y + q];                                             \
        uint4 h2 = H4[(s4).z + q];                                             \
        uint4 h3 = H4[(s4).w + q];                                             \
        float e0 = __expf(leaky(s0 + aD_h));                                   \
        float e1 = __expf(leaky(s1 + aD_h));                                   \
        float e2 = __expf(leaky(s2 + aD_h));                                   \
        float e3 = __expf(leaky(s3 + aD_h));                                   \
        den += (e0 + e1) + (e2 + e3);                                          \
        float2 f0, f1, f2, f3;                                                 \
        bf16x8_unpack(h0, f0, f1, f2, f3);                                     \
        a0 = fmaf(f0.x, e0, a0); a1 = fmaf(f0.y, e0, a1);                      \
        a2 = fmaf(f1.x, e0, a2); a3 = fmaf(f1.y, e0, a3);                      \
        a4 = fmaf(f2.x, e0, a4); a5 = fmaf(f2.y, e0, a5);                      \
        a6 = fmaf(f3.x, e0, a6); a7 = fmaf(f3.y, e0, a7);                      \
        bf16x8_unpack(h1, f0, f1, f2, f3);                                     \
        a0 = fmaf(f0.x, e1, a0); a1 = fmaf(f0.y, e1, a1);                      \
        a2 = fmaf(f1.x, e1, a2); a3 = fmaf(f1.y, e1, a3);                      \
        a4 = fmaf(f2.x, e1, a4); a5 = fmaf(f2.y, e1, a5);                      \
        a6 = fmaf(f3.x, e1, a6); a7 = fmaf(f3.y, e1, a7);                      \
        bf16x8_unpack(h2, f0, f1, f2, f3);                                     \
        a0 = fmaf(f0.x, e2, a0); a1 = fmaf(f0.y, e2, a1);                      \
        a2 = fmaf(f1.x, e2, a2); a3 = fmaf(f1.y, e2, a3);                      \
        a4 = fmaf(f2.x, e2, a4); a5 = fmaf(f2.y, e2, a5);                      \
        a6 = fmaf(f3.x, e2, a6); a7 = fmaf(f3.y, e2, a7);                      \
        bf16x8_unpack(h3, f0, f1, f2, f3);                                     \
        a0 = fmaf(f0.x, e3, a0); a1 = fmaf(f0.y, e3, a1);                      \
        a2 = fmaf(f1.x, e3, a2); a3 = fmaf(f1.y, e3, a3);                      \
        a4 = fmaf(f2.x, e3, a4); a5 = fmaf(f2.y, e3, a5);                      \
        a6 = fmaf(f3.x, e3, a6); a7 = fmaf(f3.y, e3, a7);                      \
    } while (0)

#define AGG2_QUAD(s4)                                                          \
    do {                                                                       \
        float s0 = aS[(s4).x >> 4];                                            \
        float s1 = aS[(s4).y >> 4];                                            \
        float s2 = aS[(s4).z >> 4];                                            \
        float s3 = aS[(s4).w >> 4];                                            \
        uint4 h0 = H4[(s4).x + q];                                             \
        uint4 h1 = H4[(s4).y + q];                                             \
        uint4 h2 = H4[(s4).z + q];                                             \
        uint4 h3 = H4[(s4).w + q];                                             \
        float e0 = __expf(leaky(s0 + aDn));                                    \
        float e1 = __expf(leaky(s1 + aDn));                                    \
        float e2 = __expf(leaky(s2 + aDn));                                    \
        float e3 = __expf(leaky(s3 + aDn));                                    \
        den += (e0 + e1) + (e2 + e3);                                          \
        float2 f0, f1, f2, f3;                                                 \
        bf16x8_unpack(h0, f0, f1, f2, f3);                                     \
        a0 = fmaf(f0.x, e0, a0); a1 = fmaf(f0.y, e0, a1);                      \
        a2 = fmaf(f1.x, e0, a2); a3 = fmaf(f1.y, e0, a3);                      \
        a4 = fmaf(f2.x, e0, a4); a5 = fmaf(f2.y, e0, a5);                      \
        a6 = fmaf(f3.x, e0, a6); a7 = fmaf(f3.y, e0, a7);                      \
        bf16x8_unpack(h1, f0, f1, f2, f3);                                     \
        a0 = fmaf(f0.x, e1, a0); a1 = fmaf(f0.y, e1, a1);                      \
        a2 = fmaf(f1.x, e1, a2); a3 = fmaf(f1.y, e1, a3);                      \
        a4 = fmaf(f2.x, e1, a4); a5 = fmaf(f2.y, e1, a5);                      \
        a6 = fmaf(f3.x, e1, a6); a7 = fmaf(f3.y, e1, a7);                      \
        bf16x8_unpack(h2, f0, f1, f2, f3);                                     \
        a0 = fmaf(f0.x, e2, a0); a1 = fmaf(f0.y, e2, a1);                      \
        a2 = fmaf(f1.x, e2, a2); a3 = fmaf(f1.y, e2, a3);                      \
        a4 = fmaf(f2.x, e2, a4); a5 = fmaf(f2.y, e2, a5);                      \
        a6 = fmaf(f3.x, e2, a6); a7 = fmaf(f3.y, e2, a7);                      \
        bf16x8_unpack(h3, f0, f1, f2, f3);                                     \
        a0 = fmaf(f0.x, e3, a0); a1 = fmaf(f0.y, e3, a1);                      \
        a2 = fmaf(f1.x, e3, a2); a3 = fmaf(f1.y, e3, a3);                      \
        a4 = fmaf(f2.x, e3, a4); a5 = fmaf(f2.y, e3, a5);                      \
        a6 = fmaf(f3.x, e3, a6); a7 = fmaf(f3.y, e3, a7);                      \
    } while (0)

// ---------------- layer 1 fused aggregation (+bias+BN+ELU, bf16 out) --------
__global__ void __launch_bounds__(256, 6) agg_layer1(
        const int* __restrict__ srcs, const int* __restrict__ off,
        const float* __restrict__ aS, const float* __restrict__ aD,
        const __nv_bfloat16* __restrict__ H,
        const float* __restrict__ b1,
        const float* __restrict__ bn_g, const float* __restrict__ bn_b,
        const float* __restrict__ bn_m, const float* __restrict__ bn_v,
        __nv_bfloat16* __restrict__ out)
{
    int wid  = threadIdx.x >> 5;
    int lane = threadIdx.x & 31;
    int q    = lane & 15;
    int half = lane >> 4;
    int node = blockIdx.x * 16 + wid * 2 + half;   // 50000 = 3125*16, always valid
    int h    = q >> 1;
    const uint4* H4 = (const uint4*)H;

    float aD_h = aD[node * HEADS + h];
    float den  = __expf(leaky(aS[node * HEADS + h] + aD_h));   // self loop
    float2 u0, u1, u2, u3;
    bf16x8_unpack(H4[node * 16 + q], u0, u1, u2, u3);
    float a0 = u0.x * den, a1 = u0.y * den, a2 = u1.x * den, a3 = u1.y * den;
    float a4 = u2.x * den, a5 = u2.y * den, a6 = u3.x * den, a7 = u3.y * den;

    int beg = off[node];
    int n   = off[node + 1] - beg;        // multiple of 4
    int noth = __shfl_xor_sync(0xffffffff, n, 16);
    int nqmin = min(n, noth) >> 2;
    int nqmax = max(n, noth) >> 2;
    int nq    = n >> 2;
    const int4* base = (const int4*)(srcs + beg);

    int iq = 0;
#pragma unroll 2
    for (; iq < nqmin; iq++) {
        int4 s4 = base[iq];
        AGG1_QUAD(s4);
    }
    for (; iq < nqmax; iq++) {
        int4 s4 = (iq < nq) ? base[iq] : *(const int4*)g_sentq;
        AGG1_QUAD(s4);
    }
    float inv = 1.f / den;

    // epilogue: + b1, BN(eval), ELU, bf16 pack
    const float4* B1 = (const float4*)b1;
    const float4* GG = (const float4*)bn_g;
    const float4* BE = (const float4*)bn_b;
    const float4* MU = (const float4*)bn_m;
    const float4* VA = (const float4*)bn_v;
    float r[8] = {a0, a1, a2, a3, a4, a5, a6, a7};
    float4 oo[2];
#pragma unroll
    for (int p = 0; p < 2; p++) {
        float4 bb = B1[q * 2 + p];
        float4 gg = GG[q * 2 + p];
        float4 be = BE[q * 2 + p];
        float4 mu = MU[q * 2 + p];
        float4 va = VA[q * 2 + p];
        float4 o;
        o.x = (r[p*4+0] * inv + bb.x - mu.x) * gg.x * rsqrtf(va.x + BN_EPS) + be.x;
        o.y = (r[p*4+1] * inv + bb.y - mu.y) * gg.y * rsqrtf(va.y + BN_EPS) + be.y;
        o.z = (r[p*4+2] * inv + bb.z - mu.z) * gg.z * rsqrtf(va.z + BN_EPS) + be.z;
        o.w = (r[p*4+3] * inv + bb.w - mu.w) * gg.w * rsqrtf(va.w + BN_EPS) + be.w;
        o.x = o.x > 0.f ? o.x : expm1f(o.x);
        o.y = o.y > 0.f ? o.y : expm1f(o.y);
        o.z = o.z > 0.f ? o.z : expm1f(o.z);
        o.w = o.w > 0.f ? o.w : expm1f(o.w);
        oo[p] = o;
    }
    uint4 ob;
    *(__nv_bfloat162*)&ob.x = __floats2bfloat162_rn(oo[0].x, oo[0].y);
    *(__nv_bfloat162*)&ob.y = __floats2bfloat162_rn(oo[0].z, oo[0].w);
    *(__nv_bfloat162*)&ob.z = __floats2bfloat162_rn(oo[1].x, oo[1].y);
    *(__nv_bfloat162*)&ob.w = __floats2bfloat162_rn(oo[1].z, oo[1].w);
    ((uint4*)out)[node * 16 + q] = ob;
}

// ---------------- layer 2 fused aggregation (+pool) -------------------------
__global__ void __launch_bounds__(256, 6) agg_layer2(
        const int* __restrict__ srcs, const int* __restrict__ off,
        const float* __restrict__ aS, const float* __restrict__ aD,
        const __nv_bfloat16* __restrict__ H,
        const int* __restrict__ batch,
        float* __restrict__ gsum)
{
    __shared__ float sacc[16][DIM];
    __shared__ int   sbatch[16];
    int wid  = threadIdx.x >> 5;
    int lane = threadIdx.x & 31;
    int q    = lane & 15;
    int half = lane >> 4;
    int node = blockIdx.x * 16 + wid * 2 + half;   // always valid
    int nl   = wid * 2 + half;
    const uint4* H4 = (const uint4*)H;

    float aDn = aD[node];
    float den = __expf(leaky(aS[node] + aDn));     // self loop
    float2 u0, u1, u2, u3;
    bf16x8_unpack(H4[node * 16 + q], u0, u1, u2, u3);
    float a0 = u0.x * den, a1 = u0.y * den, a2 = u1.x * den, a3 = u1.y * den;
    float a4 = u2.x * den, a5 = u2.y * den, a6 = u3.x * den, a7 = u3.y * den;

    int beg = off[node];
    int n   = off[node + 1] - beg;
    int noth = __shfl_xor_sync(0xffffffff, n, 16);
    int nqmin = min(n, noth) >> 2;
    int nqmax = max(n, noth) >> 2;
    int nq    = n >> 2;
    const int4* base = (const int4*)(srcs + beg);

    int iq = 0;
#pragma unroll 2
    for (; iq < nqmin; iq++) {
        int4 s4 = base[iq];
        AGG2_QUAD(s4);
    }
    for (; iq < nqmax; iq++) {
        int4 s4 = (iq < nq) ? base[iq] : *(const int4*)g_sentq;
        AGG2_QUAD(s4);
    }
    float inv = 1.f / den;
    a0 *= inv; a1 *= inv; a2 *= inv; a3 *= inv;
    a4 *= inv; a5 *= inv; a6 *= inv; a7 *= inv;
    int g = batch[node];

    if (q == 0) sbatch[nl] = g;
    float* sr = &sacc[nl][q * 8];
    sr[0] = a0; sr[1] = a1; sr[2] = a2; sr[3] = a3;
    sr[4] = a4; sr[5] = a5; sr[6] = a6; sr[7] = a7;
    __syncthreads();

    int g0 = sbatch[0];
    bool uniform = true;
#pragma unroll
    for (int w = 1; w < 16; w++) uniform &= (sbatch[w] == g0);

    if (uniform) {
        if (threadIdx.x < DIM) {
            float v = 0.f;
#pragma unroll
            for (int w = 0; w < 16; w++) v += sacc[w][threadIdx.x];
            atomicAdd(&gsum[g0 * DIM + threadIdx.x], v);
        }
    } else {
        float* dp = &gsum[g * DIM + q * 8];
        atomicAdd(dp + 0, a0); atomicAdd(dp + 1, a1);
        atomicAdd(dp + 2, a2); atomicAdd(dp + 3, a3);
        atomicAdd(dp + 4, a4); atomicAdd(dp + 5, a5);
        atomicAdd(dp + 6, a6); atomicAdd(dp + 7, a7);
    }
}

// ---------------- classifier MLP ---------------------------------------------
__global__ void classifier(const float* __restrict__ gsum, const float* __restrict__ gcnt,
                           const float* __restrict__ b2,
                           const float* __restrict__ Wc1, const float* __restrict__ bc1,
                           const float* __restrict__ Wc2, const float* __restrict__ bc2,
                           float* __restrict__ out)
{
    __shared__ float emb[DIM];
    __shared__ float z[64];
    int g = blockIdx.x, t = threadIdx.x;
    float cnt = fmaxf(gcnt[g], 1.f);
    emb[t] = gsum[g * DIM + t] / cnt + b2[t];
    __syncthreads();
    if (t < 64) {
        float a = bc1[t];
#pragma unroll 8
        for (int k = 0; k < DIM; k++) a = fmaf(emb[k], Wc1[k * 64 + t], a);
        z[t] = a > 0.f ? a : expm1f(a);
    }
    __syncthreads();
    if (t < NCLASS) {
        float a = bc2[t];
#pragma unroll
        for (int k = 0; k < 64; k++) a = fmaf(z[k], Wc2[k * NCLASS + t], a);
        out[g * NCLASS + t] = a;
    }
}

// ---------------- launch ------------------------------------------------------
extern "C" void kernel_launch(void* const* d_in, const int* in_sizes, int n_in,
                              void* d_out, int out_size)
{
    const float* x        = (const float*)d_in[0];
    const int*   esrc     = (const int*)  d_in[1];
    const int*   edst     = (const int*)  d_in[2];
    const int*   batch    = (const int*)  d_in[3];
    const float* W1       = (const float*)d_in[4];
    const float* b1       = (const float*)d_in[5];
    const float* att_src1 = (const float*)d_in[6];
    const float* att_dst1 = (const float*)d_in[7];
    const float* W2       = (const float*)d_in[8];
    const float* b2       = (const float*)d_in[9];
    const float* att_src2 = (const float*)d_in[10];
    const float* att_dst2 = (const float*)d_in[11];
    const float* bn_g     = (const float*)d_in[12];
    const float* bn_b     = (const float*)d_in[13];
    const float* bn_m     = (const float*)d_in[14];
    const float* bn_v     = (const float*)d_in[15];
    const float* Wc1      = (const float*)d_in[16];
    const float* bc1      = (const float*)d_in[17];
    const float* Wc2      = (const float*)d_in[18];
    const float* bc2      = (const float*)d_in[19];
    float* out = (float*)d_out;

    __nv_bfloat16 *p_h, *p_midb;
    float *p_w1p, *p_w2p, *p_as, *p_ad, *p_gsum, *p_gcnt;
    int *p_deg, *p_off, *p_cur, *p_srcs;
    cudaGetSymbolAddress((void**)&p_h,    g_h);
    cudaGetSymbolAddress((void**)&p_midb, g_midb);
    cudaGetSymbolAddress((void**)&p_w1p,  g_w1p);
    cudaGetSymbolAddress((void**)&p_w2p,  g_w2p);
    cudaGetSymbolAddress((void**)&p_as,   g_asrc);
    cudaGetSymbolAddress((void**)&p_ad,   g_adst);
    cudaGetSymbolAddress((void**)&p_deg,  g_deg);
    cudaGetSymbolAddress((void**)&p_off,  g_off);
    cudaGetSymbolAddress((void**)&p_cur,  g_cur);
    cudaGetSymbolAddress((void**)&p_srcs, g_srcs);
    cudaGetSymbolAddress((void**)&p_gsum, g_gsum);
    cudaGetSymbolAddress((void**)&p_gcnt, g_gcnt);

    static cudaStream_t s2 = 0;
    static cudaEvent_t evFork = 0, evJoin = 0;
    const int XSMEM = 128 * 132 * (int)sizeof(float);
    if (s2 == 0) {
        cudaStreamCreateWithFlags(&s2, cudaStreamNonBlocking);
        cudaEventCreateWithFlags(&evFork, cudaEventDisableTiming);
        cudaEventCreateWithFlags(&evJoin, cudaEventDisableTiming);
        cudaFuncSetAttribute(gemm_mma_kernel,
                             cudaFuncAttributeMaxDynamicSharedMemorySize, XSMEM);
    }

    const int TB = 256;
    int gemm_blocks = (N_NODES + 127) / 128;
    int agg_blocks  = N_NODES / 16;           // 3125

    cudaEventRecord(evFork, 0);
    cudaStreamWaitEvent(s2, evFork, 0);

    build_csr<<<NB_CSR, TB, 0, s2>>>(esrc, edst, batch, p_deg, p_off, p_cur,  // 0
                                     p_srcs, p_gsum, p_gcnt);
    cudaEventRecord(evJoin, s2);

    pack_w_tf32<<<(16 * 8 * 32 + TB - 1) / TB, TB>>>(W1, W2, p_w1p, p_w2p);   // 1
    gemm_mma_kernel<<<gemm_blocks, TB, XSMEM>>>(x, p_w1p, att_src1, att_dst1, // 2
                                                p_h, p_as, p_ad, HEADS, 0);
    cudaStreamWaitEvent(0, evJoin, 0);

    agg_layer1<<<agg_blocks, TB>>>(p_srcs, p_off, p_as, p_ad, p_h,            // 3 <- profiled
                                   b1, bn_g, bn_b, bn_m, bn_v, p_midb);
    gemm_mma_kernel<<<gemm_blocks, TB, XSMEM>>>((const float*)p_midb, p_w2p,  // 4
                                                att_src2, att_dst2, p_h, p_as, p_ad, 1, 1);
    agg_layer2<<<agg_blocks, TB>>>(p_srcs, p_off, p_as, p_ad, p_h, batch, p_gsum); // 5
    classifier<<<GRAPHS, DIM>>>(p_gsum, p_gcnt, b2, Wc1, bc1, Wc2, bc2, out);      // 6
}